// round 1
// baseline (speedup 1.0000x reference)
#include <cuda_runtime.h>
#include <math.h>

#define B_  4
#define L_  1024
#define D_  1024
#define H_  16
#define HD_ 64
#define M_TOT (B_*L_)   // 4096

// Scratch (static device allocations are allowed; cudaMalloc is not)
__device__ float g_q[M_TOT * D_];
__device__ float g_k[M_TOT * D_];
__device__ float g_v[M_TOT * D_];
__device__ float g_ctx[M_TOT * D_];
__device__ float g_x[M_TOT * D_];

// ---------------------------------------------------------------------------
// SGEMM: C[M,N] = A[M,K] @ B[K,N] + bias[N] (+ res[M,N] if res != nullptr)
// 128x128 block tile, BK=8, 256 threads, 8x8 per-thread microtile (split-64).
// ---------------------------------------------------------------------------
__global__ __launch_bounds__(256) void sgemm128(
    const float* __restrict__ A, const float* __restrict__ Bw,
    const float* __restrict__ bias, const float* __restrict__ res,
    float* __restrict__ C, int M, int N, int K)
{
    __shared__ float As[8][128];   // [k][m]
    __shared__ float Bs[8][128];   // [k][n]
    const int tid = threadIdx.x;
    const int tx = tid & 15, ty = tid >> 4;
    const int bm = blockIdx.y * 128, bn = blockIdx.x * 128;

    const int arow = tid >> 1, acol = (tid & 1) << 2;
    const int brow = tid >> 5, bcol = (tid & 31) << 2;

    const float* Ap = A + (bm + arow) * K + acol;
    const float* Bp = Bw + brow * N + bn + bcol;

    float4 af = *(const float4*)Ap;
    float4 bf = *(const float4*)Bp;

    float acc[8][8];
    #pragma unroll
    for (int i = 0; i < 8; i++)
        #pragma unroll
        for (int j = 0; j < 8; j++) acc[i][j] = 0.f;

    const int KT = K >> 3;
    for (int t = 0; t < KT; t++) {
        As[acol+0][arow] = af.x;
        As[acol+1][arow] = af.y;
        As[acol+2][arow] = af.z;
        As[acol+3][arow] = af.w;
        *(float4*)&Bs[brow][bcol] = bf;
        __syncthreads();
        if (t + 1 < KT) {
            af = *(const float4*)(Ap + (t + 1) * 8);
            bf = *(const float4*)(Bp + (t + 1) * 8 * N);
        }
        #pragma unroll
        for (int k = 0; k < 8; k++) {
            float ar[8], br[8];
            *(float4*)&ar[0] = *(float4*)&As[k][ty*4];
            *(float4*)&ar[4] = *(float4*)&As[k][ty*4 + 64];
            *(float4*)&br[0] = *(float4*)&Bs[k][tx*4];
            *(float4*)&br[4] = *(float4*)&Bs[k][tx*4 + 64];
            #pragma unroll
            for (int i = 0; i < 8; i++)
                #pragma unroll
                for (int j = 0; j < 8; j++)
                    acc[i][j] = fmaf(ar[i], br[j], acc[i][j]);
        }
        __syncthreads();
    }

    #pragma unroll
    for (int i = 0; i < 8; i++) {
        int row = bm + ty*4 + (i & 3) + ((i >= 4) ? 64 : 0);
        #pragma unroll
        for (int jh = 0; jh < 2; jh++) {
            int col = bn + tx*4 + jh*64;
            float4 bv = *(const float4*)&bias[col];
            float4 o;
            o.x = acc[i][jh*4+0] + bv.x;
            o.y = acc[i][jh*4+1] + bv.y;
            o.z = acc[i][jh*4+2] + bv.z;
            o.w = acc[i][jh*4+3] + bv.w;
            if (res) {
                float4 rv = *(const float4*)&res[row * N + col];
                o.x += rv.x; o.y += rv.y; o.z += rv.z; o.w += rv.w;
            }
            *(float4*)&C[row * N + col] = o;
        }
    }
}

// ---------------------------------------------------------------------------
// In-place per-head scale (1 + gamma*tanh(mag)) + rotation by phase phi.
// Each thread handles the pair (d, d+32) of one (b,l,h) for both Q and K.
// ---------------------------------------------------------------------------
__global__ __launch_bounds__(256) void rotscale(
    float* __restrict__ q, float* __restrict__ k,
    const float* __restrict__ phi, const float* __restrict__ mag,
    const float* __restrict__ gamma)
{
    int idx = blockIdx.x * 256 + threadIdx.x;   // < B*L*H*32 = 2097152
    int d = idx & 31;
    int h = (idx >> 5) & 15;
    int l = (idx >> 9) & 1023;
    int b = idx >> 19;
    int phl = (b * 16 + h) * 1024 + l;          // [B,H,L]
    float sc = 1.0f + gamma[h] * tanhf(mag[phl]);
    float s, c;
    sincosf(phi[phl], &s, &c);
    int base = (b * 1024 + l) * 1024 + h * 64 + d;
    float q1 = q[base] * sc, q2 = q[base + 32] * sc;
    q[base]      = q1 * c - q2 * s;
    q[base + 32] = q2 * c + q1 * s;
    float k1 = k[base] * sc, k2 = k[base + 32] * sc;
    k[base]      = k1 * c - k2 * s;
    k[base + 32] = k2 * c + k1 * s;
}

// ---------------------------------------------------------------------------
// Flash-style attention. One block per (b, h, 64-query tile).
// Q,K,V in [b,l,h*64+d] layout. Online softmax across 16 KV tiles of 64.
// smem: QsT[64][68] ([dim][row]), KP[64][68] (KsT [dim][key], then P [row][key]),
//       Vs[64][64] ([key][dim]).  Total 51200 B dynamic.
// ---------------------------------------------------------------------------
__global__ __launch_bounds__(256) void attn64(
    const float* __restrict__ Q, const float* __restrict__ K,
    const float* __restrict__ V, const float* __restrict__ mask,
    float* __restrict__ Ctx)
{
    extern __shared__ float sm[];
    float* QsT = sm;                 // 64*68
    float* KP  = sm + 64 * 68;       // 64*68
    float* Vs  = sm + 2 * 64 * 68;   // 64*64
    const int tid = threadIdx.x;
    const int tx = tid & 15, ty = tid >> 4;
    const int qt = blockIdx.x;             // 0..15
    const int b = blockIdx.y >> 4, h = blockIdx.y & 15;

    const float* Qg = Q + (size_t)b * L_ * D_ + h * HD_;
    const float* Kg = K + (size_t)b * L_ * D_ + h * HD_;
    const float* Vg = V + (size_t)b * L_ * D_ + h * HD_;
    const float* mk = mask + b * L_;

    // Load Q tile transposed: QsT[dim][row]
    for (int i = tid; i < 64 * 16; i += 256) {
        int r  = i >> 4;
        int c4 = (i & 15) << 2;
        float4 qv = *(const float4*)(Qg + (qt * 64 + r) * D_ + c4);
        QsT[(c4+0)*68 + r] = qv.x;
        QsT[(c4+1)*68 + r] = qv.y;
        QsT[(c4+2)*68 + r] = qv.z;
        QsT[(c4+3)*68 + r] = qv.w;
    }

    float mrow[4], lrow[4], o[4][4];
    #pragma unroll
    for (int i = 0; i < 4; i++) {
        mrow[i] = -INFINITY; lrow[i] = 0.f;
        #pragma unroll
        for (int j = 0; j < 4; j++) o[i][j] = 0.f;
    }

    for (int kt = 0; kt < 16; kt++) {
        __syncthreads();   // prev PV reads done (and Q load on first iter)
        // load K tile transposed + V tile
        for (int i = tid; i < 64 * 16; i += 256) {
            int r  = i >> 4;
            int c4 = (i & 15) << 2;
            float4 kv = *(const float4*)(Kg + (kt * 64 + r) * D_ + c4);
            KP[(c4+0)*68 + r] = kv.x;
            KP[(c4+1)*68 + r] = kv.y;
            KP[(c4+2)*68 + r] = kv.z;
            KP[(c4+3)*68 + r] = kv.w;
            float4 vv = *(const float4*)(Vg + (kt * 64 + r) * D_ + c4);
            *(float4*)&Vs[r * 64 + c4] = vv;
        }
        __syncthreads();

        // S = Q K^T for this tile: s[4][4] (rows ty*4+i, keys tx*4+j)
        float s[4][4];
        #pragma unroll
        for (int i = 0; i < 4; i++)
            #pragma unroll
            for (int j = 0; j < 4; j++) s[i][j] = 0.f;
        #pragma unroll 8
        for (int k = 0; k < 64; k++) {
            float4 qv = *(float4*)&QsT[k * 68 + ty * 4];
            float4 kv = *(float4*)&KP [k * 68 + tx * 4];
            s[0][0] = fmaf(qv.x, kv.x, s[0][0]); s[0][1] = fmaf(qv.x, kv.y, s[0][1]);
            s[0][2] = fmaf(qv.x, kv.z, s[0][2]); s[0][3] = fmaf(qv.x, kv.w, s[0][3]);
            s[1][0] = fmaf(qv.y, kv.x, s[1][0]); s[1][1] = fmaf(qv.y, kv.y, s[1][1]);
            s[1][2] = fmaf(qv.y, kv.z, s[1][2]); s[1][3] = fmaf(qv.y, kv.w, s[1][3]);
            s[2][0] = fmaf(qv.z, kv.x, s[2][0]); s[2][1] = fmaf(qv.z, kv.y, s[2][1]);
            s[2][2] = fmaf(qv.z, kv.z, s[2][2]); s[2][3] = fmaf(qv.z, kv.w, s[2][3]);
            s[3][0] = fmaf(qv.w, kv.x, s[3][0]); s[3][1] = fmaf(qv.w, kv.y, s[3][1]);
            s[3][2] = fmaf(qv.w, kv.z, s[3][2]); s[3][3] = fmaf(qv.w, kv.w, s[3][3]);
        }

        // scale + mask
        float4 mj = *(const float4*)&mk[kt * 64 + tx * 4];
        #pragma unroll
        for (int i = 0; i < 4; i++) {
            s[i][0] = s[i][0] * 0.125f + mj.x;
            s[i][1] = s[i][1] * 0.125f + mj.y;
            s[i][2] = s[i][2] * 0.125f + mj.z;
            s[i][3] = s[i][3] * 0.125f + mj.w;
        }

        // online softmax update (rows are shared by 16 consecutive lanes)
        float p[4][4];
        #pragma unroll
        for (int i = 0; i < 4; i++) {
            float tmax = fmaxf(fmaxf(s[i][0], s[i][1]), fmaxf(s[i][2], s[i][3]));
            #pragma unroll
            for (int off = 8; off > 0; off >>= 1)
                tmax = fmaxf(tmax, __shfl_xor_sync(0xffffffffu, tmax, off));
            float mnew = fmaxf(mrow[i], tmax);
            float corr = __expf(mrow[i] - mnew);
            mrow[i] = mnew;
            p[i][0] = __expf(s[i][0] - mnew);
            p[i][1] = __expf(s[i][1] - mnew);
            p[i][2] = __expf(s[i][2] - mnew);
            p[i][3] = __expf(s[i][3] - mnew);
            float tsum = p[i][0] + p[i][1] + p[i][2] + p[i][3];
            #pragma unroll
            for (int off = 8; off > 0; off >>= 1)
                tsum += __shfl_xor_sync(0xffffffffu, tsum, off);
            lrow[i] = lrow[i] * corr + tsum;
            o[i][0] *= corr; o[i][1] *= corr; o[i][2] *= corr; o[i][3] *= corr;
        }

        __syncthreads();   // everyone done reading KP as K^T
        #pragma unroll
        for (int i = 0; i < 4; i++)
            *(float4*)&KP[(ty*4 + i) * 68 + tx * 4] =
                make_float4(p[i][0], p[i][1], p[i][2], p[i][3]);
        __syncthreads();

        // O += P @ V  (thread owns rows ty*4+i, dims tx*4..+3)
        #pragma unroll 8
        for (int j = 0; j < 64; j++) {
            float4 vv = *(float4*)&Vs[j * 64 + tx * 4];
            #pragma unroll
            for (int i = 0; i < 4; i++) {
                float pv = KP[(ty*4 + i) * 68 + j];
                o[i][0] = fmaf(pv, vv.x, o[i][0]);
                o[i][1] = fmaf(pv, vv.y, o[i][1]);
                o[i][2] = fmaf(pv, vv.z, o[i][2]);
                o[i][3] = fmaf(pv, vv.w, o[i][3]);
            }
        }
    }

    #pragma unroll
    for (int i = 0; i < 4; i++) {
        float inv = 1.0f / lrow[i];
        int row = qt * 64 + ty * 4 + i;
        float4 ov = make_float4(o[i][0]*inv, o[i][1]*inv, o[i][2]*inv, o[i][3]*inv);
        *(float4*)&Ctx[((size_t)b * L_ + row) * D_ + h * HD_ + tx * 4] = ov;
    }
}

// ---------------------------------------------------------------------------
// LayerNorm over last dim (1024). One block per row; each thread owns 4 cols.
// ---------------------------------------------------------------------------
__global__ __launch_bounds__(256) void lnorm(
    const float* __restrict__ X, const float* __restrict__ hsc,
    const float* __restrict__ hbi, float* __restrict__ out)
{
    int row = blockIdx.x;
    int c4 = threadIdx.x * 4;
    const float* x = X + (size_t)row * D_;
    float4 v = *(const float4*)(x + c4);
    float sum = v.x + v.y + v.z + v.w;
    float sq  = v.x*v.x + v.y*v.y + v.z*v.z + v.w*v.w;
    #pragma unroll
    for (int off = 16; off > 0; off >>= 1) {
        sum += __shfl_xor_sync(0xffffffffu, sum, off);
        sq  += __shfl_xor_sync(0xffffffffu, sq,  off);
    }
    __shared__ float rs[8], rq[8];
    int warp = threadIdx.x >> 5;
    if ((threadIdx.x & 31) == 0) { rs[warp] = sum; rq[warp] = sq; }
    __syncthreads();
    float tot = 0.f, totq = 0.f;
    #pragma unroll
    for (int w = 0; w < 8; w++) { tot += rs[w]; totq += rq[w]; }
    float mu  = tot  * (1.0f / 1024.0f);
    float var = totq * (1.0f / 1024.0f) - mu * mu;
    float inv = rsqrtf(var + 1e-12f);
    float4 sc = *(const float4*)(hsc + c4);
    float4 bi = *(const float4*)(hbi + c4);
    float4 o;
    o.x = (v.x - mu) * inv * sc.x + bi.x;
    o.y = (v.y - mu) * inv * sc.y + bi.y;
    o.z = (v.z - mu) * inv * sc.z + bi.z;
    o.w = (v.w - mu) * inv * sc.w + bi.w;
    *(float4*)&out[(size_t)row * D_ + c4] = o;
}

// ---------------------------------------------------------------------------
extern "C" void kernel_launch(void* const* d_in, const int* in_sizes, int n_in,
                              void* d_out, int out_size)
{
    const float* hidden = (const float*)d_in[0];
    const float* mask   = (const float*)d_in[1];
    const float* phi    = (const float*)d_in[2];
    const float* mag    = (const float*)d_in[3];
    const float* Wq     = (const float*)d_in[4];
    const float* bq     = (const float*)d_in[5];
    const float* Wk     = (const float*)d_in[6];
    const float* bk     = (const float*)d_in[7];
    const float* Wv     = (const float*)d_in[8];
    const float* bv     = (const float*)d_in[9];
    const float* gamma  = (const float*)d_in[10];
    const float* Wo     = (const float*)d_in[11];
    const float* bo     = (const float*)d_in[12];
    const float* lns    = (const float*)d_in[13];
    const float* lnb    = (const float*)d_in[14];
    float* out = (float*)d_out;

    float *q, *k, *v, *ctx, *x;
    cudaGetSymbolAddress((void**)&q,   g_q);
    cudaGetSymbolAddress((void**)&k,   g_k);
    cudaGetSymbolAddress((void**)&v,   g_v);
    cudaGetSymbolAddress((void**)&ctx, g_ctx);
    cudaGetSymbolAddress((void**)&x,   g_x);

    dim3 gg(D_ / 128, M_TOT / 128);   // (8, 32)
    sgemm128<<<gg, 256>>>(hidden, Wq, bq, nullptr, q, M_TOT, D_, D_);
    sgemm128<<<gg, 256>>>(hidden, Wk, bk, nullptr, k, M_TOT, D_, D_);
    sgemm128<<<gg, 256>>>(hidden, Wv, bv, nullptr, v, M_TOT, D_, D_);

    rotscale<<<(B_ * L_ * H_ * 32) / 256, 256>>>(q, k, phi, mag, gamma);

    cudaFuncSetAttribute(attn64, cudaFuncAttributeMaxDynamicSharedMemorySize, 51200);
    attn64<<<dim3(L_ / 64, B_ * H_), 256, 51200>>>(q, k, v, mask, ctx);

    sgemm128<<<gg, 256>>>(ctx, Wo, bo, hidden, x, M_TOT, D_, D_);

    lnorm<<<M_TOT, 256>>>(x, lns, lnb, out);
}

// round 3
// speedup vs baseline: 1.3948x; 1.3948x over previous
#include <cuda_runtime.h>
#include <cuda_bf16.h>
#include <math.h>
#include <stdint.h>

#define B_  4
#define L_  1024
#define D_  1024
#define H_  16
#define HD_ 64
#define M_TOT (B_*L_)   // 4096

typedef unsigned long long ull;

// ---------------------------------------------------------------------------
// Scratch (static device arrays; no cudaMalloc anywhere)
// ---------------------------------------------------------------------------
__device__ float g_q[M_TOT * D_];
__device__ float g_k[M_TOT * D_];
__device__ float g_v[M_TOT * D_];
__device__ float g_ctx[M_TOT * D_];
__device__ float g_x[M_TOT * D_];
__device__ __nv_bfloat16 g_ahi[M_TOT * D_];
__device__ __nv_bfloat16 g_alo[M_TOT * D_];
__device__ __nv_bfloat16 g_wthi[4 * D_ * D_];   // W^T [N][K] hi, 4 matrices
__device__ __nv_bfloat16 g_wtlo[4 * D_ * D_];   // lo

// ---------------------------------------------------------------------------
// Helpers
// ---------------------------------------------------------------------------
__device__ __forceinline__ uint32_t smem_to_u32(const void* p) {
    uint32_t a;
    asm("{ .reg .u64 t; cvta.to.shared.u64 t, %1; cvt.u32.u64 %0, t; }"
        : "=r"(a) : "l"(p));
    return a;
}

#define CP16(dst, src) \
    asm volatile("cp.async.cg.shared.global [%0], [%1], 16;" \
                 :: "r"(dst), "l"(src) : "memory")
#define CP_COMMIT() asm volatile("cp.async.commit_group;" ::: "memory")

#define LDSM4(r, addr) \
    asm volatile("ldmatrix.sync.aligned.m8n8.x4.shared.b16 {%0,%1,%2,%3}, [%4];" \
                 : "=r"((r)[0]), "=r"((r)[1]), "=r"((r)[2]), "=r"((r)[3]) : "r"(addr))

#define MMA16816(c, a, b0, b1) \
    asm volatile("mma.sync.aligned.m16n8k16.row.col.f32.bf16.bf16.f32 " \
                 "{%0,%1,%2,%3}, {%4,%5,%6,%7}, {%8,%9}, {%0,%1,%2,%3};" \
                 : "+f"((c)[0]), "+f"((c)[1]), "+f"((c)[2]), "+f"((c)[3]) \
                 : "r"((a)[0]), "r"((a)[1]), "r"((a)[2]), "r"((a)[3]), \
                   "r"(b0), "r"(b1))

#define LDS64(v, addr) \
    asm volatile("ld.shared.b64 %0, [%1];" : "=l"(v) : "r"(addr))
#define FMA2(acc, a, b) \
    asm volatile("fma.rn.f32x2 %0, %1, %2, %0;" : "+l"(acc) : "l"(a), "l"(b))
#define MUL2(acc, b) \
    asm volatile("mul.rn.f32x2 %0, %0, %1;" : "+l"(acc) : "l"(b))
#define PACK2(d, f) \
    asm volatile("mov.b64 %0, {%1, %1};" : "=l"(d) : "f"(f))
#define UNPACK2(lo, hi, v) \
    asm volatile("mov.b64 {%0, %1}, %2;" : "=f"(lo), "=f"(hi) : "l"(v))

// ---------------------------------------------------------------------------
// fp32 -> bf16 hi/lo split
// ---------------------------------------------------------------------------
__device__ __forceinline__ void split1(float x, uint32_t& h, uint32_t& l) {
    __nv_bfloat16 hb = __float2bfloat16(x);
    float hf = __bfloat162float(hb);
    __nv_bfloat16 lb = __float2bfloat16(x - hf);
    h = (uint32_t)__bfloat16_as_ushort(hb);
    l = (uint32_t)__bfloat16_as_ushort(lb);
}

__global__ __launch_bounds__(256) void convA(
    const float4* __restrict__ x, uint2* __restrict__ hi, uint2* __restrict__ lo, int n4)
{
    int i = blockIdx.x * 256 + threadIdx.x;
    if (i >= n4) return;
    float4 v = x[i];
    uint32_t h0,l0,h1,l1,h2,l2,h3,l3;
    split1(v.x, h0, l0); split1(v.y, h1, l1);
    split1(v.z, h2, l2); split1(v.w, h3, l3);
    uint2 ho, lv;
    ho.x = h0 | (h1 << 16); ho.y = h2 | (h3 << 16);
    lv.x = l0 | (l1 << 16); lv.y = l2 | (l3 << 16);
    hi[i] = ho; lo[i] = lv;
}

// W[K,N] fp32 -> WT[N,K] bf16 hi/lo
__global__ __launch_bounds__(256) void convW(
    const float* __restrict__ W, __nv_bfloat16* __restrict__ hi, __nv_bfloat16* __restrict__ lo)
{
    __shared__ float t[32][33];
    int n0 = blockIdx.x * 32, k0 = blockIdx.y * 32;
    int tx = threadIdx.x & 31, ty = threadIdx.x >> 5;
    #pragma unroll
    for (int j = 0; j < 4; j++)
        t[ty + j*8][tx] = W[(size_t)(k0 + ty + j*8) * D_ + n0 + tx];
    __syncthreads();
    #pragma unroll
    for (int j = 0; j < 4; j++) {
        float v = t[tx][ty + j*8];
        uint32_t h, l;
        split1(v, h, l);
        size_t o = (size_t)(n0 + ty + j*8) * D_ + k0 + tx;
        hi[o] = __ushort_as_bfloat16((unsigned short)h);
        lo[o] = __ushort_as_bfloat16((unsigned short)l);
    }
}

// ---------------------------------------------------------------------------
// HMMA bf16 3-term GEMM: C[M,N] = A @ W (+bias, +res), fp32 in/out.
// A as Ahi/Alo [M,K] bf16; W as WThi/WTlo [N,K] bf16 (B col-major for mma).
// CTA tile 128x128, KC=64, cp.async double-buffered, 8 warps (64x32 each).
// ---------------------------------------------------------------------------
#define GM 128
#define GN 128
#define KC 64
#define ROWB 144                   // 64 halves + 8 pad = 144 B per smem row
#define OFF_ALO (128*ROWB)
#define OFF_BHI (2*128*ROWB)
#define OFF_BLO (3*128*ROWB)
#define STAGE   (4*128*ROWB)       // 73728 B
#define GEMM_DYN (2*STAGE)         // 147456 B

__global__ __launch_bounds__(256, 1) void gemm_hmma(
    const __nv_bfloat16* __restrict__ Ahi, const __nv_bfloat16* __restrict__ Alo,
    const __nv_bfloat16* __restrict__ Bhi, const __nv_bfloat16* __restrict__ Blo,
    const float* __restrict__ bias, const float* __restrict__ res,
    float* __restrict__ C)
{
    extern __shared__ char smraw[];
    const uint32_t sbase = smem_to_u32(smraw);
    const int tid  = threadIdx.x;
    const int lane = tid & 31, wid = tid >> 5;
    const int wm = wid >> 2, wn = wid & 3;
    const int bm = blockIdx.y * GM, bn = blockIdx.x * GN;

    // ---- async stage loader ----
    #define LOAD_STAGE(s, kc) do { \
        uint32_t sb_ = sbase + (uint32_t)(s) * STAGE; \
        _Pragma("unroll") \
        for (int it = 0; it < 4; it++) { \
            int i_ = tid + it * 256; \
            int r_ = i_ >> 3, seg_ = i_ & 7; \
            uint32_t d_ = sb_ + r_ * ROWB + seg_ * 16; \
            size_t ga_ = (size_t)(bm + r_) * D_ + (kc) + seg_ * 8; \
            size_t gb_ = (size_t)(bn + r_) * D_ + (kc) + seg_ * 8; \
            CP16(d_,           Ahi + ga_); \
            CP16(d_ + OFF_ALO, Alo + ga_); \
            CP16(d_ + OFF_BHI, Bhi + gb_); \
            CP16(d_ + OFF_BLO, Blo + gb_); \
        } \
        CP_COMMIT(); \
    } while (0)

    float c[4][4][4];
    #pragma unroll
    for (int mi = 0; mi < 4; mi++)
        #pragma unroll
        for (int ni = 0; ni < 4; ni++)
            #pragma unroll
            for (int e = 0; e < 4; e++) c[mi][ni][e] = 0.f;

    LOAD_STAGE(0, 0);

    for (int ch = 0; ch < 16; ch++) {
        if (ch < 15) {
            LOAD_STAGE((ch + 1) & 1, (ch + 1) * KC);
            asm volatile("cp.async.wait_group 1;" ::: "memory");
        } else {
            asm volatile("cp.async.wait_group 0;" ::: "memory");
        }
        __syncthreads();

        const uint32_t sb = sbase + (uint32_t)(ch & 1) * STAGE;
        #pragma unroll
        for (int ks = 0; ks < 4; ks++) {
            uint32_t ah[4][4], al[4][4], bh[2][4], bl[2][4];
            // A fragments (64 rows of this warp, hi+lo)
            #pragma unroll
            for (int mi = 0; mi < 4; mi++) {
                int m0 = wm * 64 + mi * 16;
                uint32_t addr = sb + (uint32_t)(m0 + (lane & 15)) * ROWB
                              + ks * 32 + ((lane >> 4) << 4);
                LDSM4(ah[mi], addr);
                LDSM4(al[mi], addr + OFF_ALO);
            }
            // B fragments (32 cols of this warp = 4 n-tiles, in 2 pairs)
            #pragma unroll
            for (int np = 0; np < 2; np++) {
                int n0 = wn * 32 + np * 16;
                int row = n0 + ((lane >> 4) << 3) + (lane & 7);
                uint32_t addr = sb + OFF_BHI + (uint32_t)row * ROWB
                              + ks * 32 + (((lane >> 3) & 1) << 4);
                LDSM4(bh[np], addr);
                LDSM4(bl[np], addr + (OFF_BLO - OFF_BHI));
            }
            // 3-term MMAs: hi*hi + hi*lo + lo*hi
            #pragma unroll
            for (int mi = 0; mi < 4; mi++)
                #pragma unroll
                for (int ni = 0; ni < 4; ni++) {
                    int np = ni >> 1, rb = (ni & 1) * 2;
                    MMA16816(c[mi][ni], ah[mi], bh[np][rb], bh[np][rb + 1]);
                    MMA16816(c[mi][ni], ah[mi], bl[np][rb], bl[np][rb + 1]);
                    MMA16816(c[mi][ni], al[mi], bh[np][rb], bh[np][rb + 1]);
                }
        }
        __syncthreads();
    }

    // ---- epilogue ----
    const int g = lane >> 2, tig = lane & 3;
    #pragma unroll
    for (int mi = 0; mi < 4; mi++) {
        int row0 = bm + wm * 64 + mi * 16 + g;
        #pragma unroll
        for (int ni = 0; ni < 4; ni++) {
            int col = bn + wn * 32 + ni * 8 + tig * 2;
            float2 bv = *(const float2*)(bias + col);
            float2 o0, o1;
            o0.x = c[mi][ni][0] + bv.x; o0.y = c[mi][ni][1] + bv.y;
            o1.x = c[mi][ni][2] + bv.x; o1.y = c[mi][ni][3] + bv.y;
            if (res) {
                float2 r0 = *(const float2*)(res + (size_t)row0 * D_ + col);
                float2 r1 = *(const float2*)(res + (size_t)(row0 + 8) * D_ + col);
                o0.x += r0.x; o0.y += r0.y;
                o1.x += r1.x; o1.y += r1.y;
            }
            *(float2*)(C + (size_t)row0 * D_ + col) = o0;
            *(float2*)(C + (size_t)(row0 + 8) * D_ + col) = o1;
        }
    }
    #undef LOAD_STAGE
}

// ---------------------------------------------------------------------------
// In-place per-head scale (1 + gamma*tanh(mag)) + rotation by phase phi.
// ---------------------------------------------------------------------------
__global__ __launch_bounds__(256) void rotscale(
    float* __restrict__ q, float* __restrict__ k,
    const float* __restrict__ phi, const float* __restrict__ mag,
    const float* __restrict__ gamma)
{
    int idx = blockIdx.x * 256 + threadIdx.x;
    int d = idx & 31;
    int h = (idx >> 5) & 15;
    int l = (idx >> 9) & 1023;
    int b = idx >> 19;
    int phl = (b * 16 + h) * 1024 + l;
    float sc = 1.0f + gamma[h] * tanhf(mag[phl]);
    float s, c;
    sincosf(phi[phl], &s, &c);
    int base = (b * 1024 + l) * 1024 + h * 64 + d;
    float q1 = q[base] * sc, q2 = q[base + 32] * sc;
    q[base]      = q1 * c - q2 * s;
    q[base + 32] = q2 * c + q1 * s;
    float k1 = k[base] * sc, k2 = k[base + 32] * sc;
    k[base]      = k1 * c - k2 * s;
    k[base + 32] = k2 * c + k1 * s;
}

// ---------------------------------------------------------------------------
// Flash-style fp32 attention with packed f32x2 FMAs.
// One block per (b, h, 64-query tile). 256 threads, thread tile 4 rows x 4 keys.
// Smem (floats): Qs [64 rows][64], KsP [64][64] (K^T tile then P), VsT [64 dims][64 keys].
// All rows use XOR pair-swizzle: element (row,k) at word row*64 + 2*((k>>1)^((row>>2)&15)) + (k&1)
//  -> LDS.64 of (k,k+1) pairs is conflict-free for row strides of 1 and 4.
// ---------------------------------------------------------------------------
#define ATTN_DYN (3 * 64 * 64 * 4)   // 49152 B

__global__ __launch_bounds__(256) void attn64(
    const float* __restrict__ Q, const float* __restrict__ K,
    const float* __restrict__ V, const float* __restrict__ mask,
    float* __restrict__ Ctx)
{
    extern __shared__ float sm[];
    const uint32_t sb = smem_to_u32(sm);
    const int tid = threadIdx.x;
    const int tx = tid & 15, ty = tid >> 4;
    const int qt = blockIdx.x;
    const int b = blockIdx.y >> 4, h = blockIdx.y & 15;

    const float* Qg = Q + (size_t)b * L_ * D_ + h * HD_;
    const float* Kg = K + (size_t)b * L_ * D_ + h * HD_;
    const float* Vg = V + (size_t)b * L_ * D_ + h * HD_;
    const float* mk = mask + b * L_;

    // Load Q tile (swizzled, row-major k)
    for (int i = tid; i < 1024; i += 256) {
        int r = i >> 4, cc = i & 15;
        float4 qv = *(const float4*)(Qg + (size_t)(qt * 64 + r) * D_ + 4 * cc);
        int sw = (r >> 2) & 15;
        float* row = sm + r * 64;
        *(float2*)(row + 2 * ((2 * cc) ^ sw))     = make_float2(qv.x, qv.y);
        *(float2*)(row + 2 * ((2 * cc + 1) ^ sw)) = make_float2(qv.z, qv.w);
    }

    ull o2[4][4];
    float mrow[4], lrow[4];
    #pragma unroll
    for (int i = 0; i < 4; i++) {
        mrow[i] = -INFINITY; lrow[i] = 0.f;
        #pragma unroll
        for (int j = 0; j < 4; j++) o2[i][j] = 0ull;
    }

    for (int kt = 0; kt < 16; kt++) {
        __syncthreads();   // prior-iter P/V reads done
        // load K tile (swizzled rows) + V tile transposed (dims as rows)
        for (int i = tid; i < 1024; i += 256) {
            int r = i >> 4, cc = i & 15;
            float4 kv = *(const float4*)(Kg + (size_t)(kt * 64 + r) * D_ + 4 * cc);
            int sw = (r >> 2) & 15;
            float* row = sm + 4096 + r * 64;
            *(float2*)(row + 2 * ((2 * cc) ^ sw))     = make_float2(kv.x, kv.y);
            *(float2*)(row + 2 * ((2 * cc + 1) ^ sw)) = make_float2(kv.z, kv.w);

            float4 vv = *(const float4*)(Vg + (size_t)(kt * 64 + r) * D_ + 4 * cc);
            // VsT element (row=dim d=4cc+jj, k=key r); sw = ((4cc+jj)>>2)&15 = cc
            int off = 2 * ((r >> 1) ^ cc) + (r & 1);
            float* vbase = sm + 8192 + 4 * cc * 64 + off;
            vbase[0]   = vv.x;
            vbase[64]  = vv.y;
            vbase[128] = vv.z;
            vbase[192] = vv.w;
        }
        __syncthreads();

        // S = Q K^T (packed over k-pairs)
        ull acc[4][4];
        #pragma unroll
        for (int i = 0; i < 4; i++)
            #pragma unroll
            for (int j = 0; j < 4; j++) acc[i][j] = 0ull;

        const uint32_t qb = sb + (uint32_t)(ty * 4 * 64) * 4;
        const uint32_t kb = sb + 4096u * 4 + (uint32_t)(tx * 4 * 64) * 4;
        #pragma unroll 4
        for (int kp = 0; kp < 32; kp++) {
            uint32_t oq = (uint32_t)((kp ^ ty) << 3);
            uint32_t ok = (uint32_t)((kp ^ tx) << 3);
            ull qa[4], kv2[4];
            #pragma unroll
            for (int i = 0; i < 4; i++) LDS64(qa[i], qb + i * 256 + oq);
            #pragma unroll
            for (int j = 0; j < 4; j++) LDS64(kv2[j], kb + j * 256 + ok);
            #pragma unroll
            for (int i = 0; i < 4; i++)
                #pragma unroll
                for (int j = 0; j < 4; j++)
                    FMA2(acc[i][j], qa[i], kv2[j]);
        }

        // unpack + scale + mask
        float s[4][4];
        float4 mj = *(const float4*)&mk[kt * 64 + tx * 4];
        #pragma unroll
        for (int i = 0; i < 4; i++) {
            #pragma unroll
            for (int j = 0; j < 4; j++) {
                float lo, hi;
                UNPACK2(lo, hi, acc[i][j]);
                s[i][j] = (lo + hi) * 0.125f;
            }
            s[i][0] += mj.x; s[i][1] += mj.y; s[i][2] += mj.z; s[i][3] += mj.w;
        }

        // online softmax + rescale packed accumulators
        float p[4][4];
        #pragma unroll
        for (int i = 0; i < 4; i++) {
            float tmax = fmaxf(fmaxf(s[i][0], s[i][1]), fmaxf(s[i][2], s[i][3]));
            #pragma unroll
            for (int off = 8; off > 0; off >>= 1)
                tmax = fmaxf(tmax, __shfl_xor_sync(0xffffffffu, tmax, off));
            float mnew = fmaxf(mrow[i], tmax);
            float corr = __expf(mrow[i] - mnew);
            mrow[i] = mnew;
            p[i][0] = __expf(s[i][0] - mnew);
            p[i][1] = __expf(s[i][1] - mnew);
            p[i][2] = __expf(s[i][2] - mnew);
            p[i][3] = __expf(s[i][3] - mnew);
            float tsum = p[i][0] + p[i][1] + p[i][2] + p[i][3];
            #pragma unroll
            for (int off = 8; off > 0; off >>= 1)
                tsum += __shfl_xor_sync(0xffffffffu, tsum, off);
            lrow[i] = lrow[i] * corr + tsum;
            ull cs; PACK2(cs, corr);
            #pragma unroll
            for (int j = 0; j < 4; j++) MUL2(o2[i][j], cs);
        }

        __syncthreads();   // all warps done reading KsP as K^T
        #pragma unroll
        for (int i = 0; i < 4; i++) {
            float* prow = sm + 4096 + (ty * 4 + i) * 64;
            *(float2*)(prow + 2 * ((2 * tx) ^ ty))     = make_float2(p[i][0], p[i][1]);
            *(float2*)(prow + 2 * ((2 * tx + 1) ^ ty)) = make_float2(p[i][2], p[i][3]);
        }
        __syncthreads();

        // O += P @ V (packed over key-pairs)
        const uint32_t pb = sb + 4096u * 4 + (uint32_t)(ty * 4 * 64) * 4;
        const uint32_t vb = sb + 8192u * 4 + (uint32_t)(tx * 4 * 64) * 4;
        #pragma unroll 4
        for (int kp = 0; kp < 32; kp++) {
            uint32_t op = (uint32_t)((kp ^ ty) << 3);
            uint32_t ov = (uint32_t)((kp ^ tx) << 3);
            ull pa[4], vv2[4];
            #pragma unroll
            for (int i = 0; i < 4; i++) LDS64(pa[i], pb + i * 256 + op);
            #pragma unroll
            for (int j = 0; j < 4; j++) LDS64(vv2[j], vb + j * 256 + ov);
            #pragma unroll
            for (int i = 0; i < 4; i++)
                #pragma unroll
                for (int j = 0; j < 4; j++)
                    FMA2(o2[i][j], pa[i], vv2[j]);
        }
    }

    #pragma unroll
    for (int i = 0; i < 4; i++) {
        float inv = 1.0f / lrow[i];
        int row = qt * 64 + ty * 4 + i;
        float4 ov;
        float lo, hi;
        UNPACK2(lo, hi, o2[i][0]); ov.x = (lo + hi) * inv;
        UNPACK2(lo, hi, o2[i][1]); ov.y = (lo + hi) * inv;
        UNPACK2(lo, hi, o2[i][2]); ov.z = (lo + hi) * inv;
        UNPACK2(lo, hi, o2[i][3]); ov.w = (lo + hi) * inv;
        *(float4*)&Ctx[((size_t)b * L_ + row) * D_ + h * HD_ + tx * 4] = ov;
    }
}

// ---------------------------------------------------------------------------
// LayerNorm over last dim (1024).
// ---------------------------------------------------------------------------
__global__ __launch_bounds__(256) void lnorm(
    const float* __restrict__ X, const float* __restrict__ hsc,
    const float* __restrict__ hbi, float* __restrict__ out)
{
    int row = blockIdx.x;
    int c4 = threadIdx.x * 4;
    const float* x = X + (size_t)row * D_;
    float4 v = *(const float4*)(x + c4);
    float sum = v.x + v.y + v.z + v.w;
    float sq  = v.x*v.x + v.y*v.y + v.z*v.z + v.w*v.w;
    #pragma unroll
    for (int off = 16; off > 0; off >>= 1) {
        sum += __shfl_xor_sync(0xffffffffu, sum, off);
        sq  += __shfl_xor_sync(0xffffffffu, sq,  off);
    }
    __shared__ float rs[8], rq[8];
    int warp = threadIdx.x >> 5;
    if ((threadIdx.x & 31) == 0) { rs[warp] = sum; rq[warp] = sq; }
    __syncthreads();
    float tot = 0.f, totq = 0.f;
    #pragma unroll
    for (int w = 0; w < 8; w++) { tot += rs[w]; totq += rq[w]; }
    float mu  = tot  * (1.0f / 1024.0f);
    float var = totq * (1.0f / 1024.0f) - mu * mu;
    float inv = rsqrtf(var + 1e-12f);
    float4 sc = *(const float4*)(hsc + c4);
    float4 bi = *(const float4*)(hbi + c4);
    float4 o;
    o.x = (v.x - mu) * inv * sc.x + bi.x;
    o.y = (v.y - mu) * inv * sc.y + bi.y;
    o.z = (v.z - mu) * inv * sc.z + bi.z;
    o.w = (v.w - mu) * inv * sc.w + bi.w;
    *(float4*)&out[(size_t)row * D_ + c4] = o;
}

// ---------------------------------------------------------------------------
extern "C" void kernel_launch(void* const* d_in, const int* in_sizes, int n_in,
                              void* d_out, int out_size)
{
    const float* hidden = (const float*)d_in[0];
    const float* mask   = (const float*)d_in[1];
    const float* phi    = (const float*)d_in[2];
    const float* mag    = (const float*)d_in[3];
    const float* Wq     = (const float*)d_in[4];
    const float* bq     = (const float*)d_in[5];
    const float* Wk     = (const float*)d_in[6];
    const float* bk     = (const float*)d_in[7];
    const float* Wv     = (const float*)d_in[8];
    const float* bv     = (const float*)d_in[9];
    const float* gamma  = (const float*)d_in[10];
    const float* Wo     = (const float*)d_in[11];
    const float* bo     = (const float*)d_in[12];
    const float* lns    = (const float*)d_in[13];
    const float* lnb    = (const float*)d_in[14];
    float* out = (float*)d_out;

    float *q, *k, *v, *ctx, *x;
    __nv_bfloat16 *ahi, *alo, *wthi, *wtlo;
    cudaGetSymbolAddress((void**)&q,    g_q);
    cudaGetSymbolAddress((void**)&k,    g_k);
    cudaGetSymbolAddress((void**)&v,    g_v);
    cudaGetSymbolAddress((void**)&ctx,  g_ctx);
    cudaGetSymbolAddress((void**)&x,    g_x);
    cudaGetSymbolAddress((void**)&ahi,  g_ahi);
    cudaGetSymbolAddress((void**)&alo,  g_alo);
    cudaGetSymbolAddress((void**)&wthi, g_wthi);
    cudaGetSymbolAddress((void**)&wtlo, g_wtlo);

    cudaFuncSetAttribute(gemm_hmma, cudaFuncAttributeMaxDynamicSharedMemorySize, GEMM_DYN);
    cudaFuncSetAttribute(attn64, cudaFuncAttributeMaxDynamicSharedMemorySize, ATTN_DYN);

    const int DD = D_ * D_;

    convA<<<(M_TOT * D_ / 4 + 255) / 256, 256>>>((const float4*)hidden, (uint2*)ahi, (uint2*)alo, M_TOT * D_ / 4);
    convW<<<dim3(32, 32), 256>>>(Wq, wthi + 0*DD, wtlo + 0*DD);
    convW<<<dim3(32, 32), 256>>>(Wk, wthi + 1*DD, wtlo + 1*DD);
    convW<<<dim3(32, 32), 256>>>(Wv, wthi + 2*DD, wtlo + 2*DD);
    convW<<<dim3(32, 32), 256>>>(Wo, wthi + 3*DD, wtlo + 3*DD);

    dim3 gg(D_ / GN, M_TOT / GM);   // (8, 32)
    gemm_hmma<<<gg, 256, GEMM_DYN>>>(ahi, alo, wthi + 0*DD, wtlo + 0*DD, bq, nullptr, q);
    gemm_hmma<<<gg, 256, GEMM_DYN>>>(ahi, alo, wthi + 1*DD, wtlo + 1*DD, bk, nullptr, k);
    gemm_hmma<<<gg, 256, GEMM_DYN>>>(ahi, alo, wthi + 2*DD, wtlo + 2*DD, bv, nullptr, v);

    rotscale<<<(B_ * L_ * H_ * 32) / 256, 256>>>(q, k, phi, mag, gamma);

    attn64<<<dim3(L_ / 64, B_ * H_), 256, ATTN_DYN>>>(q, k, v, mask, ctx);

    convA<<<(M_TOT * D_ / 4 + 255) / 256, 256>>>((const float4*)ctx, (uint2*)ahi, (uint2*)alo, M_TOT * D_ / 4);
    gemm_hmma<<<gg, 256, GEMM_DYN>>>(ahi, alo, wthi + 3*DD, wtlo + 3*DD, bo, hidden, x);

    lnorm<<<M_TOT, 256>>>(x, lns, lnb, out);
}

// round 4
// speedup vs baseline: 1.4911x; 1.0690x over previous
#include <cuda_runtime.h>
#include <cuda_bf16.h>
#include <math.h>
#include <stdint.h>

#define B_  4
#define L_  1024
#define D_  1024
#define H_  16
#define HD_ 64
#define M_TOT (B_*L_)   // 4096

typedef unsigned long long ull;

// ---------------------------------------------------------------------------
// Scratch
// ---------------------------------------------------------------------------
__device__ float g_q[M_TOT * D_];
__device__ float g_k[M_TOT * D_];
__device__ float g_v[M_TOT * D_];
__device__ float g_ctx[M_TOT * D_];
__device__ float g_x[M_TOT * D_];
__device__ __nv_bfloat16 g_ahi[M_TOT * D_];
__device__ __nv_bfloat16 g_alo[M_TOT * D_];
__device__ __nv_bfloat16 g_wthi[4 * D_ * D_];   // W^T [N][K] hi (q,k,v,o)
__device__ __nv_bfloat16 g_wtlo[4 * D_ * D_];

// ---------------------------------------------------------------------------
// Helpers
// ---------------------------------------------------------------------------
__device__ __forceinline__ uint32_t smem_to_u32(const void* p) {
    uint32_t a;
    asm("{ .reg .u64 t; cvta.to.shared.u64 t, %1; cvt.u32.u64 %0, t; }"
        : "=r"(a) : "l"(p));
    return a;
}

#define CP16(dst, src) \
    asm volatile("cp.async.cg.shared.global [%0], [%1], 16;" \
                 :: "r"(dst), "l"(src) : "memory")
#define CP_COMMIT() asm volatile("cp.async.commit_group;" ::: "memory")

#define LDSM4(r, addr) \
    asm volatile("ldmatrix.sync.aligned.m8n8.x4.shared.b16 {%0,%1,%2,%3}, [%4];" \
                 : "=r"((r)[0]), "=r"((r)[1]), "=r"((r)[2]), "=r"((r)[3]) : "r"(addr))

#define MMA16816(c, a, b0, b1) \
    asm volatile("mma.sync.aligned.m16n8k16.row.col.f32.bf16.bf16.f32 " \
                 "{%0,%1,%2,%3}, {%4,%5,%6,%7}, {%8,%9}, {%0,%1,%2,%3};" \
                 : "+f"((c)[0]), "+f"((c)[1]), "+f"((c)[2]), "+f"((c)[3]) \
                 : "r"((a)[0]), "r"((a)[1]), "r"((a)[2]), "r"((a)[3]), \
                   "r"(b0), "r"(b1))

#define LDS64(v, addr) \
    asm volatile("ld.shared.b64 %0, [%1];" : "=l"(v) : "r"(addr))
#define FMA2(acc, a, b) \
    asm volatile("fma.rn.f32x2 %0, %1, %2, %0;" : "+l"(acc) : "l"(a), "l"(b))
#define MUL2(acc, b) \
    asm volatile("mul.rn.f32x2 %0, %0, %1;" : "+l"(acc) : "l"(b))
#define PACK2(d, f) \
    asm volatile("mov.b64 %0, {%1, %1};" : "=l"(d) : "f"(f))
#define UNPACK2(lo, hi, v) \
    asm volatile("mov.b64 {%0, %1}, %2;" : "=f"(lo), "=f"(hi) : "l"(v))

// ---------------------------------------------------------------------------
// fp32 -> bf16 hi/lo split
// ---------------------------------------------------------------------------
__device__ __forceinline__ void split1(float x, uint32_t& h, uint32_t& l) {
    __nv_bfloat16 hb = __float2bfloat16(x);
    float hf = __bfloat162float(hb);
    __nv_bfloat16 lb = __float2bfloat16(x - hf);
    h = (uint32_t)__bfloat16_as_ushort(hb);
    l = (uint32_t)__bfloat16_as_ushort(lb);
}

__global__ __launch_bounds__(256) void convA(
    const float4* __restrict__ x, uint2* __restrict__ hi, uint2* __restrict__ lo, int n4)
{
    int i = blockIdx.x * 256 + threadIdx.x;
    if (i >= n4) return;
    float4 v = x[i];
    uint32_t h0,l0,h1,l1,h2,l2,h3,l3;
    split1(v.x, h0, l0); split1(v.y, h1, l1);
    split1(v.z, h2, l2); split1(v.w, h3, l3);
    uint2 ho, lv;
    ho.x = h0 | (h1 << 16); ho.y = h2 | (h3 << 16);
    lv.x = l0 | (l1 << 16); lv.y = l2 | (l3 << 16);
    hi[i] = ho; lo[i] = lv;
}

// W[K,N] fp32 -> WT[N,K] bf16 hi/lo
__global__ __launch_bounds__(256) void convW(
    const float* __restrict__ W, __nv_bfloat16* __restrict__ hi, __nv_bfloat16* __restrict__ lo)
{
    __shared__ float t[32][33];
    int n0 = blockIdx.x * 32, k0 = blockIdx.y * 32;
    int tx = threadIdx.x & 31, ty = threadIdx.x >> 5;
    #pragma unroll
    for (int j = 0; j < 4; j++)
        t[ty + j*8][tx] = W[(size_t)(k0 + ty + j*8) * D_ + n0 + tx];
    __syncthreads();
    #pragma unroll
    for (int j = 0; j < 4; j++) {
        float v = t[tx][ty + j*8];
        uint32_t h, l;
        split1(v, h, l);
        size_t o = (size_t)(n0 + ty + j*8) * D_ + k0 + tx;
        hi[o] = __ushort_as_bfloat16((unsigned short)h);
        lo[o] = __ushort_as_bfloat16((unsigned short)l);
    }
}

// ---------------------------------------------------------------------------
// HMMA bf16 3-term GEMM, wide tile: C[M,N] = A @ W (+bias, +res).
// CTA tile 128x256, KC=64, 512 threads = 16 warps (32x64 warp tiles).
// Smem: 128B rows, XOR swizzle (seg ^ (row&7)); no padding.
// grid.z selects (weight matrix, bias, output) -> QKV fused in one launch.
// ---------------------------------------------------------------------------
#define GM 128
#define GN 256
#define KC 64
#define OFF_ALO  16384
#define OFF_BHI  32768
#define OFF_BLO  65536
#define STAGE    98304
#define GEMM_DYN (2*STAGE)   // 196608 B

__global__ __launch_bounds__(512, 1) void gemm_hmma(
    const __nv_bfloat16* __restrict__ Ahi, const __nv_bfloat16* __restrict__ Alo,
    const __nv_bfloat16* __restrict__ WThi, const __nv_bfloat16* __restrict__ WTlo,
    const float* __restrict__ bias0, const float* __restrict__ bias1,
    const float* __restrict__ bias2,
    float* __restrict__ C0, float* __restrict__ C1, float* __restrict__ C2,
    const float* __restrict__ res)
{
    extern __shared__ char smraw[];
    const uint32_t sbase = smem_to_u32(smraw);
    const int tid  = threadIdx.x;
    const int lane = tid & 31, wid = tid >> 5;
    const int wm = wid >> 2, wn = wid & 3;
    const int bm = blockIdx.y * GM, bn = blockIdx.x * GN;
    const int z  = blockIdx.z;

    const __nv_bfloat16* Bh = WThi + (size_t)z * D_ * D_;
    const __nv_bfloat16* Bl = WTlo + (size_t)z * D_ * D_;
    const float* bias = (z == 0) ? bias0 : (z == 1) ? bias1 : bias2;
    float* C = (z == 0) ? C0 : (z == 1) ? C1 : C2;

    const int rr  = tid >> 3;      // 0..63
    const int seg = tid & 7;       // 16B segment within 128B row

    #define LOAD_STAGE(s, kc) do { \
        uint32_t sb_ = sbase + (uint32_t)(s) * STAGE; \
        _Pragma("unroll") \
        for (int h2 = 0; h2 < 2; h2++) { \
            int r_ = rr + h2 * 64; \
            uint32_t sw_ = (uint32_t)r_ * 128 + (uint32_t)((seg ^ (r_ & 7)) << 4); \
            size_t g_ = (size_t)(bm + r_) * D_ + (kc) + seg * 8; \
            CP16(sb_ + sw_,           Ahi + g_); \
            CP16(sb_ + OFF_ALO + sw_, Alo + g_); \
        } \
        _Pragma("unroll") \
        for (int h4 = 0; h4 < 4; h4++) { \
            int r_ = rr + h4 * 64; \
            uint32_t sw_ = (uint32_t)r_ * 128 + (uint32_t)((seg ^ (r_ & 7)) << 4); \
            size_t g_ = (size_t)(bn + r_) * D_ + (kc) + seg * 8; \
            CP16(sb_ + OFF_BHI + sw_, Bh + g_); \
            CP16(sb_ + OFF_BLO + sw_, Bl + g_); \
        } \
        CP_COMMIT(); \
    } while (0)

    float c[2][8][4];
    #pragma unroll
    for (int mi = 0; mi < 2; mi++)
        #pragma unroll
        for (int ni = 0; ni < 8; ni++)
            #pragma unroll
            for (int e = 0; e < 4; e++) c[mi][ni][e] = 0.f;

    LOAD_STAGE(0, 0);

    // per-lane ldmatrix row bases (swizzle-friendly)
    const int rA  = wm * 32 + (lane & 15);                         // A row base
    const int rB  = wn * 64 + ((lane >> 4) << 3) + (lane & 7);     // B row base
    const int sgA = lane >> 4;            // extra A segment select
    const int sgB = (lane >> 3) & 1;      // extra B segment select

    for (int ch = 0; ch < 16; ch++) {
        if (ch < 15) {
            LOAD_STAGE((ch + 1) & 1, (ch + 1) * KC);
            asm volatile("cp.async.wait_group 1;" ::: "memory");
        } else {
            asm volatile("cp.async.wait_group 0;" ::: "memory");
        }
        __syncthreads();

        const uint32_t sb = sbase + (uint32_t)(ch & 1) * STAGE;
        #pragma unroll
        for (int ks = 0; ks < 4; ks++) {
            uint32_t ah[2][4], al[2][4];
            {
                uint32_t swa = (uint32_t)(((ks * 2 + sgA) ^ (rA & 7)) << 4);
                #pragma unroll
                for (int mi = 0; mi < 2; mi++) {
                    uint32_t addr = sb + (uint32_t)(rA + mi * 16) * 128 + swa;
                    LDSM4(ah[mi], addr);
                    LDSM4(al[mi], addr + OFF_ALO);
                }
            }
            uint32_t swb = (uint32_t)(((ks * 2 + sgB) ^ (rB & 7)) << 4);
            #pragma unroll
            for (int np = 0; np < 4; np++) {
                uint32_t bh[4], bl[4];
                uint32_t addr = sb + OFF_BHI + (uint32_t)(rB + np * 16) * 128 + swb;
                LDSM4(bh, addr);
                LDSM4(bl, addr + (OFF_BLO - OFF_BHI));
                #pragma unroll
                for (int mi = 0; mi < 2; mi++)
                    #pragma unroll
                    for (int hf = 0; hf < 2; hf++) {
                        int ni = np * 2 + hf, rb = hf * 2;
                        MMA16816(c[mi][ni], ah[mi], bh[rb], bh[rb + 1]);
                        MMA16816(c[mi][ni], ah[mi], bl[rb], bl[rb + 1]);
                        MMA16816(c[mi][ni], al[mi], bh[rb], bh[rb + 1]);
                    }
            }
        }
        __syncthreads();
    }

    // ---- epilogue ----
    const int g = lane >> 2, tig = lane & 3;
    #pragma unroll
    for (int mi = 0; mi < 2; mi++) {
        int row0 = bm + wm * 32 + mi * 16 + g;
        #pragma unroll
        for (int ni = 0; ni < 8; ni++) {
            int col = bn + wn * 64 + ni * 8 + tig * 2;
            float2 bv = *(const float2*)(bias + col);
            float2 o0, o1;
            o0.x = c[mi][ni][0] + bv.x; o0.y = c[mi][ni][1] + bv.y;
            o1.x = c[mi][ni][2] + bv.x; o1.y = c[mi][ni][3] + bv.y;
            if (res) {
                float2 r0 = *(const float2*)(res + (size_t)row0 * D_ + col);
                float2 r1 = *(const float2*)(res + (size_t)(row0 + 8) * D_ + col);
                o0.x += r0.x; o0.y += r0.y;
                o1.x += r1.x; o1.y += r1.y;
            }
            *(float2*)(C + (size_t)row0 * D_ + col) = o0;
            *(float2*)(C + (size_t)(row0 + 8) * D_ + col) = o1;
        }
    }
    #undef LOAD_STAGE
}

// ---------------------------------------------------------------------------
// In-place per-head scale (1 + gamma*tanh(mag)) + rotation by phase phi.
// ---------------------------------------------------------------------------
__global__ __launch_bounds__(256) void rotscale(
    float* __restrict__ q, float* __restrict__ k,
    const float* __restrict__ phi, const float* __restrict__ mag,
    const float* __restrict__ gamma)
{
    int idx = blockIdx.x * 256 + threadIdx.x;
    int d = idx & 31;
    int h = (idx >> 5) & 15;
    int l = (idx >> 9) & 1023;
    int b = idx >> 19;
    int phl = (b * 16 + h) * 1024 + l;
    float sc = 1.0f + gamma[h] * tanhf(mag[phl]);
    float s, c;
    sincosf(phi[phl], &s, &c);
    int base = (b * 1024 + l) * 1024 + h * 64 + d;
    float q1 = q[base] * sc, q2 = q[base + 32] * sc;
    q[base]      = q1 * c - q2 * s;
    q[base + 32] = q2 * c + q1 * s;
    float k1 = k[base] * sc, k2 = k[base + 32] * sc;
    k[base]      = k1 * c - k2 * s;
    k[base + 32] = k2 * c + k1 * s;
}

// ---------------------------------------------------------------------------
// Flash-style fp32 attention with packed f32x2 FMAs (unchanged from R3).
// ---------------------------------------------------------------------------
#define ATTN_DYN (3 * 64 * 64 * 4)   // 49152 B

__global__ __launch_bounds__(256) void attn64(
    const float* __restrict__ Q, const float* __restrict__ K,
    const float* __restrict__ V, const float* __restrict__ mask,
    float* __restrict__ Ctx)
{
    extern __shared__ float sm[];
    const uint32_t sb = smem_to_u32(sm);
    const int tid = threadIdx.x;
    const int tx = tid & 15, ty = tid >> 4;
    const int qt = blockIdx.x;
    const int b = blockIdx.y >> 4, h = blockIdx.y & 15;

    const float* Qg = Q + (size_t)b * L_ * D_ + h * HD_;
    const float* Kg = K + (size_t)b * L_ * D_ + h * HD_;
    const float* Vg = V + (size_t)b * L_ * D_ + h * HD_;
    const float* mk = mask + b * L_;

    for (int i = tid; i < 1024; i += 256) {
        int r = i >> 4, cc = i & 15;
        float4 qv = *(const float4*)(Qg + (size_t)(qt * 64 + r) * D_ + 4 * cc);
        int sw = (r >> 2) & 15;
        float* row = sm + r * 64;
        *(float2*)(row + 2 * ((2 * cc) ^ sw))     = make_float2(qv.x, qv.y);
        *(float2*)(row + 2 * ((2 * cc + 1) ^ sw)) = make_float2(qv.z, qv.w);
    }

    ull o2[4][4];
    float mrow[4], lrow[4];
    #pragma unroll
    for (int i = 0; i < 4; i++) {
        mrow[i] = -INFINITY; lrow[i] = 0.f;
        #pragma unroll
        for (int j = 0; j < 4; j++) o2[i][j] = 0ull;
    }

    for (int kt = 0; kt < 16; kt++) {
        __syncthreads();
        for (int i = tid; i < 1024; i += 256) {
            int r = i >> 4, cc = i & 15;
            float4 kv = *(const float4*)(Kg + (size_t)(kt * 64 + r) * D_ + 4 * cc);
            int sw = (r >> 2) & 15;
            float* row = sm + 4096 + r * 64;
            *(float2*)(row + 2 * ((2 * cc) ^ sw))     = make_float2(kv.x, kv.y);
            *(float2*)(row + 2 * ((2 * cc + 1) ^ sw)) = make_float2(kv.z, kv.w);

            float4 vv = *(const float4*)(Vg + (size_t)(kt * 64 + r) * D_ + 4 * cc);
            int off = 2 * ((r >> 1) ^ cc) + (r & 1);
            float* vbase = sm + 8192 + 4 * cc * 64 + off;
            vbase[0]   = vv.x;
            vbase[64]  = vv.y;
            vbase[128] = vv.z;
            vbase[192] = vv.w;
        }
        __syncthreads();

        ull acc[4][4];
        #pragma unroll
        for (int i = 0; i < 4; i++)
            #pragma unroll
            for (int j = 0; j < 4; j++) acc[i][j] = 0ull;

        const uint32_t qb = sb + (uint32_t)(ty * 4 * 64) * 4;
        const uint32_t kb = sb + 4096u * 4 + (uint32_t)(tx * 4 * 64) * 4;
        #pragma unroll 4
        for (int kp = 0; kp < 32; kp++) {
            uint32_t oq = (uint32_t)((kp ^ ty) << 3);
            uint32_t ok = (uint32_t)((kp ^ tx) << 3);
            ull qa[4], kv2[4];
            #pragma unroll
            for (int i = 0; i < 4; i++) LDS64(qa[i], qb + i * 256 + oq);
            #pragma unroll
            for (int j = 0; j < 4; j++) LDS64(kv2[j], kb + j * 256 + ok);
            #pragma unroll
            for (int i = 0; i < 4; i++)
                #pragma unroll
                for (int j = 0; j < 4; j++)
                    FMA2(acc[i][j], qa[i], kv2[j]);
        }

        float s[4][4];
        float4 mj = *(const float4*)&mk[kt * 64 + tx * 4];
        #pragma unroll
        for (int i = 0; i < 4; i++) {
            #pragma unroll
            for (int j = 0; j < 4; j++) {
                float lo, hi;
                UNPACK2(lo, hi, acc[i][j]);
                s[i][j] = (lo + hi) * 0.125f;
            }
            s[i][0] += mj.x; s[i][1] += mj.y; s[i][2] += mj.z; s[i][3] += mj.w;
        }

        float p[4][4];
        #pragma unroll
        for (int i = 0; i < 4; i++) {
            float tmax = fmaxf(fmaxf(s[i][0], s[i][1]), fmaxf(s[i][2], s[i][3]));
            #pragma unroll
            for (int off = 8; off > 0; off >>= 1)
                tmax = fmaxf(tmax, __shfl_xor_sync(0xffffffffu, tmax, off));
            float mnew = fmaxf(mrow[i], tmax);
            float corr = __expf(mrow[i] - mnew);
            mrow[i] = mnew;
            p[i][0] = __expf(s[i][0] - mnew);
            p[i][1] = __expf(s[i][1] - mnew);
            p[i][2] = __expf(s[i][2] - mnew);
            p[i][3] = __expf(s[i][3] - mnew);
            float tsum = p[i][0] + p[i][1] + p[i][2] + p[i][3];
            #pragma unroll
            for (int off = 8; off > 0; off >>= 1)
                tsum += __shfl_xor_sync(0xffffffffu, tsum, off);
            lrow[i] = lrow[i] * corr + tsum;
            ull cs; PACK2(cs, corr);
            #pragma unroll
            for (int j = 0; j < 4; j++) MUL2(o2[i][j], cs);
        }

        __syncthreads();
        #pragma unroll
        for (int i = 0; i < 4; i++) {
            float* prow = sm + 4096 + (ty * 4 + i) * 64;
            *(float2*)(prow + 2 * ((2 * tx) ^ ty))     = make_float2(p[i][0], p[i][1]);
            *(float2*)(prow + 2 * ((2 * tx + 1) ^ ty)) = make_float2(p[i][2], p[i][3]);
        }
        __syncthreads();

        const uint32_t pb = sb + 4096u * 4 + (uint32_t)(ty * 4 * 64) * 4;
        const uint32_t vb = sb + 8192u * 4 + (uint32_t)(tx * 4 * 64) * 4;
        #pragma unroll 4
        for (int kp = 0; kp < 32; kp++) {
            uint32_t op = (uint32_t)((kp ^ ty) << 3);
            uint32_t ov = (uint32_t)((kp ^ tx) << 3);
            ull pa[4], vv2[4];
            #pragma unroll
            for (int i = 0; i < 4; i++) LDS64(pa[i], pb + i * 256 + op);
            #pragma unroll
            for (int j = 0; j < 4; j++) LDS64(vv2[j], vb + j * 256 + ov);
            #pragma unroll
            for (int i = 0; i < 4; i++)
                #pragma unroll
                for (int j = 0; j < 4; j++)
                    FMA2(o2[i][j], pa[i], vv2[j]);
        }
    }

    #pragma unroll
    for (int i = 0; i < 4; i++) {
        float inv = 1.0f / lrow[i];
        int row = qt * 64 + ty * 4 + i;
        float4 ov;
        float lo, hi;
        UNPACK2(lo, hi, o2[i][0]); ov.x = (lo + hi) * inv;
        UNPACK2(lo, hi, o2[i][1]); ov.y = (lo + hi) * inv;
        UNPACK2(lo, hi, o2[i][2]); ov.z = (lo + hi) * inv;
        UNPACK2(lo, hi, o2[i][3]); ov.w = (lo + hi) * inv;
        *(float4*)&Ctx[((size_t)b * L_ + row) * D_ + h * HD_ + tx * 4] = ov;
    }
}

// ---------------------------------------------------------------------------
// LayerNorm over last dim (1024).
// ---------------------------------------------------------------------------
__global__ __launch_bounds__(256) void lnorm(
    const float* __restrict__ X, const float* __restrict__ hsc,
    const float* __restrict__ hbi, float* __restrict__ out)
{
    int row = blockIdx.x;
    int c4 = threadIdx.x * 4;
    const float* x = X + (size_t)row * D_;
    float4 v = *(const float4*)(x + c4);
    float sum = v.x + v.y + v.z + v.w;
    float sq  = v.x*v.x + v.y*v.y + v.z*v.z + v.w*v.w;
    #pragma unroll
    for (int off = 16; off > 0; off >>= 1) {
        sum += __shfl_xor_sync(0xffffffffu, sum, off);
        sq  += __shfl_xor_sync(0xffffffffu, sq,  off);
    }
    __shared__ float rs[8], rq[8];
    int warp = threadIdx.x >> 5;
    if ((threadIdx.x & 31) == 0) { rs[warp] = sum; rq[warp] = sq; }
    __syncthreads();
    float tot = 0.f, totq = 0.f;
    #pragma unroll
    for (int w = 0; w < 8; w++) { tot += rs[w]; totq += rq[w]; }
    float mu  = tot  * (1.0f / 1024.0f);
    float var = totq * (1.0f / 1024.0f) - mu * mu;
    float inv = rsqrtf(var + 1e-12f);
    float4 sc = *(const float4*)(hsc + c4);
    float4 bi = *(const float4*)(hbi + c4);
    float4 o;
    o.x = (v.x - mu) * inv * sc.x + bi.x;
    o.y = (v.y - mu) * inv * sc.y + bi.y;
    o.z = (v.z - mu) * inv * sc.z + bi.z;
    o.w = (v.w - mu) * inv * sc.w + bi.w;
    *(float4*)&out[(size_t)row * D_ + c4] = o;
}

// ---------------------------------------------------------------------------
extern "C" void kernel_launch(void* const* d_in, const int* in_sizes, int n_in,
                              void* d_out, int out_size)
{
    const float* hidden = (const float*)d_in[0];
    const float* mask   = (const float*)d_in[1];
    const float* phi    = (const float*)d_in[2];
    const float* mag    = (const float*)d_in[3];
    const float* Wq     = (const float*)d_in[4];
    const float* bq     = (const float*)d_in[5];
    const float* Wk     = (const float*)d_in[6];
    const float* bk     = (const float*)d_in[7];
    const float* Wv     = (const float*)d_in[8];
    const float* bv     = (const float*)d_in[9];
    const float* gamma  = (const float*)d_in[10];
    const float* Wo     = (const float*)d_in[11];
    const float* bo     = (const float*)d_in[12];
    const float* lns    = (const float*)d_in[13];
    const float* lnb    = (const float*)d_in[14];
    float* out = (float*)d_out;

    float *q, *k, *v, *ctx, *x;
    __nv_bfloat16 *ahi, *alo, *wthi, *wtlo;
    cudaGetSymbolAddress((void**)&q,    g_q);
    cudaGetSymbolAddress((void**)&k,    g_k);
    cudaGetSymbolAddress((void**)&v,    g_v);
    cudaGetSymbolAddress((void**)&ctx,  g_ctx);
    cudaGetSymbolAddress((void**)&x,    g_x);
    cudaGetSymbolAddress((void**)&ahi,  g_ahi);
    cudaGetSymbolAddress((void**)&alo,  g_alo);
    cudaGetSymbolAddress((void**)&wthi, g_wthi);
    cudaGetSymbolAddress((void**)&wtlo, g_wtlo);

    cudaFuncSetAttribute(gemm_hmma, cudaFuncAttributeMaxDynamicSharedMemorySize, GEMM_DYN);
    cudaFuncSetAttribute(attn64, cudaFuncAttributeMaxDynamicSharedMemorySize, ATTN_DYN);

    const int DD = D_ * D_;

    convA<<<(M_TOT * D_ / 4 + 255) / 256, 256>>>((const float4*)hidden, (uint2*)ahi, (uint2*)alo, M_TOT * D_ / 4);
    convW<<<dim3(32, 32), 256>>>(Wq, wthi + 0*DD, wtlo + 0*DD);
    convW<<<dim3(32, 32), 256>>>(Wk, wthi + 1*DD, wtlo + 1*DD);
    convW<<<dim3(32, 32), 256>>>(Wv, wthi + 2*DD, wtlo + 2*DD);
    convW<<<dim3(32, 32), 256>>>(Wo, wthi + 3*DD, wtlo + 3*DD);

    // Fused QKV: grid.z = 3 selects weight/bias/output
    gemm_hmma<<<dim3(D_ / GN, M_TOT / GM, 3), 512, GEMM_DYN>>>(
        ahi, alo, wthi, wtlo, bq, bk, bv, q, k, v, nullptr);

    rotscale<<<(B_ * L_ * H_ * 32) / 256, 256>>>(q, k, phi, mag, gamma);

    attn64<<<dim3(L_ / 64, B_ * H_), 256, ATTN_DYN>>>(q, k, v, mask, ctx);

    convA<<<(M_TOT * D_ / 4 + 255) / 256, 256>>>((const float4*)ctx, (uint2*)ahi, (uint2*)alo, M_TOT * D_ / 4);
    // Wo projection (z=0 slots), with residual
    gemm_hmma<<<dim3(D_ / GN, M_TOT / GM, 1), 512, GEMM_DYN>>>(
        ahi, alo, wthi + 3*DD, wtlo + 3*DD, bo, bo, bo, x, x, x, hidden);

    lnorm<<<M_TOT, 256>>>(x, lns, lnb, out);
}

// round 5
// speedup vs baseline: 2.6260x; 1.7611x over previous
#include <cuda_runtime.h>
#include <cuda_bf16.h>
#include <math.h>
#include <stdint.h>

#define B_  4
#define L_  1024
#define D_  1024
#define H_  16
#define HD_ 64
#define M_TOT (B_*L_)   // 4096

typedef unsigned long long ull;

// ---------------------------------------------------------------------------
// Scratch
// ---------------------------------------------------------------------------
__device__ float g_q[M_TOT * D_];               // fp32 Q, head-major [BH][L][64]
__device__ float g_k[M_TOT * D_];               // fp32 K, head-major
__device__ float g_x[M_TOT * D_];
__device__ __nv_bfloat16 g_ahi[M_TOT * D_];     // activations / ctx hi
__device__ __nv_bfloat16 g_alo[M_TOT * D_];
__device__ __nv_bfloat16 g_wthi[4 * D_ * D_];   // W^T [N][K] hi (q,k,v,o)
__device__ __nv_bfloat16 g_wtlo[4 * D_ * D_];
__device__ __nv_bfloat16 g_qhi[M_TOT * D_];     // rotated Q/K bf16, head-major
__device__ __nv_bfloat16 g_qlo[M_TOT * D_];
__device__ __nv_bfloat16 g_khi[M_TOT * D_];
__device__ __nv_bfloat16 g_klo[M_TOT * D_];
__device__ __nv_bfloat16 g_vhi[M_TOT * D_];     // V bf16, head-major
__device__ __nv_bfloat16 g_vlo[M_TOT * D_];

// ---------------------------------------------------------------------------
// Helpers
// ---------------------------------------------------------------------------
__device__ __forceinline__ uint32_t smem_to_u32(const void* p) {
    uint32_t a;
    asm("{ .reg .u64 t; cvta.to.shared.u64 t, %1; cvt.u32.u64 %0, t; }"
        : "=r"(a) : "l"(p));
    return a;
}

#define CP16(dst, src) \
    asm volatile("cp.async.cg.shared.global [%0], [%1], 16;" \
                 :: "r"(dst), "l"(src) : "memory")
#define CP_COMMIT() asm volatile("cp.async.commit_group;" ::: "memory")

#define LDSM4(r, addr) \
    asm volatile("ldmatrix.sync.aligned.m8n8.x4.shared.b16 {%0,%1,%2,%3}, [%4];" \
                 : "=r"((r)[0]), "=r"((r)[1]), "=r"((r)[2]), "=r"((r)[3]) : "r"(addr))
#define LDSM4T(r, addr) \
    asm volatile("ldmatrix.sync.aligned.m8n8.x4.trans.shared.b16 {%0,%1,%2,%3}, [%4];" \
                 : "=r"((r)[0]), "=r"((r)[1]), "=r"((r)[2]), "=r"((r)[3]) : "r"(addr))

#define MMA16816(c, a, b0, b1) \
    asm volatile("mma.sync.aligned.m16n8k16.row.col.f32.bf16.bf16.f32 " \
                 "{%0,%1,%2,%3}, {%4,%5,%6,%7}, {%8,%9}, {%0,%1,%2,%3};" \
                 : "+f"((c)[0]), "+f"((c)[1]), "+f"((c)[2]), "+f"((c)[3]) \
                 : "r"((a)[0]), "r"((a)[1]), "r"((a)[2]), "r"((a)[3]), \
                   "r"(b0), "r"(b1))

// fp32 -> bf16 hi/lo split
__device__ __forceinline__ void split1(float x, uint32_t& h, uint32_t& l) {
    __nv_bfloat16 hb = __float2bfloat16(x);
    float hf = __bfloat162float(hb);
    __nv_bfloat16 lb = __float2bfloat16(x - hf);
    h = (uint32_t)__bfloat16_as_ushort(hb);
    l = (uint32_t)__bfloat16_as_ushort(lb);
}
// two floats -> packed bf16x2 hi + lo
__device__ __forceinline__ void split2(float x, float y, uint32_t& h, uint32_t& l) {
    uint32_t hx, lx, hy, ly;
    split1(x, hx, lx); split1(y, hy, ly);
    h = hx | (hy << 16);
    l = lx | (ly << 16);
}

// ---------------------------------------------------------------------------
// convA: fp32 -> bf16 hi/lo (hidden states)
// ---------------------------------------------------------------------------
__global__ __launch_bounds__(256) void convA(
    const float4* __restrict__ x, uint2* __restrict__ hi, uint2* __restrict__ lo, int n4)
{
    int i = blockIdx.x * 256 + threadIdx.x;
    if (i >= n4) return;
    float4 v = x[i];
    uint2 ho, lv;
    split2(v.x, v.y, ho.x, lv.x);
    split2(v.z, v.w, ho.y, lv.y);
    hi[i] = ho; lo[i] = lv;
}

// W[K,N] fp32 -> WT[N,K] bf16 hi/lo
__global__ __launch_bounds__(256) void convW(
    const float* __restrict__ W, __nv_bfloat16* __restrict__ hi, __nv_bfloat16* __restrict__ lo)
{
    __shared__ float t[32][33];
    int n0 = blockIdx.x * 32, k0 = blockIdx.y * 32;
    int tx = threadIdx.x & 31, ty = threadIdx.x >> 5;
    #pragma unroll
    for (int j = 0; j < 4; j++)
        t[ty + j*8][tx] = W[(size_t)(k0 + ty + j*8) * D_ + n0 + tx];
    __syncthreads();
    #pragma unroll
    for (int j = 0; j < 4; j++) {
        float v = t[tx][ty + j*8];
        uint32_t h, l;
        split1(v, h, l);
        size_t o = (size_t)(n0 + ty + j*8) * D_ + k0 + tx;
        hi[o] = __ushort_as_bfloat16((unsigned short)h);
        lo[o] = __ushort_as_bfloat16((unsigned short)l);
    }
}

// ---------------------------------------------------------------------------
// HMMA bf16 3-term GEMM, 128x256 tile, 512 threads.
// Two modes:
//  res == nullptr: QKV (grid.z=3). z=0/1 -> fp32 head-major to qf/kf.
//                  z=2 -> bf16 hi/lo head-major to vh/vl.
//  res != nullptr: Wo. fp32 row-major + bias + residual -> xout.
// ---------------------------------------------------------------------------
#define GM 128
#define GN 256
#define KC 64
#define OFF_ALO  16384
#define OFF_BHI  32768
#define OFF_BLO  65536
#define STAGE    98304
#define GEMM_DYN (2*STAGE)

__device__ __forceinline__ size_t headmaj(int row, int col) {
    return (((size_t)(row >> 10) * 16 + (col >> 6)) * 1024 + (row & 1023)) * 64 + (col & 63);
}

__global__ __launch_bounds__(512, 1) void gemm_hmma(
    const __nv_bfloat16* __restrict__ Ahi, const __nv_bfloat16* __restrict__ Alo,
    const __nv_bfloat16* __restrict__ WThi, const __nv_bfloat16* __restrict__ WTlo,
    const float* __restrict__ bias0, const float* __restrict__ bias1,
    const float* __restrict__ bias2,
    float* __restrict__ qf, float* __restrict__ kf,
    __nv_bfloat16* __restrict__ vh, __nv_bfloat16* __restrict__ vl,
    const float* __restrict__ res, float* __restrict__ xout)
{
    extern __shared__ char smraw[];
    const uint32_t sbase = smem_to_u32(smraw);
    const int tid  = threadIdx.x;
    const int lane = tid & 31, wid = tid >> 5;
    const int wm = wid >> 2, wn = wid & 3;
    const int bm = blockIdx.y * GM, bn = blockIdx.x * GN;
    const int z  = blockIdx.z;

    const __nv_bfloat16* Bh = WThi + (size_t)z * D_ * D_;
    const __nv_bfloat16* Bl = WTlo + (size_t)z * D_ * D_;
    const float* bias = (z == 0) ? bias0 : (z == 1) ? bias1 : bias2;

    const int rr  = tid >> 3;
    const int seg = tid & 7;

    #define LOAD_STAGE(s, kc) do { \
        uint32_t sb_ = sbase + (uint32_t)(s) * STAGE; \
        _Pragma("unroll") \
        for (int h2 = 0; h2 < 2; h2++) { \
            int r_ = rr + h2 * 64; \
            uint32_t sw_ = (uint32_t)r_ * 128 + (uint32_t)((seg ^ (r_ & 7)) << 4); \
            size_t g_ = (size_t)(bm + r_) * D_ + (kc) + seg * 8; \
            CP16(sb_ + sw_,           Ahi + g_); \
            CP16(sb_ + OFF_ALO + sw_, Alo + g_); \
        } \
        _Pragma("unroll") \
        for (int h4 = 0; h4 < 4; h4++) { \
            int r_ = rr + h4 * 64; \
            uint32_t sw_ = (uint32_t)r_ * 128 + (uint32_t)((seg ^ (r_ & 7)) << 4); \
            size_t g_ = (size_t)(bn + r_) * D_ + (kc) + seg * 8; \
            CP16(sb_ + OFF_BHI + sw_, Bh + g_); \
            CP16(sb_ + OFF_BLO + sw_, Bl + g_); \
        } \
        CP_COMMIT(); \
    } while (0)

    float c[2][8][4];
    #pragma unroll
    for (int mi = 0; mi < 2; mi++)
        #pragma unroll
        for (int ni = 0; ni < 8; ni++)
            #pragma unroll
            for (int e = 0; e < 4; e++) c[mi][ni][e] = 0.f;

    LOAD_STAGE(0, 0);

    const int rA  = wm * 32 + (lane & 15);
    const int rB  = wn * 64 + ((lane >> 4) << 3) + (lane & 7);
    const int sgA = lane >> 4;
    const int sgB = (lane >> 3) & 1;

    for (int ch = 0; ch < 16; ch++) {
        if (ch < 15) {
            LOAD_STAGE((ch + 1) & 1, (ch + 1) * KC);
            asm volatile("cp.async.wait_group 1;" ::: "memory");
        } else {
            asm volatile("cp.async.wait_group 0;" ::: "memory");
        }
        __syncthreads();

        const uint32_t sb = sbase + (uint32_t)(ch & 1) * STAGE;
        #pragma unroll
        for (int ks = 0; ks < 4; ks++) {
            uint32_t ah[2][4], al[2][4];
            {
                uint32_t swa = (uint32_t)(((ks * 2 + sgA) ^ (rA & 7)) << 4);
                #pragma unroll
                for (int mi = 0; mi < 2; mi++) {
                    uint32_t addr = sb + (uint32_t)(rA + mi * 16) * 128 + swa;
                    LDSM4(ah[mi], addr);
                    LDSM4(al[mi], addr + OFF_ALO);
                }
            }
            uint32_t swb = (uint32_t)(((ks * 2 + sgB) ^ (rB & 7)) << 4);
            #pragma unroll
            for (int np = 0; np < 4; np++) {
                uint32_t bh[4], bl[4];
                uint32_t addr = sb + OFF_BHI + (uint32_t)(rB + np * 16) * 128 + swb;
                LDSM4(bh, addr);
                LDSM4(bl, addr + (OFF_BLO - OFF_BHI));
                #pragma unroll
                for (int mi = 0; mi < 2; mi++)
                    #pragma unroll
                    for (int hf = 0; hf < 2; hf++) {
                        int ni = np * 2 + hf, rb = hf * 2;
                        MMA16816(c[mi][ni], ah[mi], bh[rb], bh[rb + 1]);
                        MMA16816(c[mi][ni], ah[mi], bl[rb], bl[rb + 1]);
                        MMA16816(c[mi][ni], al[mi], bh[rb], bh[rb + 1]);
                    }
            }
        }
        __syncthreads();
    }

    // ---- epilogue ----
    const int g = lane >> 2, tig = lane & 3;
    #pragma unroll
    for (int mi = 0; mi < 2; mi++) {
        int row0 = bm + wm * 32 + mi * 16 + g;
        #pragma unroll
        for (int ni = 0; ni < 8; ni++) {
            int col = bn + wn * 64 + ni * 8 + tig * 2;
            float2 bv = *(const float2*)(bias + col);
            float v0 = c[mi][ni][0] + bv.x, v1 = c[mi][ni][1] + bv.y;
            float v2 = c[mi][ni][2] + bv.x, v3 = c[mi][ni][3] + bv.y;
            if (res) {
                float2 r0 = *(const float2*)(res + (size_t)row0 * D_ + col);
                float2 r1 = *(const float2*)(res + (size_t)(row0 + 8) * D_ + col);
                *(float2*)(xout + (size_t)row0 * D_ + col) = make_float2(v0 + r0.x, v1 + r0.y);
                *(float2*)(xout + (size_t)(row0 + 8) * D_ + col) = make_float2(v2 + r1.x, v3 + r1.y);
            } else {
                size_t o0 = headmaj(row0, col), o1 = headmaj(row0 + 8, col);
                if (z == 0) {
                    *(float2*)(qf + o0) = make_float2(v0, v1);
                    *(float2*)(qf + o1) = make_float2(v2, v3);
                } else if (z == 1) {
                    *(float2*)(kf + o0) = make_float2(v0, v1);
                    *(float2*)(kf + o1) = make_float2(v2, v3);
                } else {
                    uint32_t h, l;
                    split2(v0, v1, h, l);
                    *(uint32_t*)(vh + o0) = h; *(uint32_t*)(vl + o0) = l;
                    split2(v2, v3, h, l);
                    *(uint32_t*)(vh + o1) = h; *(uint32_t*)(vl + o1) = l;
                }
            }
        }
    }
    #undef LOAD_STAGE
}

// ---------------------------------------------------------------------------
// rotscale: fp32 head-major Q/K -> rotated/scaled bf16 hi/lo head-major.
// Thread handles pair (d, d+32) of one (bh, l).
// ---------------------------------------------------------------------------
__global__ __launch_bounds__(256) void rotscale(
    const float* __restrict__ q, const float* __restrict__ k,
    const float* __restrict__ phi, const float* __restrict__ mag,
    const float* __restrict__ gamma,
    __nv_bfloat16* __restrict__ qhi, __nv_bfloat16* __restrict__ qlo,
    __nv_bfloat16* __restrict__ khi, __nv_bfloat16* __restrict__ klo)
{
    int idx = blockIdx.x * 256 + threadIdx.x;   // [bh][l][d<32]
    int d = idx & 31;
    int l = (idx >> 5) & 1023;
    int bh = idx >> 15;
    int phl = bh * 1024 + l;
    float sc = 1.0f + gamma[bh & 15] * tanhf(mag[phl]);
    float s, c;
    sincosf(phi[phl], &s, &c);
    size_t base = ((size_t)bh * 1024 + l) * 64 + d;

    float q1 = q[base] * sc, q2 = q[base + 32] * sc;
    float k1 = k[base] * sc, k2 = k[base + 32] * sc;
    uint32_t h, lo;
    split1(q1 * c - q2 * s, h, lo);
    qhi[base] = __ushort_as_bfloat16((unsigned short)h);
    qlo[base] = __ushort_as_bfloat16((unsigned short)lo);
    split1(q2 * c + q1 * s, h, lo);
    qhi[base + 32] = __ushort_as_bfloat16((unsigned short)h);
    qlo[base + 32] = __ushort_as_bfloat16((unsigned short)lo);
    split1(k1 * c - k2 * s, h, lo);
    khi[base] = __ushort_as_bfloat16((unsigned short)h);
    klo[base] = __ushort_as_bfloat16((unsigned short)lo);
    split1(k2 * c + k1 * s, h, lo);
    khi[base + 32] = __ushort_as_bfloat16((unsigned short)h);
    klo[base + 32] = __ushort_as_bfloat16((unsigned short)lo);
}

// ---------------------------------------------------------------------------
// HMMA flash attention. Block = (qt: 128 q-rows, bh). 256 thr = 8 warps,
// warp w owns q-rows [w*16, w*16+16). KV tiles of 64 keys, double-buffered.
// S = QK^T via 3-term bf16 HMMA; softmax on C-frags; P repacked in regs
// (2-term) for PV; V B-frags via ldmatrix.x4.trans from [key][hd].
// Output written as bf16 hi/lo into the Wo GEMM input buffers.
// ---------------------------------------------------------------------------
#define AT_QHI 0
#define AT_QLO 16384
#define AT_STG 32768                 // + s*32768: Khi,Klo,Vhi,Vlo @ +0,8K,16K,24K
#define AT_MASK (AT_STG + 2*32768)   // 98304
#define ATTN_DYN (AT_MASK + 4096)    // 102400

__global__ __launch_bounds__(256, 2) void attn_hmma(
    const __nv_bfloat16* __restrict__ qhi, const __nv_bfloat16* __restrict__ qlo,
    const __nv_bfloat16* __restrict__ khi, const __nv_bfloat16* __restrict__ klo,
    const __nv_bfloat16* __restrict__ vhi, const __nv_bfloat16* __restrict__ vlo,
    const float* __restrict__ mask,
    __nv_bfloat16* __restrict__ chi, __nv_bfloat16* __restrict__ clo)
{
    extern __shared__ char smraw[];
    const uint32_t sb = smem_to_u32(smraw);
    const int tid = threadIdx.x, lane = tid & 31, w = tid >> 5;
    const int qt = blockIdx.x, bh = blockIdx.y;
    const int b = bh >> 4, h = bh & 15;

    // mask row for this batch (1024 floats)
    CP16(sb + AT_MASK + tid * 16, mask + b * 1024 + tid * 4);
    // Q tile 128x64 hi/lo
    #pragma unroll
    for (int it = 0; it < 4; it++) {
        int idx = tid + it * 256, r = idx >> 3, seg = idx & 7;
        size_t g = ((size_t)bh * 1024 + qt * 128 + r) * 64 + seg * 8;
        uint32_t d = sb + (uint32_t)r * 128 + (uint32_t)((seg ^ (r & 7)) << 4);
        CP16(d + AT_QHI, qhi + g);
        CP16(d + AT_QLO, qlo + g);
    }
    CP_COMMIT();

    #define LOADKV(s, kt_) do { \
        _Pragma("unroll") \
        for (int it = 0; it < 2; it++) { \
            int idx = tid + it * 256, r = idx >> 3, sg = idx & 7; \
            size_t g = ((size_t)bh * 1024 + (kt_) * 64 + r) * 64 + sg * 8; \
            uint32_t d = sb + AT_STG + (uint32_t)(s) * 32768 \
                       + (uint32_t)r * 128 + (uint32_t)((sg ^ (r & 7)) << 4); \
            CP16(d,         khi + g); \
            CP16(d + 8192,  klo + g); \
            CP16(d + 16384, vhi + g); \
            CP16(d + 24576, vlo + g); \
        } \
        CP_COMMIT(); \
    } while (0)

    LOADKV(0, 0);

    float o[8][4];
    #pragma unroll
    for (int j = 0; j < 8; j++)
        #pragma unroll
        for (int e = 0; e < 4; e++) o[j][e] = 0.f;
    float m0 = -INFINITY, m1 = -INFINITY, l0 = 0.f, l1 = 0.f;

    const int rA = w * 16 + (lane & 15);
    const int rBb = ((lane >> 4) << 3) + (lane & 7);
    const int c2 = (lane & 3) * 2;

    for (int kt = 0; kt < 16; kt++) {
        asm volatile("cp.async.wait_group 0;" ::: "memory");
        __syncthreads();
        if (kt < 15) LOADKV((kt + 1) & 1, kt + 1);
        const uint32_t kb = sb + AT_STG + (uint32_t)(kt & 1) * 32768;

        // ---- S = Q K^T ----
        float s[8][4];
        #pragma unroll
        for (int j = 0; j < 8; j++)
            #pragma unroll
            for (int e = 0; e < 4; e++) s[j][e] = 0.f;

        #pragma unroll
        for (int ks = 0; ks < 4; ks++) {
            uint32_t ah[4], al[4];
            uint32_t aaddr = sb + AT_QHI + (uint32_t)rA * 128
                           + (uint32_t)(((ks * 2 + (lane >> 4)) ^ (rA & 7)) << 4);
            LDSM4(ah, aaddr);
            LDSM4(al, aaddr + (AT_QLO - AT_QHI));
            #pragma unroll
            for (int np = 0; np < 4; np++) {
                int rB = np * 16 + rBb;
                uint32_t baddr = kb + (uint32_t)rB * 128
                               + (uint32_t)(((ks * 2 + ((lane >> 3) & 1)) ^ (rB & 7)) << 4);
                uint32_t bhF[4], blF[4];
                LDSM4(bhF, baddr);
                LDSM4(blF, baddr + 8192);
                #pragma unroll
                for (int hf = 0; hf < 2; hf++) {
                    int nt = np * 2 + hf, rb = hf * 2;
                    MMA16816(s[nt], ah, bhF[rb], bhF[rb + 1]);
                    MMA16816(s[nt], ah, blF[rb], blF[rb + 1]);
                    MMA16816(s[nt], al, bhF[rb], bhF[rb + 1]);
                }
            }
        }

        // ---- softmax on C fragments ----
        float mx0 = -INFINITY, mx1 = -INFINITY;
        #pragma unroll
        for (int j = 0; j < 8; j++) {
            float2 mk = *(float2*)(smraw + AT_MASK + (size_t)(kt * 64 + j * 8 + c2) * 4);
            s[j][0] = s[j][0] * 0.125f + mk.x;
            s[j][1] = s[j][1] * 0.125f + mk.y;
            s[j][2] = s[j][2] * 0.125f + mk.x;
            s[j][3] = s[j][3] * 0.125f + mk.y;
            mx0 = fmaxf(mx0, fmaxf(s[j][0], s[j][1]));
            mx1 = fmaxf(mx1, fmaxf(s[j][2], s[j][3]));
        }
        #pragma unroll
        for (int off = 1; off < 4; off <<= 1) {
            mx0 = fmaxf(mx0, __shfl_xor_sync(0xffffffffu, mx0, off));
            mx1 = fmaxf(mx1, __shfl_xor_sync(0xffffffffu, mx1, off));
        }
        float mn0 = fmaxf(m0, mx0), mn1 = fmaxf(m1, mx1);
        float corr0 = __expf(m0 - mn0), corr1 = __expf(m1 - mn1);
        m0 = mn0; m1 = mn1;
        float sum0 = 0.f, sum1 = 0.f;
        #pragma unroll
        for (int j = 0; j < 8; j++) {
            s[j][0] = __expf(s[j][0] - m0);
            s[j][1] = __expf(s[j][1] - m0);
            s[j][2] = __expf(s[j][2] - m1);
            s[j][3] = __expf(s[j][3] - m1);
            sum0 += s[j][0] + s[j][1];
            sum1 += s[j][2] + s[j][3];
        }
        #pragma unroll
        for (int off = 1; off < 4; off <<= 1) {
            sum0 += __shfl_xor_sync(0xffffffffu, sum0, off);
            sum1 += __shfl_xor_sync(0xffffffffu, sum1, off);
        }
        l0 = l0 * corr0 + sum0;
        l1 = l1 * corr1 + sum1;
        #pragma unroll
        for (int j = 0; j < 8; j++) {
            o[j][0] *= corr0; o[j][1] *= corr0;
            o[j][2] *= corr1; o[j][3] *= corr1;
        }

        // ---- O += P V ----
        #pragma unroll
        for (int kg = 0; kg < 4; kg++) {
            uint32_t ph[4], pl[4];
            split2(s[2*kg][0],   s[2*kg][1],   ph[0], pl[0]);
            split2(s[2*kg][2],   s[2*kg][3],   ph[1], pl[1]);
            split2(s[2*kg+1][0], s[2*kg+1][1], ph[2], pl[2]);
            split2(s[2*kg+1][2], s[2*kg+1][3], ph[3], pl[3]);
            int rV = kg * 16 + (lane & 15);
            #pragma unroll
            for (int np = 0; np < 4; np++) {
                uint32_t vaddr = kb + 16384 + (uint32_t)rV * 128
                               + (uint32_t)(((np * 2 + (lane >> 4)) ^ (rV & 7)) << 4);
                uint32_t vhF[4], vlF[4];
                LDSM4T(vhF, vaddr);
                LDSM4T(vlF, vaddr + 8192);
                #pragma unroll
                for (int hf = 0; hf < 2; hf++) {
                    int nt = np * 2 + hf, rb = hf * 2;
                    MMA16816(o[nt], ph, vhF[rb], vhF[rb + 1]);
                    MMA16816(o[nt], pl, vhF[rb], vhF[rb + 1]);
                    MMA16816(o[nt], ph, vlF[rb], vlF[rb + 1]);
                }
            }
        }
    }

    // ---- epilogue: normalize + split to bf16 hi/lo ctx ----
    float i0 = 1.0f / l0, i1 = 1.0f / l1;
    size_t row0 = (size_t)b * 1024 + qt * 128 + w * 16 + (lane >> 2);
    #pragma unroll
    for (int j = 0; j < 8; j++) {
        int col = h * 64 + j * 8 + c2;
        uint32_t hph, lph;
        split2(o[j][0] * i0, o[j][1] * i0, hph, lph);
        *(uint32_t*)(chi + row0 * D_ + col) = hph;
        *(uint32_t*)(clo + row0 * D_ + col) = lph;
        split2(o[j][2] * i1, o[j][3] * i1, hph, lph);
        *(uint32_t*)(chi + (row0 + 8) * D_ + col) = hph;
        *(uint32_t*)(clo + (row0 + 8) * D_ + col) = lph;
    }
    #undef LOADKV
}

// ---------------------------------------------------------------------------
// LayerNorm over last dim (1024).
// ---------------------------------------------------------------------------
__global__ __launch_bounds__(256) void lnorm(
    const float* __restrict__ X, const float* __restrict__ hsc,
    const float* __restrict__ hbi, float* __restrict__ out)
{
    int row = blockIdx.x;
    int c4 = threadIdx.x * 4;
    const float* x = X + (size_t)row * D_;
    float4 v = *(const float4*)(x + c4);
    float sum = v.x + v.y + v.z + v.w;
    float sq  = v.x*v.x + v.y*v.y + v.z*v.z + v.w*v.w;
    #pragma unroll
    for (int off = 16; off > 0; off >>= 1) {
        sum += __shfl_xor_sync(0xffffffffu, sum, off);
        sq  += __shfl_xor_sync(0xffffffffu, sq,  off);
    }
    __shared__ float rs[8], rq[8];
    int warp = threadIdx.x >> 5;
    if ((threadIdx.x & 31) == 0) { rs[warp] = sum; rq[warp] = sq; }
    __syncthreads();
    float tot = 0.f, totq = 0.f;
    #pragma unroll
    for (int wv = 0; wv < 8; wv++) { tot += rs[wv]; totq += rq[wv]; }
    float mu  = tot  * (1.0f / 1024.0f);
    float var = totq * (1.0f / 1024.0f) - mu * mu;
    float inv = rsqrtf(var + 1e-12f);
    float4 sc = *(const float4*)(hsc + c4);
    float4 bi = *(const float4*)(hbi + c4);
    float4 oo;
    oo.x = (v.x - mu) * inv * sc.x + bi.x;
    oo.y = (v.y - mu) * inv * sc.y + bi.y;
    oo.z = (v.z - mu) * inv * sc.z + bi.z;
    oo.w = (v.w - mu) * inv * sc.w + bi.w;
    *(float4*)&out[(size_t)row * D_ + c4] = oo;
}

// ---------------------------------------------------------------------------
extern "C" void kernel_launch(void* const* d_in, const int* in_sizes, int n_in,
                              void* d_out, int out_size)
{
    const float* hidden = (const float*)d_in[0];
    const float* mask   = (const float*)d_in[1];
    const float* phi    = (const float*)d_in[2];
    const float* mag    = (const float*)d_in[3];
    const float* Wq     = (const float*)d_in[4];
    const float* bq     = (const float*)d_in[5];
    const float* Wk     = (const float*)d_in[6];
    const float* bk     = (const float*)d_in[7];
    const float* Wv     = (const float*)d_in[8];
    const float* bv     = (const float*)d_in[9];
    const float* gamma  = (const float*)d_in[10];
    const float* Wo     = (const float*)d_in[11];
    const float* bo     = (const float*)d_in[12];
    const float* lns    = (const float*)d_in[13];
    const float* lnb    = (const float*)d_in[14];
    float* out = (float*)d_out;

    float *q, *k, *x;
    __nv_bfloat16 *ahi, *alo, *wthi, *wtlo, *qhi, *qlo, *khi, *klo, *vhi, *vlo;
    cudaGetSymbolAddress((void**)&q,    g_q);
    cudaGetSymbolAddress((void**)&k,    g_k);
    cudaGetSymbolAddress((void**)&x,    g_x);
    cudaGetSymbolAddress((void**)&ahi,  g_ahi);
    cudaGetSymbolAddress((void**)&alo,  g_alo);
    cudaGetSymbolAddress((void**)&wthi, g_wthi);
    cudaGetSymbolAddress((void**)&wtlo, g_wtlo);
    cudaGetSymbolAddress((void**)&qhi,  g_qhi);
    cudaGetSymbolAddress((void**)&qlo,  g_qlo);
    cudaGetSymbolAddress((void**)&khi,  g_khi);
    cudaGetSymbolAddress((void**)&klo,  g_klo);
    cudaGetSymbolAddress((void**)&vhi,  g_vhi);
    cudaGetSymbolAddress((void**)&vlo,  g_vlo);

    cudaFuncSetAttribute(gemm_hmma, cudaFuncAttributeMaxDynamicSharedMemorySize, GEMM_DYN);
    cudaFuncSetAttribute(attn_hmma, cudaFuncAttributeMaxDynamicSharedMemorySize, ATTN_DYN);

    const int DD = D_ * D_;

    convA<<<(M_TOT * D_ / 4 + 255) / 256, 256>>>((const float4*)hidden, (uint2*)ahi, (uint2*)alo, M_TOT * D_ / 4);
    convW<<<dim3(32, 32), 256>>>(Wq, wthi + 0*DD, wtlo + 0*DD);
    convW<<<dim3(32, 32), 256>>>(Wk, wthi + 1*DD, wtlo + 1*DD);
    convW<<<dim3(32, 32), 256>>>(Wv, wthi + 2*DD, wtlo + 2*DD);
    convW<<<dim3(32, 32), 256>>>(Wo, wthi + 3*DD, wtlo + 3*DD);

    // QKV fused (z: 0=Q fp32, 1=K fp32, 2=V bf16 hi/lo), head-major outputs
    gemm_hmma<<<dim3(D_ / GN, M_TOT / GM, 3), 512, GEMM_DYN>>>(
        ahi, alo, wthi, wtlo, bq, bk, bv, q, k, vhi, vlo, nullptr, nullptr);

    rotscale<<<(B_ * L_ * H_ * 32) / 256, 256>>>(q, k, phi, mag, gamma,
                                                 qhi, qlo, khi, klo);

    attn_hmma<<<dim3(L_ / 128, B_ * H_), 256, ATTN_DYN>>>(
        qhi, qlo, khi, klo, vhi, vlo, mask, ahi, alo);

    // Wo projection + residual (z=0 -> uses wthi+3*DD via pointer offset)
    gemm_hmma<<<dim3(D_ / GN, M_TOT / GM, 1), 512, GEMM_DYN>>>(
        ahi, alo, wthi + 3*DD, wtlo + 3*DD, bo, bo, bo,
        nullptr, nullptr, nullptr, nullptr, hidden, x);

    lnorm<<<M_TOT, 256>>>(x, lns, lnb, out);
}

// round 6
// speedup vs baseline: 2.6984x; 1.0275x over previous
#include <cuda_runtime.h>
#include <cuda_bf16.h>
#include <math.h>
#include <stdint.h>

#define B_  4
#define L_  1024
#define D_  1024
#define H_  16
#define HD_ 64
#define M_TOT (B_*L_)   // 4096

typedef unsigned long long ull;

// ---------------------------------------------------------------------------
// Scratch
// ---------------------------------------------------------------------------
__device__ float g_q[M_TOT * D_];               // fp32 Q, head-major [BH][L][64]
__device__ float g_k[M_TOT * D_];               // fp32 K, head-major
__device__ float g_x[M_TOT * D_];
__device__ __nv_bfloat16 g_ahi[M_TOT * D_];     // activations / ctx hi
__device__ __nv_bfloat16 g_alo[M_TOT * D_];
__device__ __nv_bfloat16 g_wthi[4 * D_ * D_];   // W^T [N][K] hi (q,k,v,o)
__device__ __nv_bfloat16 g_wtlo[4 * D_ * D_];
__device__ __nv_bfloat16 g_qhi[M_TOT * D_];     // rotated Q/K bf16, head-major
__device__ __nv_bfloat16 g_qlo[M_TOT * D_];
__device__ __nv_bfloat16 g_khi[M_TOT * D_];
__device__ __nv_bfloat16 g_klo[M_TOT * D_];
__device__ __nv_bfloat16 g_vhi[M_TOT * D_];     // V bf16, head-major
__device__ __nv_bfloat16 g_vlo[M_TOT * D_];

// ---------------------------------------------------------------------------
// Helpers
// ---------------------------------------------------------------------------
__device__ __forceinline__ uint32_t smem_to_u32(const void* p) {
    uint32_t a;
    asm("{ .reg .u64 t; cvta.to.shared.u64 t, %1; cvt.u32.u64 %0, t; }"
        : "=r"(a) : "l"(p));
    return a;
}

#define CP16(dst, src) \
    asm volatile("cp.async.cg.shared.global [%0], [%1], 16;" \
                 :: "r"(dst), "l"(src) : "memory")
#define CP_COMMIT() asm volatile("cp.async.commit_group;" ::: "memory")

#define LDSM4(r, addr) \
    asm volatile("ldmatrix.sync.aligned.m8n8.x4.shared.b16 {%0,%1,%2,%3}, [%4];" \
                 : "=r"((r)[0]), "=r"((r)[1]), "=r"((r)[2]), "=r"((r)[3]) : "r"(addr))
#define LDSM4T(r, addr) \
    asm volatile("ldmatrix.sync.aligned.m8n8.x4.trans.shared.b16 {%0,%1,%2,%3}, [%4];" \
                 : "=r"((r)[0]), "=r"((r)[1]), "=r"((r)[2]), "=r"((r)[3]) : "r"(addr))

#define MMA16816(c, a, b0, b1) \
    asm volatile("mma.sync.aligned.m16n8k16.row.col.f32.bf16.bf16.f32 " \
                 "{%0,%1,%2,%3}, {%4,%5,%6,%7}, {%8,%9}, {%0,%1,%2,%3};" \
                 : "+f"((c)[0]), "+f"((c)[1]), "+f"((c)[2]), "+f"((c)[3]) \
                 : "r"((a)[0]), "r"((a)[1]), "r"((a)[2]), "r"((a)[3]), \
                   "r"(b0), "r"(b1))

// fp32 -> bf16 hi/lo split
__device__ __forceinline__ void split1(float x, uint32_t& h, uint32_t& l) {
    __nv_bfloat16 hb = __float2bfloat16(x);
    float hf = __bfloat162float(hb);
    __nv_bfloat16 lb = __float2bfloat16(x - hf);
    h = (uint32_t)__bfloat16_as_ushort(hb);
    l = (uint32_t)__bfloat16_as_ushort(lb);
}
__device__ __forceinline__ void split2(float x, float y, uint32_t& h, uint32_t& l) {
    uint32_t hx, lx, hy, ly;
    split1(x, hx, lx); split1(y, hy, ly);
    h = hx | (hy << 16);
    l = lx | (ly << 16);
}

// ---------------------------------------------------------------------------
// convA: fp32 -> bf16 hi/lo
// ---------------------------------------------------------------------------
__global__ __launch_bounds__(256) void convA(
    const float4* __restrict__ x, uint2* __restrict__ hi, uint2* __restrict__ lo, int n4)
{
    int i = blockIdx.x * 256 + threadIdx.x;
    if (i >= n4) return;
    float4 v = x[i];
    uint2 ho, lv;
    split2(v.x, v.y, ho.x, lv.x);
    split2(v.z, v.w, ho.y, lv.y);
    hi[i] = ho; lo[i] = lv;
}

// W[K,N] fp32 -> WT[N,K] bf16 hi/lo; grid.z selects which of 4 matrices.
__global__ __launch_bounds__(256) void convW4(
    const float* __restrict__ Wq, const float* __restrict__ Wk,
    const float* __restrict__ Wv, const float* __restrict__ Wo,
    __nv_bfloat16* __restrict__ hi, __nv_bfloat16* __restrict__ lo)
{
    __shared__ float t[32][33];
    const int z = blockIdx.z;
    const float* W = (z == 0) ? Wq : (z == 1) ? Wk : (z == 2) ? Wv : Wo;
    __nv_bfloat16* hz = hi + (size_t)z * D_ * D_;
    __nv_bfloat16* lz = lo + (size_t)z * D_ * D_;
    int n0 = blockIdx.x * 32, k0 = blockIdx.y * 32;
    int tx = threadIdx.x & 31, ty = threadIdx.x >> 5;
    #pragma unroll
    for (int j = 0; j < 4; j++)
        t[ty + j*8][tx] = W[(size_t)(k0 + ty + j*8) * D_ + n0 + tx];
    __syncthreads();
    #pragma unroll
    for (int j = 0; j < 4; j++) {
        float v = t[tx][ty + j*8];
        uint32_t h, l;
        split1(v, h, l);
        size_t o = (size_t)(n0 + ty + j*8) * D_ + k0 + tx;
        hz[o] = __ushort_as_bfloat16((unsigned short)h);
        lz[o] = __ushort_as_bfloat16((unsigned short)l);
    }
}

// ---------------------------------------------------------------------------
// HMMA bf16 3-term GEMM, 128x256 CTA tile, 256 threads = 8 warps (64x64 tiles).
// 16 LDSM4 per 96 MMAs. Modes as before (QKV z-dispatch / Wo + residual).
// ---------------------------------------------------------------------------
#define GM 128
#define GN 256
#define KC 64
#define OFF_ALO  16384
#define OFF_BHI  32768
#define OFF_BLO  65536
#define STAGE    98304
#define GEMM_DYN (2*STAGE)

__device__ __forceinline__ size_t headmaj(int row, int col) {
    return (((size_t)(row >> 10) * 16 + (col >> 6)) * 1024 + (row & 1023)) * 64 + (col & 63);
}

__global__ __launch_bounds__(256, 1) void gemm_hmma(
    const __nv_bfloat16* __restrict__ Ahi, const __nv_bfloat16* __restrict__ Alo,
    const __nv_bfloat16* __restrict__ WThi, const __nv_bfloat16* __restrict__ WTlo,
    const float* __restrict__ bias0, const float* __restrict__ bias1,
    const float* __restrict__ bias2,
    float* __restrict__ qf, float* __restrict__ kf,
    __nv_bfloat16* __restrict__ vh, __nv_bfloat16* __restrict__ vl,
    const float* __restrict__ res, float* __restrict__ xout)
{
    extern __shared__ char smraw[];
    const uint32_t sbase = smem_to_u32(smraw);
    const int tid  = threadIdx.x;
    const int lane = tid & 31, wid = tid >> 5;
    const int wm = wid >> 2, wn = wid & 3;           // 2 x 4 warps of 64x64
    const int bm = blockIdx.y * GM, bn = blockIdx.x * GN;
    const int z  = blockIdx.z;

    const __nv_bfloat16* Bh = WThi + (size_t)z * D_ * D_;
    const __nv_bfloat16* Bl = WTlo + (size_t)z * D_ * D_;
    const float* bias = (z == 0) ? bias0 : (z == 1) ? bias1 : bias2;

    const int rr  = tid >> 3;      // 0..31
    const int seg = tid & 7;

    #define LOAD_STAGE(s, kc) do { \
        uint32_t sb_ = sbase + (uint32_t)(s) * STAGE; \
        _Pragma("unroll") \
        for (int h4 = 0; h4 < 4; h4++) { \
            int r_ = rr + h4 * 32; \
            uint32_t sw_ = (uint32_t)r_ * 128 + (uint32_t)((seg ^ (r_ & 7)) << 4); \
            size_t g_ = (size_t)(bm + r_) * D_ + (kc) + seg * 8; \
            CP16(sb_ + sw_,           Ahi + g_); \
            CP16(sb_ + OFF_ALO + sw_, Alo + g_); \
        } \
        _Pragma("unroll") \
        for (int h8 = 0; h8 < 8; h8++) { \
            int r_ = rr + h8 * 32; \
            uint32_t sw_ = (uint32_t)r_ * 128 + (uint32_t)((seg ^ (r_ & 7)) << 4); \
            size_t g_ = (size_t)(bn + r_) * D_ + (kc) + seg * 8; \
            CP16(sb_ + OFF_BHI + sw_, Bh + g_); \
            CP16(sb_ + OFF_BLO + sw_, Bl + g_); \
        } \
        CP_COMMIT(); \
    } while (0)

    float c[4][8][4];
    #pragma unroll
    for (int mi = 0; mi < 4; mi++)
        #pragma unroll
        for (int ni = 0; ni < 8; ni++)
            #pragma unroll
            for (int e = 0; e < 4; e++) c[mi][ni][e] = 0.f;

    LOAD_STAGE(0, 0);

    const int rAb = wm * 64 + (lane & 15);
    const int rBb = wn * 64 + ((lane >> 4) << 3) + (lane & 7);
    const int sgA = lane >> 4;
    const int sgB = (lane >> 3) & 1;

    for (int ch = 0; ch < 16; ch++) {
        if (ch < 15) {
            LOAD_STAGE((ch + 1) & 1, (ch + 1) * KC);
            asm volatile("cp.async.wait_group 1;" ::: "memory");
        } else {
            asm volatile("cp.async.wait_group 0;" ::: "memory");
        }
        __syncthreads();

        const uint32_t sb = sbase + (uint32_t)(ch & 1) * STAGE;
        #pragma unroll
        for (int ks = 0; ks < 4; ks++) {
            uint32_t ah[4][4], al[4][4];
            #pragma unroll
            for (int mi = 0; mi < 4; mi++) {
                int rA = rAb + mi * 16;
                uint32_t addr = sb + (uint32_t)rA * 128
                              + (uint32_t)(((ks * 2 + sgA) ^ (rA & 7)) << 4);
                LDSM4(ah[mi], addr);
                LDSM4(al[mi], addr + OFF_ALO);
            }
            #pragma unroll
            for (int np = 0; np < 4; np++) {
                int rB = rBb + np * 16;
                uint32_t addr = sb + OFF_BHI + (uint32_t)rB * 128
                              + (uint32_t)(((ks * 2 + sgB) ^ (rB & 7)) << 4);
                uint32_t bh[4], bl[4];
                LDSM4(bh, addr);
                LDSM4(bl, addr + (OFF_BLO - OFF_BHI));
                #pragma unroll
                for (int hf = 0; hf < 2; hf++) {
                    int ni = np * 2 + hf, rb = hf * 2;
                    #pragma unroll
                    for (int mi = 0; mi < 4; mi++) {
                        MMA16816(c[mi][ni], ah[mi], bh[rb], bh[rb + 1]);
                        MMA16816(c[mi][ni], ah[mi], bl[rb], bl[rb + 1]);
                        MMA16816(c[mi][ni], al[mi], bh[rb], bh[rb + 1]);
                    }
                }
            }
        }
        __syncthreads();
    }

    // ---- epilogue ----
    const int g = lane >> 2, tig = lane & 3;
    #pragma unroll
    for (int mi = 0; mi < 4; mi++) {
        int row0 = bm + wm * 64 + mi * 16 + g;
        #pragma unroll
        for (int ni = 0; ni < 8; ni++) {
            int col = bn + wn * 64 + ni * 8 + tig * 2;
            float2 bv = *(const float2*)(bias + col);
            float v0 = c[mi][ni][0] + bv.x, v1 = c[mi][ni][1] + bv.y;
            float v2 = c[mi][ni][2] + bv.x, v3 = c[mi][ni][3] + bv.y;
            if (res) {
                float2 r0 = *(const float2*)(res + (size_t)row0 * D_ + col);
                float2 r1 = *(const float2*)(res + (size_t)(row0 + 8) * D_ + col);
                *(float2*)(xout + (size_t)row0 * D_ + col) = make_float2(v0 + r0.x, v1 + r0.y);
                *(float2*)(xout + (size_t)(row0 + 8) * D_ + col) = make_float2(v2 + r1.x, v3 + r1.y);
            } else {
                size_t o0 = headmaj(row0, col), o1 = headmaj(row0 + 8, col);
                if (z == 0) {
                    *(float2*)(qf + o0) = make_float2(v0, v1);
                    *(float2*)(qf + o1) = make_float2(v2, v3);
                } else if (z == 1) {
                    *(float2*)(kf + o0) = make_float2(v0, v1);
                    *(float2*)(kf + o1) = make_float2(v2, v3);
                } else {
                    uint32_t h, l;
                    split2(v0, v1, h, l);
                    *(uint32_t*)(vh + o0) = h; *(uint32_t*)(vl + o0) = l;
                    split2(v2, v3, h, l);
                    *(uint32_t*)(vh + o1) = h; *(uint32_t*)(vl + o1) = l;
                }
            }
        }
    }
    #undef LOAD_STAGE
}

// ---------------------------------------------------------------------------
// rotscale: fp32 head-major Q/K -> rotated/scaled bf16 hi/lo head-major.
// ---------------------------------------------------------------------------
__global__ __launch_bounds__(256) void rotscale(
    const float* __restrict__ q, const float* __restrict__ k,
    const float* __restrict__ phi, const float* __restrict__ mag,
    const float* __restrict__ gamma,
    __nv_bfloat16* __restrict__ qhi, __nv_bfloat16* __restrict__ qlo,
    __nv_bfloat16* __restrict__ khi, __nv_bfloat16* __restrict__ klo)
{
    int idx = blockIdx.x * 256 + threadIdx.x;   // [bh][l][d<32]
    int d = idx & 31;
    int l = (idx >> 5) & 1023;
    int bh = idx >> 15;
    int phl = bh * 1024 + l;
    float sc = 1.0f + gamma[bh & 15] * tanhf(mag[phl]);
    float s, c;
    sincosf(phi[phl], &s, &c);
    size_t base = ((size_t)bh * 1024 + l) * 64 + d;

    float q1 = q[base] * sc, q2 = q[base + 32] * sc;
    float k1 = k[base] * sc, k2 = k[base + 32] * sc;
    uint32_t h, lo;
    split1(q1 * c - q2 * s, h, lo);
    qhi[base] = __ushort_as_bfloat16((unsigned short)h);
    qlo[base] = __ushort_as_bfloat16((unsigned short)lo);
    split1(q2 * c + q1 * s, h, lo);
    qhi[base + 32] = __ushort_as_bfloat16((unsigned short)h);
    qlo[base + 32] = __ushort_as_bfloat16((unsigned short)lo);
    split1(k1 * c - k2 * s, h, lo);
    khi[base] = __ushort_as_bfloat16((unsigned short)h);
    klo[base] = __ushort_as_bfloat16((unsigned short)lo);
    split1(k2 * c + k1 * s, h, lo);
    khi[base + 32] = __ushort_as_bfloat16((unsigned short)h);
    klo[base + 32] = __ushort_as_bfloat16((unsigned short)lo);
}

// ---------------------------------------------------------------------------
// HMMA flash attention (unchanged from R5).
// ---------------------------------------------------------------------------
#define AT_QHI 0
#define AT_QLO 16384
#define AT_STG 32768
#define AT_MASK (AT_STG + 2*32768)
#define ATTN_DYN (AT_MASK + 4096)

__global__ __launch_bounds__(256, 2) void attn_hmma(
    const __nv_bfloat16* __restrict__ qhi, const __nv_bfloat16* __restrict__ qlo,
    const __nv_bfloat16* __restrict__ khi, const __nv_bfloat16* __restrict__ klo,
    const __nv_bfloat16* __restrict__ vhi, const __nv_bfloat16* __restrict__ vlo,
    const float* __restrict__ mask,
    __nv_bfloat16* __restrict__ chi, __nv_bfloat16* __restrict__ clo)
{
    extern __shared__ char smraw[];
    const uint32_t sb = smem_to_u32(smraw);
    const int tid = threadIdx.x, lane = tid & 31, w = tid >> 5;
    const int qt = blockIdx.x, bh = blockIdx.y;
    const int b = bh >> 4, h = bh & 15;

    CP16(sb + AT_MASK + tid * 16, mask + b * 1024 + tid * 4);
    #pragma unroll
    for (int it = 0; it < 4; it++) {
        int idx = tid + it * 256, r = idx >> 3, seg = idx & 7;
        size_t g = ((size_t)bh * 1024 + qt * 128 + r) * 64 + seg * 8;
        uint32_t d = sb + (uint32_t)r * 128 + (uint32_t)((seg ^ (r & 7)) << 4);
        CP16(d + AT_QHI, qhi + g);
        CP16(d + AT_QLO, qlo + g);
    }
    CP_COMMIT();

    #define LOADKV(s, kt_) do { \
        _Pragma("unroll") \
        for (int it = 0; it < 2; it++) { \
            int idx = tid + it * 256, r = idx >> 3, sg = idx & 7; \
            size_t g = ((size_t)bh * 1024 + (kt_) * 64 + r) * 64 + sg * 8; \
            uint32_t d = sb + AT_STG + (uint32_t)(s) * 32768 \
                       + (uint32_t)r * 128 + (uint32_t)((sg ^ (r & 7)) << 4); \
            CP16(d,         khi + g); \
            CP16(d + 8192,  klo + g); \
            CP16(d + 16384, vhi + g); \
            CP16(d + 24576, vlo + g); \
        } \
        CP_COMMIT(); \
    } while (0)

    LOADKV(0, 0);

    float o[8][4];
    #pragma unroll
    for (int j = 0; j < 8; j++)
        #pragma unroll
        for (int e = 0; e < 4; e++) o[j][e] = 0.f;
    float m0 = -INFINITY, m1 = -INFINITY, l0 = 0.f, l1 = 0.f;

    const int rA = w * 16 + (lane & 15);
    const int rBb = ((lane >> 4) << 3) + (lane & 7);
    const int c2 = (lane & 3) * 2;

    for (int kt = 0; kt < 16; kt++) {
        asm volatile("cp.async.wait_group 0;" ::: "memory");
        __syncthreads();
        if (kt < 15) LOADKV((kt + 1) & 1, kt + 1);
        const uint32_t kb = sb + AT_STG + (uint32_t)(kt & 1) * 32768;

        float s[8][4];
        #pragma unroll
        for (int j = 0; j < 8; j++)
            #pragma unroll
            for (int e = 0; e < 4; e++) s[j][e] = 0.f;

        #pragma unroll
        for (int ks = 0; ks < 4; ks++) {
            uint32_t ah[4], al[4];
            uint32_t aaddr = sb + AT_QHI + (uint32_t)rA * 128
                           + (uint32_t)(((ks * 2 + (lane >> 4)) ^ (rA & 7)) << 4);
            LDSM4(ah, aaddr);
            LDSM4(al, aaddr + (AT_QLO - AT_QHI));
            #pragma unroll
            for (int np = 0; np < 4; np++) {
                int rB = np * 16 + rBb;
                uint32_t baddr = kb + (uint32_t)rB * 128
                               + (uint32_t)(((ks * 2 + ((lane >> 3) & 1)) ^ (rB & 7)) << 4);
                uint32_t bhF[4], blF[4];
                LDSM4(bhF, baddr);
                LDSM4(blF, baddr + 8192);
                #pragma unroll
                for (int hf = 0; hf < 2; hf++) {
                    int nt = np * 2 + hf, rb = hf * 2;
                    MMA16816(s[nt], ah, bhF[rb], bhF[rb + 1]);
                    MMA16816(s[nt], ah, blF[rb], blF[rb + 1]);
                    MMA16816(s[nt], al, bhF[rb], bhF[rb + 1]);
                }
            }
        }

        float mx0 = -INFINITY, mx1 = -INFINITY;
        #pragma unroll
        for (int j = 0; j < 8; j++) {
            float2 mk = *(float2*)(smraw + AT_MASK + (size_t)(kt * 64 + j * 8 + c2) * 4);
            s[j][0] = s[j][0] * 0.125f + mk.x;
            s[j][1] = s[j][1] * 0.125f + mk.y;
            s[j][2] = s[j][2] * 0.125f + mk.x;
            s[j][3] = s[j][3] * 0.125f + mk.y;
            mx0 = fmaxf(mx0, fmaxf(s[j][0], s[j][1]));
            mx1 = fmaxf(mx1, fmaxf(s[j][2], s[j][3]));
        }
        #pragma unroll
        for (int off = 1; off < 4; off <<= 1) {
            mx0 = fmaxf(mx0, __shfl_xor_sync(0xffffffffu, mx0, off));
            mx1 = fmaxf(mx1, __shfl_xor_sync(0xffffffffu, mx1, off));
        }
        float mn0 = fmaxf(m0, mx0), mn1 = fmaxf(m1, mx1);
        float corr0 = __expf(m0 - mn0), corr1 = __expf(m1 - mn1);
        m0 = mn0; m1 = mn1;
        float sum0 = 0.f, sum1 = 0.f;
        #pragma unroll
        for (int j = 0; j < 8; j++) {
            s[j][0] = __expf(s[j][0] - m0);
            s[j][1] = __expf(s[j][1] - m0);
            s[j][2] = __expf(s[j][2] - m1);
            s[j][3] = __expf(s[j][3] - m1);
            sum0 += s[j][0] + s[j][1];
            sum1 += s[j][2] + s[j][3];
        }
        #pragma unroll
        for (int off = 1; off < 4; off <<= 1) {
            sum0 += __shfl_xor_sync(0xffffffffu, sum0, off);
            sum1 += __shfl_xor_sync(0xffffffffu, sum1, off);
        }
        l0 = l0 * corr0 + sum0;
        l1 = l1 * corr1 + sum1;
        #pragma unroll
        for (int j = 0; j < 8; j++) {
            o[j][0] *= corr0; o[j][1] *= corr0;
            o[j][2] *= corr1; o[j][3] *= corr1;
        }

        #pragma unroll
        for (int kg = 0; kg < 4; kg++) {
            uint32_t ph[4], pl[4];
            split2(s[2*kg][0],   s[2*kg][1],   ph[0], pl[0]);
            split2(s[2*kg][2],   s[2*kg][3],   ph[1], pl[1]);
            split2(s[2*kg+1][0], s[2*kg+1][1], ph[2], pl[2]);
            split2(s[2*kg+1][2], s[2*kg+1][3], ph[3], pl[3]);
            int rV = kg * 16 + (lane & 15);
            #pragma unroll
            for (int np = 0; np < 4; np++) {
                uint32_t vaddr = kb + 16384 + (uint32_t)rV * 128
                               + (uint32_t)(((np * 2 + (lane >> 4)) ^ (rV & 7)) << 4);
                uint32_t vhF[4], vlF[4];
                LDSM4T(vhF, vaddr);
                LDSM4T(vlF, vaddr + 8192);
                #pragma unroll
                for (int hf = 0; hf < 2; hf++) {
                    int nt = np * 2 + hf, rb = hf * 2;
                    MMA16816(o[nt], ph, vhF[rb], vhF[rb + 1]);
                    MMA16816(o[nt], pl, vhF[rb], vhF[rb + 1]);
                    MMA16816(o[nt], ph, vlF[rb], vlF[rb + 1]);
                }
            }
        }
    }

    float i0 = 1.0f / l0, i1 = 1.0f / l1;
    size_t row0 = (size_t)b * 1024 + qt * 128 + w * 16 + (lane >> 2);
    #pragma unroll
    for (int j = 0; j < 8; j++) {
        int col = h * 64 + j * 8 + c2;
        uint32_t hph, lph;
        split2(o[j][0] * i0, o[j][1] * i0, hph, lph);
        *(uint32_t*)(chi + row0 * D_ + col) = hph;
        *(uint32_t*)(clo + row0 * D_ + col) = lph;
        split2(o[j][2] * i1, o[j][3] * i1, hph, lph);
        *(uint32_t*)(chi + (row0 + 8) * D_ + col) = hph;
        *(uint32_t*)(clo + (row0 + 8) * D_ + col) = lph;
    }
    #undef LOADKV
}

// ---------------------------------------------------------------------------
// LayerNorm over last dim (1024).
// ---------------------------------------------------------------------------
__global__ __launch_bounds__(256) void lnorm(
    const float* __restrict__ X, const float* __restrict__ hsc,
    const float* __restrict__ hbi, float* __restrict__ out)
{
    int row = blockIdx.x;
    int c4 = threadIdx.x * 4;
    const float* x = X + (size_t)row * D_;
    float4 v = *(const float4*)(x + c4);
    float sum = v.x + v.y + v.z + v.w;
    float sq  = v.x*v.x + v.y*v.y + v.z*v.z + v.w*v.w;
    #pragma unroll
    for (int off = 16; off > 0; off >>= 1) {
        sum += __shfl_xor_sync(0xffffffffu, sum, off);
        sq  += __shfl_xor_sync(0xffffffffu, sq,  off);
    }
    __shared__ float rs[8], rq[8];
    int warp = threadIdx.x >> 5;
    if ((threadIdx.x & 31) == 0) { rs[warp] = sum; rq[warp] = sq; }
    __syncthreads();
    float tot = 0.f, totq = 0.f;
    #pragma unroll
    for (int wv = 0; wv < 8; wv++) { tot += rs[wv]; totq += rq[wv]; }
    float mu  = tot  * (1.0f / 1024.0f);
    float var = totq * (1.0f / 1024.0f) - mu * mu;
    float inv = rsqrtf(var + 1e-12f);
    float4 sc = *(const float4*)(hsc + c4);
    float4 bi = *(const float4*)(hbi + c4);
    float4 oo;
    oo.x = (v.x - mu) * inv * sc.x + bi.x;
    oo.y = (v.y - mu) * inv * sc.y + bi.y;
    oo.z = (v.z - mu) * inv * sc.z + bi.z;
    oo.w = (v.w - mu) * inv * sc.w + bi.w;
    *(float4*)&out[(size_t)row * D_ + c4] = oo;
}

// ---------------------------------------------------------------------------
extern "C" void kernel_launch(void* const* d_in, const int* in_sizes, int n_in,
                              void* d_out, int out_size)
{
    const float* hidden = (const float*)d_in[0];
    const float* mask   = (const float*)d_in[1];
    const float* phi    = (const float*)d_in[2];
    const float* mag    = (const float*)d_in[3];
    const float* Wq     = (const float*)d_in[4];
    const float* bq     = (const float*)d_in[5];
    const float* Wk     = (const float*)d_in[6];
    const float* bk     = (const float*)d_in[7];
    const float* Wv     = (const float*)d_in[8];
    const float* bv     = (const float*)d_in[9];
    const float* gamma  = (const float*)d_in[10];
    const float* Wo     = (const float*)d_in[11];
    const float* bo     = (const float*)d_in[12];
    const float* lns    = (const float*)d_in[13];
    const float* lnb    = (const float*)d_in[14];
    float* out = (float*)d_out;

    float *q, *k, *x;
    __nv_bfloat16 *ahi, *alo, *wthi, *wtlo, *qhi, *qlo, *khi, *klo, *vhi, *vlo;
    cudaGetSymbolAddress((void**)&q,    g_q);
    cudaGetSymbolAddress((void**)&k,    g_k);
    cudaGetSymbolAddress((void**)&x,    g_x);
    cudaGetSymbolAddress((void**)&ahi,  g_ahi);
    cudaGetSymbolAddress((void**)&alo,  g_alo);
    cudaGetSymbolAddress((void**)&wthi, g_wthi);
    cudaGetSymbolAddress((void**)&wtlo, g_wtlo);
    cudaGetSymbolAddress((void**)&qhi,  g_qhi);
    cudaGetSymbolAddress((void**)&qlo,  g_qlo);
    cudaGetSymbolAddress((void**)&khi,  g_khi);
    cudaGetSymbolAddress((void**)&klo,  g_klo);
    cudaGetSymbolAddress((void**)&vhi,  g_vhi);
    cudaGetSymbolAddress((void**)&vlo,  g_vlo);

    cudaFuncSetAttribute(gemm_hmma, cudaFuncAttributeMaxDynamicSharedMemorySize, GEMM_DYN);
    cudaFuncSetAttribute(attn_hmma, cudaFuncAttributeMaxDynamicSharedMemorySize, ATTN_DYN);

    const int DD = D_ * D_;

    convA<<<(M_TOT * D_ / 4 + 255) / 256, 256>>>((const float4*)hidden, (uint2*)ahi, (uint2*)alo, M_TOT * D_ / 4);
    convW4<<<dim3(32, 32, 4), 256>>>(Wq, Wk, Wv, Wo, wthi, wtlo);

    // QKV fused (z: 0=Q fp32, 1=K fp32, 2=V bf16 hi/lo), head-major outputs
    gemm_hmma<<<dim3(D_ / GN, M_TOT / GM, 3), 256, GEMM_DYN>>>(
        ahi, alo, wthi, wtlo, bq, bk, bv, q, k, vhi, vlo, nullptr, nullptr);

    rotscale<<<(B_ * L_ * H_ * 32) / 256, 256>>>(q, k, phi, mag, gamma,
                                                 qhi, qlo, khi, klo);

    attn_hmma<<<dim3(L_ / 128, B_ * H_), 256, ATTN_DYN>>>(
        qhi, qlo, khi, klo, vhi, vlo, mask, ahi, alo);

    // Wo projection + residual
    gemm_hmma<<<dim3(D_ / GN, M_TOT / GM, 1), 256, GEMM_DYN>>>(
        ahi, alo, wthi + 3*DD, wtlo + 3*DD, bo, bo, bo,
        nullptr, nullptr, nullptr, nullptr, hidden, x);

    lnorm<<<M_TOT, 256>>>(x, lns, lnb, out);
}

// round 7
// speedup vs baseline: 2.7748x; 1.0283x over previous
#include <cuda_runtime.h>
#include <cuda_bf16.h>
#include <math.h>
#include <stdint.h>

#define B_  4
#define L_  1024
#define D_  1024
#define H_  16
#define HD_ 64
#define M_TOT (B_*L_)   // 4096

typedef unsigned long long ull;

// ---------------------------------------------------------------------------
// Scratch
// ---------------------------------------------------------------------------
__device__ float g_x[M_TOT * D_];
__device__ float4 g_prep[B_ * H_ * L_];          // (sc, sin, cos, 0) per (bh,l)
__device__ __nv_bfloat16 g_ahi[M_TOT * D_];      // activations / ctx hi
__device__ __nv_bfloat16 g_alo[M_TOT * D_];
__device__ __nv_bfloat16 g_wthi[4 * D_ * D_];    // W^T [N][K] hi (q,k,v,o)
__device__ __nv_bfloat16 g_wtlo[4 * D_ * D_];
__device__ __nv_bfloat16 g_qhi[M_TOT * D_];      // rotated Q/K bf16, head-major
__device__ __nv_bfloat16 g_qlo[M_TOT * D_];
__device__ __nv_bfloat16 g_khi[M_TOT * D_];
__device__ __nv_bfloat16 g_klo[M_TOT * D_];
__device__ __nv_bfloat16 g_vhi[M_TOT * D_];      // V bf16, head-major
__device__ __nv_bfloat16 g_vlo[M_TOT * D_];

// ---------------------------------------------------------------------------
// Helpers
// ---------------------------------------------------------------------------
__device__ __forceinline__ uint32_t smem_to_u32(const void* p) {
    uint32_t a;
    asm("{ .reg .u64 t; cvta.to.shared.u64 t, %1; cvt.u32.u64 %0, t; }"
        : "=r"(a) : "l"(p));
    return a;
}

#define CP16(dst, src) \
    asm volatile("cp.async.cg.shared.global [%0], [%1], 16;" \
                 :: "r"(dst), "l"(src) : "memory")
#define CP_COMMIT() asm volatile("cp.async.commit_group;" ::: "memory")

#define LDSM4(r, addr) \
    asm volatile("ldmatrix.sync.aligned.m8n8.x4.shared.b16 {%0,%1,%2,%3}, [%4];" \
                 : "=r"((r)[0]), "=r"((r)[1]), "=r"((r)[2]), "=r"((r)[3]) : "r"(addr))
#define LDSM4T(r, addr) \
    asm volatile("ldmatrix.sync.aligned.m8n8.x4.trans.shared.b16 {%0,%1,%2,%3}, [%4];" \
                 : "=r"((r)[0]), "=r"((r)[1]), "=r"((r)[2]), "=r"((r)[3]) : "r"(addr))

#define MMA16816(c, a, b0, b1) \
    asm volatile("mma.sync.aligned.m16n8k16.row.col.f32.bf16.bf16.f32 " \
                 "{%0,%1,%2,%3}, {%4,%5,%6,%7}, {%8,%9}, {%0,%1,%2,%3};" \
                 : "+f"((c)[0]), "+f"((c)[1]), "+f"((c)[2]), "+f"((c)[3]) \
                 : "r"((a)[0]), "r"((a)[1]), "r"((a)[2]), "r"((a)[3]), \
                   "r"(b0), "r"(b1))

// scalar fp32 -> bf16 hi/lo split (round-nearest)
__device__ __forceinline__ void split1(float x, uint32_t& h, uint32_t& l) {
    __nv_bfloat16 hb = __float2bfloat16(x);
    float hf = __bfloat162float(hb);
    __nv_bfloat16 lb = __float2bfloat16(x - hf);
    h = (uint32_t)__bfloat16_as_ushort(hb);
    l = (uint32_t)__bfloat16_as_ushort(lb);
}
// fast packed split: two floats -> bf16x2 hi + bf16x2 lo (x in low half)
__device__ __forceinline__ void split2(float x, float y, uint32_t& h, uint32_t& l) {
    uint32_t hp;
    asm("cvt.rn.bf16x2.f32 %0, %1, %2;" : "=r"(hp) : "f"(y), "f"(x));
    float xr = __uint_as_float(hp << 16);
    float yr = __uint_as_float(hp & 0xffff0000u);
    uint32_t lp;
    asm("cvt.rn.bf16x2.f32 %0, %1, %2;" : "=r"(lp) : "f"(y - yr), "f"(x - xr));
    h = hp; l = lp;
}

// ---------------------------------------------------------------------------
// prep: per (bh, l) compute (scale, sin(phi), cos(phi))
// ---------------------------------------------------------------------------
__global__ __launch_bounds__(256) void prep(
    const float* __restrict__ phi, const float* __restrict__ mag,
    const float* __restrict__ gamma, float4* __restrict__ out)
{
    int i = blockIdx.x * 256 + threadIdx.x;      // < 65536
    int h = (i >> 10) & 15;
    float sc = 1.0f + gamma[h] * tanhf(mag[i]);
    float s, c;
    sincosf(phi[i], &s, &c);
    out[i] = make_float4(sc, s, c, 0.f);
}

// ---------------------------------------------------------------------------
// convA: fp32 -> bf16 hi/lo
// ---------------------------------------------------------------------------
__global__ __launch_bounds__(256) void convA(
    const float4* __restrict__ x, uint2* __restrict__ hi, uint2* __restrict__ lo, int n4)
{
    int i = blockIdx.x * 256 + threadIdx.x;
    if (i >= n4) return;
    float4 v = x[i];
    uint2 ho, lv;
    split2(v.x, v.y, ho.x, lv.x);
    split2(v.z, v.w, ho.y, lv.y);
    hi[i] = ho; lo[i] = lv;
}

// W[K,N] fp32 -> WT[N,K] bf16 hi/lo; grid.z selects matrix.
__global__ __launch_bounds__(256) void convW4(
    const float* __restrict__ Wq, const float* __restrict__ Wk,
    const float* __restrict__ Wv, const float* __restrict__ Wo,
    __nv_bfloat16* __restrict__ hi, __nv_bfloat16* __restrict__ lo)
{
    __shared__ float t[32][33];
    const int z = blockIdx.z;
    const float* W = (z == 0) ? Wq : (z == 1) ? Wk : (z == 2) ? Wv : Wo;
    __nv_bfloat16* hz = hi + (size_t)z * D_ * D_;
    __nv_bfloat16* lz = lo + (size_t)z * D_ * D_;
    int n0 = blockIdx.x * 32, k0 = blockIdx.y * 32;
    int tx = threadIdx.x & 31, ty = threadIdx.x >> 5;
    #pragma unroll
    for (int j = 0; j < 4; j++)
        t[ty + j*8][tx] = W[(size_t)(k0 + ty + j*8) * D_ + n0 + tx];
    __syncthreads();
    #pragma unroll
    for (int j = 0; j < 4; j++) {
        float v = t[tx][ty + j*8];
        uint32_t h, l;
        split1(v, h, l);
        size_t o = (size_t)(n0 + ty + j*8) * D_ + k0 + tx;
        hz[o] = __ushort_as_bfloat16((unsigned short)h);
        lz[o] = __ushort_as_bfloat16((unsigned short)l);
    }
}

// ---------------------------------------------------------------------------
// HMMA bf16 3-term GEMM, 128x256 CTA tile, 256 threads = 8 warps (64x64 tiles).
// Modes:
//  res == nullptr, z=0/1: Q/K -> bias + scale + rotate -> bf16 hi/lo head-major
//  res == nullptr, z=2:   V  -> bias -> bf16 hi/lo head-major
//  res != nullptr:        Wo -> bias + residual -> fp32 row-major
// ---------------------------------------------------------------------------
#define GM 128
#define GN 256
#define KC 64
#define OFF_ALO  16384
#define OFF_BHI  32768
#define OFF_BLO  65536
#define STAGE    98304
#define GEMM_DYN (2*STAGE)

__global__ __launch_bounds__(256, 1) void gemm_hmma(
    const __nv_bfloat16* __restrict__ Ahi, const __nv_bfloat16* __restrict__ Alo,
    const __nv_bfloat16* __restrict__ WThi, const __nv_bfloat16* __restrict__ WTlo,
    const float* __restrict__ bias0, const float* __restrict__ bias1,
    const float* __restrict__ bias2,
    const float4* __restrict__ prp,
    __nv_bfloat16* __restrict__ qh, __nv_bfloat16* __restrict__ ql,
    __nv_bfloat16* __restrict__ kh, __nv_bfloat16* __restrict__ kl,
    __nv_bfloat16* __restrict__ vh, __nv_bfloat16* __restrict__ vl,
    const float* __restrict__ res, float* __restrict__ xout)
{
    extern __shared__ char smraw[];
    const uint32_t sbase = smem_to_u32(smraw);
    const int tid  = threadIdx.x;
    const int lane = tid & 31, wid = tid >> 5;
    const int wm = wid >> 2, wn = wid & 3;
    const int bm = blockIdx.y * GM, bn = blockIdx.x * GN;
    const int z  = blockIdx.z;

    const __nv_bfloat16* Bh = WThi + (size_t)z * D_ * D_;
    const __nv_bfloat16* Bl = WTlo + (size_t)z * D_ * D_;
    const float* bias = (z == 0) ? bias0 : (z == 1) ? bias1 : bias2;

    const int rr  = tid >> 3;
    const int seg = tid & 7;

    #define LOAD_STAGE(s, kc) do { \
        uint32_t sb_ = sbase + (uint32_t)(s) * STAGE; \
        _Pragma("unroll") \
        for (int h4 = 0; h4 < 4; h4++) { \
            int r_ = rr + h4 * 32; \
            uint32_t sw_ = (uint32_t)r_ * 128 + (uint32_t)((seg ^ (r_ & 7)) << 4); \
            size_t g_ = (size_t)(bm + r_) * D_ + (kc) + seg * 8; \
            CP16(sb_ + sw_,           Ahi + g_); \
            CP16(sb_ + OFF_ALO + sw_, Alo + g_); \
        } \
        _Pragma("unroll") \
        for (int h8 = 0; h8 < 8; h8++) { \
            int r_ = rr + h8 * 32; \
            uint32_t sw_ = (uint32_t)r_ * 128 + (uint32_t)((seg ^ (r_ & 7)) << 4); \
            size_t g_ = (size_t)(bn + r_) * D_ + (kc) + seg * 8; \
            CP16(sb_ + OFF_BHI + sw_, Bh + g_); \
            CP16(sb_ + OFF_BLO + sw_, Bl + g_); \
        } \
        CP_COMMIT(); \
    } while (0)

    float c[4][8][4];
    #pragma unroll
    for (int mi = 0; mi < 4; mi++)
        #pragma unroll
        for (int ni = 0; ni < 8; ni++)
            #pragma unroll
            for (int e = 0; e < 4; e++) c[mi][ni][e] = 0.f;

    LOAD_STAGE(0, 0);

    const int rAb = wm * 64 + (lane & 15);
    const int rBb = wn * 64 + ((lane >> 4) << 3) + (lane & 7);
    const int sgA = lane >> 4;
    const int sgB = (lane >> 3) & 1;

    for (int ch = 0; ch < 16; ch++) {
        if (ch < 15) {
            LOAD_STAGE((ch + 1) & 1, (ch + 1) * KC);
            asm volatile("cp.async.wait_group 1;" ::: "memory");
        } else {
            asm volatile("cp.async.wait_group 0;" ::: "memory");
        }
        __syncthreads();

        const uint32_t sb = sbase + (uint32_t)(ch & 1) * STAGE;
        #pragma unroll
        for (int ks = 0; ks < 4; ks++) {
            uint32_t ah[4][4], al[4][4];
            #pragma unroll
            for (int mi = 0; mi < 4; mi++) {
                int rA = rAb + mi * 16;
                uint32_t addr = sb + (uint32_t)rA * 128
                              + (uint32_t)(((ks * 2 + sgA) ^ (rA & 7)) << 4);
                LDSM4(ah[mi], addr);
                LDSM4(al[mi], addr + OFF_ALO);
            }
            #pragma unroll
            for (int np = 0; np < 4; np++) {
                int rB = rBb + np * 16;
                uint32_t addr = sb + OFF_BHI + (uint32_t)rB * 128
                              + (uint32_t)(((ks * 2 + sgB) ^ (rB & 7)) << 4);
                uint32_t bh[4], bl[4];
                LDSM4(bh, addr);
                LDSM4(bl, addr + (OFF_BLO - OFF_BHI));
                #pragma unroll
                for (int hf = 0; hf < 2; hf++) {
                    int ni = np * 2 + hf, rb = hf * 2;
                    #pragma unroll
                    for (int mi = 0; mi < 4; mi++) {
                        MMA16816(c[mi][ni], ah[mi], bh[rb], bh[rb + 1]);
                        MMA16816(c[mi][ni], ah[mi], bl[rb], bl[rb + 1]);
                        MMA16816(c[mi][ni], al[mi], bh[rb], bh[rb + 1]);
                    }
                }
            }
        }
        __syncthreads();
    }

    // ---- epilogue ----
    const int g = lane >> 2, tig = lane & 3;
    if (res) {
        // Wo projection + bias + residual -> fp32 row-major
        #pragma unroll
        for (int mi = 0; mi < 4; mi++) {
            int row0 = bm + wm * 64 + mi * 16 + g;
            #pragma unroll
            for (int ni = 0; ni < 8; ni++) {
                int col = bn + wn * 64 + ni * 8 + tig * 2;
                float2 bv = *(const float2*)(bias + col);
                float2 r0 = *(const float2*)(res + (size_t)row0 * D_ + col);
                float2 r1 = *(const float2*)(res + (size_t)(row0 + 8) * D_ + col);
                *(float2*)(xout + (size_t)row0 * D_ + col) =
                    make_float2(c[mi][ni][0] + bv.x + r0.x, c[mi][ni][1] + bv.y + r0.y);
                *(float2*)(xout + (size_t)(row0 + 8) * D_ + col) =
                    make_float2(c[mi][ni][2] + bv.x + r1.x, c[mi][ni][3] + bv.y + r1.y);
            }
        }
    } else if (z == 2) {
        // V: bias -> bf16 hi/lo head-major
        #pragma unroll
        for (int mi = 0; mi < 4; mi++) {
            int row0 = bm + wm * 64 + mi * 16 + g;
            int bidx = row0 >> 10, l0 = row0 & 1023;
            #pragma unroll
            for (int ni = 0; ni < 8; ni++) {
                int col = bn + wn * 64 + ni * 8 + tig * 2;
                float2 bv = *(const float2*)(bias + col);
                size_t o0 = (((size_t)bidx * 16 + (col >> 6)) * 1024 + l0) * 64 + (col & 63);
                size_t o1 = o0 + 8 * 64;
                uint32_t h, l;
                split2(c[mi][ni][0] + bv.x, c[mi][ni][1] + bv.y, h, l);
                *(uint32_t*)(vh + o0) = h; *(uint32_t*)(vl + o0) = l;
                split2(c[mi][ni][2] + bv.x, c[mi][ni][3] + bv.y, h, l);
                *(uint32_t*)(vh + o1) = h; *(uint32_t*)(vl + o1) = l;
            }
        }
    } else {
        // Q/K: bias + scale + rotate -> bf16 hi/lo head-major
        __nv_bfloat16* oh = (z == 0) ? qh : kh;
        __nv_bfloat16* ol = (z == 0) ? ql : kl;
        const int hh = (bn + wn * 64) >> 6;     // head for this warp (64-col span)
        #pragma unroll
        for (int mi = 0; mi < 4; mi++) {
            int row0 = bm + wm * 64 + mi * 16 + g;
            int bidx = row0 >> 10, l0 = row0 & 1023;
            int pidx = (bidx * 16 + hh) * 1024 + l0;
            float4 p0 = prp[pidx];
            float4 p1 = prp[pidx + 8];
            size_t ob = ((size_t)(bidx * 16 + hh) * 1024 + l0) * 64;
            #pragma unroll
            for (int ni = 0; ni < 4; ni++) {
                int d = ni * 8 + tig * 2;
                float2 b1 = *(const float2*)(bias + bn + wn * 64 + d);
                float2 b2 = *(const float2*)(bias + bn + wn * 64 + d + 32);
                uint32_t hA, lA, hB, lB;
                // row0
                {
                    float x0 = (c[mi][ni][0]   + b1.x) * p0.x;
                    float x1 = (c[mi][ni][1]   + b1.y) * p0.x;
                    float y0 = (c[mi][ni+4][0] + b2.x) * p0.x;
                    float y1 = (c[mi][ni+4][1] + b2.y) * p0.x;
                    split2(x0 * p0.z - y0 * p0.y, x1 * p0.z - y1 * p0.y, hA, lA);
                    split2(y0 * p0.z + x0 * p0.y, y1 * p0.z + x1 * p0.y, hB, lB);
                    *(uint32_t*)(oh + ob + d)      = hA; *(uint32_t*)(ol + ob + d)      = lA;
                    *(uint32_t*)(oh + ob + d + 32) = hB; *(uint32_t*)(ol + ob + d + 32) = lB;
                }
                // row0 + 8
                {
                    float x0 = (c[mi][ni][2]   + b1.x) * p1.x;
                    float x1 = (c[mi][ni][3]   + b1.y) * p1.x;
                    float y0 = (c[mi][ni+4][2] + b2.x) * p1.x;
                    float y1 = (c[mi][ni+4][3] + b2.y) * p1.x;
                    split2(x0 * p1.z - y0 * p1.y, x1 * p1.z - y1 * p1.y, hA, lA);
                    split2(y0 * p1.z + x0 * p1.y, y1 * p1.z + x1 * p1.y, hB, lB);
                    *(uint32_t*)(oh + ob + 512 + d)      = hA; *(uint32_t*)(ol + ob + 512 + d)      = lA;
                    *(uint32_t*)(oh + ob + 512 + d + 32) = hB; *(uint32_t*)(ol + ob + 512 + d + 32) = lB;
                }
            }
        }
    }
    #undef LOAD_STAGE
}

// ---------------------------------------------------------------------------
// HMMA flash attention (mainloop unchanged from R5/R6; fast split2).
// ---------------------------------------------------------------------------
#define AT_QHI 0
#define AT_QLO 16384
#define AT_STG 32768
#define AT_MASK (AT_STG + 2*32768)
#define ATTN_DYN (AT_MASK + 4096)

__global__ __launch_bounds__(256, 2) void attn_hmma(
    const __nv_bfloat16* __restrict__ qhi, const __nv_bfloat16* __restrict__ qlo,
    const __nv_bfloat16* __restrict__ khi, const __nv_bfloat16* __restrict__ klo,
    const __nv_bfloat16* __restrict__ vhi, const __nv_bfloat16* __restrict__ vlo,
    const float* __restrict__ mask,
    __nv_bfloat16* __restrict__ chi, __nv_bfloat16* __restrict__ clo)
{
    extern __shared__ char smraw[];
    const uint32_t sb = smem_to_u32(smraw);
    const int tid = threadIdx.x, lane = tid & 31, w = tid >> 5;
    const int qt = blockIdx.x, bh = blockIdx.y;
    const int b = bh >> 4, h = bh & 15;

    CP16(sb + AT_MASK + tid * 16, mask + b * 1024 + tid * 4);
    #pragma unroll
    for (int it = 0; it < 4; it++) {
        int idx = tid + it * 256, r = idx >> 3, seg = idx & 7;
        size_t g = ((size_t)bh * 1024 + qt * 128 + r) * 64 + seg * 8;
        uint32_t d = sb + (uint32_t)r * 128 + (uint32_t)((seg ^ (r & 7)) << 4);
        CP16(d + AT_QHI, qhi + g);
        CP16(d + AT_QLO, qlo + g);
    }
    CP_COMMIT();

    #define LOADKV(s, kt_) do { \
        _Pragma("unroll") \
        for (int it = 0; it < 2; it++) { \
            int idx = tid + it * 256, r = idx >> 3, sg = idx & 7; \
            size_t g = ((size_t)bh * 1024 + (kt_) * 64 + r) * 64 + sg * 8; \
            uint32_t d = sb + AT_STG + (uint32_t)(s) * 32768 \
                       + (uint32_t)r * 128 + (uint32_t)((sg ^ (r & 7)) << 4); \
            CP16(d,         khi + g); \
            CP16(d + 8192,  klo + g); \
            CP16(d + 16384, vhi + g); \
            CP16(d + 24576, vlo + g); \
        } \
        CP_COMMIT(); \
    } while (0)

    LOADKV(0, 0);

    float o[8][4];
    #pragma unroll
    for (int j = 0; j < 8; j++)
        #pragma unroll
        for (int e = 0; e < 4; e++) o[j][e] = 0.f;
    float m0 = -INFINITY, m1 = -INFINITY, l0 = 0.f, l1 = 0.f;

    const int rA = w * 16 + (lane & 15);
    const int rBb = ((lane >> 4) << 3) + (lane & 7);
    const int c2 = (lane & 3) * 2;

    for (int kt = 0; kt < 16; kt++) {
        asm volatile("cp.async.wait_group 0;" ::: "memory");
        __syncthreads();
        if (kt < 15) LOADKV((kt + 1) & 1, kt + 1);
        const uint32_t kb = sb + AT_STG + (uint32_t)(kt & 1) * 32768;

        float s[8][4];
        #pragma unroll
        for (int j = 0; j < 8; j++)
            #pragma unroll
            for (int e = 0; e < 4; e++) s[j][e] = 0.f;

        #pragma unroll
        for (int ks = 0; ks < 4; ks++) {
            uint32_t ah[4], al[4];
            uint32_t aaddr = sb + AT_QHI + (uint32_t)rA * 128
                           + (uint32_t)(((ks * 2 + (lane >> 4)) ^ (rA & 7)) << 4);
            LDSM4(ah, aaddr);
            LDSM4(al, aaddr + (AT_QLO - AT_QHI));
            #pragma unroll
            for (int np = 0; np < 4; np++) {
                int rB = np * 16 + rBb;
                uint32_t baddr = kb + (uint32_t)rB * 128
                               + (uint32_t)(((ks * 2 + ((lane >> 3) & 1)) ^ (rB & 7)) << 4);
                uint32_t bhF[4], blF[4];
                LDSM4(bhF, baddr);
                LDSM4(blF, baddr + 8192);
                #pragma unroll
                for (int hf = 0; hf < 2; hf++) {
                    int nt = np * 2 + hf, rb = hf * 2;
                    MMA16816(s[nt], ah, bhF[rb], bhF[rb + 1]);
                    MMA16816(s[nt], ah, blF[rb], blF[rb + 1]);
                    MMA16816(s[nt], al, bhF[rb], bhF[rb + 1]);
                }
            }
        }

        float mx0 = -INFINITY, mx1 = -INFINITY;
        #pragma unroll
        for (int j = 0; j < 8; j++) {
            float2 mk = *(float2*)(smraw + AT_MASK + (size_t)(kt * 64 + j * 8 + c2) * 4);
            s[j][0] = s[j][0] * 0.125f + mk.x;
            s[j][1] = s[j][1] * 0.125f + mk.y;
            s[j][2] = s[j][2] * 0.125f + mk.x;
            s[j][3] = s[j][3] * 0.125f + mk.y;
            mx0 = fmaxf(mx0, fmaxf(s[j][0], s[j][1]));
            mx1 = fmaxf(mx1, fmaxf(s[j][2], s[j][3]));
        }
        #pragma unroll
        for (int off = 1; off < 4; off <<= 1) {
            mx0 = fmaxf(mx0, __shfl_xor_sync(0xffffffffu, mx0, off));
            mx1 = fmaxf(mx1, __shfl_xor_sync(0xffffffffu, mx1, off));
        }
        float mn0 = fmaxf(m0, mx0), mn1 = fmaxf(m1, mx1);
        float corr0 = __expf(m0 - mn0), corr1 = __expf(m1 - mn1);
        m0 = mn0; m1 = mn1;
        float sum0 = 0.f, sum1 = 0.f;
        #pragma unroll
        for (int j = 0; j < 8; j++) {
            s[j][0] = __expf(s[j][0] - m0);
            s[j][1] = __expf(s[j][1] - m0);
            s[j][2] = __expf(s[j][2] - m1);
            s[j][3] = __expf(s[j][3] - m1);
            sum0 += s[j][0] + s[j][1];
            sum1 += s[j][2] + s[j][3];
        }
        #pragma unroll
        for (int off = 1; off < 4; off <<= 1) {
            sum0 += __shfl_xor_sync(0xffffffffu, sum0, off);
            sum1 += __shfl_xor_sync(0xffffffffu, sum1, off);
        }
        l0 = l0 * corr0 + sum0;
        l1 = l1 * corr1 + sum1;
        #pragma unroll
        for (int j = 0; j < 8; j++) {
            o[j][0] *= corr0; o[j][1] *= corr0;
            o[j][2] *= corr1; o[j][3] *= corr1;
        }

        #pragma unroll
        for (int kg = 0; kg < 4; kg++) {
            uint32_t ph[4], pl[4];
            split2(s[2*kg][0],   s[2*kg][1],   ph[0], pl[0]);
            split2(s[2*kg][2],   s[2*kg][3],   ph[1], pl[1]);
            split2(s[2*kg+1][0], s[2*kg+1][1], ph[2], pl[2]);
            split2(s[2*kg+1][2], s[2*kg+1][3], ph[3], pl[3]);
            int rV = kg * 16 + (lane & 15);
            #pragma unroll
            for (int np = 0; np < 4; np++) {
                uint32_t vaddr = kb + 16384 + (uint32_t)rV * 128
                               + (uint32_t)(((np * 2 + (lane >> 4)) ^ (rV & 7)) << 4);
                uint32_t vhF[4], vlF[4];
                LDSM4T(vhF, vaddr);
                LDSM4T(vlF, vaddr + 8192);
                #pragma unroll
                for (int hf = 0; hf < 2; hf++) {
                    int nt = np * 2 + hf, rb = hf * 2;
                    MMA16816(o[nt], ph, vhF[rb], vhF[rb + 1]);
                    MMA16816(o[nt], pl, vhF[rb], vhF[rb + 1]);
                    MMA16816(o[nt], ph, vlF[rb], vlF[rb + 1]);
                }
            }
        }
    }

    float i0 = 1.0f / l0, i1 = 1.0f / l1;
    size_t row0 = (size_t)b * 1024 + qt * 128 + w * 16 + (lane >> 2);
    #pragma unroll
    for (int j = 0; j < 8; j++) {
        int col = h * 64 + j * 8 + c2;
        uint32_t hph, lph;
        split2(o[j][0] * i0, o[j][1] * i0, hph, lph);
        *(uint32_t*)(chi + row0 * D_ + col) = hph;
        *(uint32_t*)(clo + row0 * D_ + col) = lph;
        split2(o[j][2] * i1, o[j][3] * i1, hph, lph);
        *(uint32_t*)(chi + (row0 + 8) * D_ + col) = hph;
        *(uint32_t*)(clo + (row0 + 8) * D_ + col) = lph;
    }
    #undef LOADKV
}

// ---------------------------------------------------------------------------
// LayerNorm over last dim (1024).
// ---------------------------------------------------------------------------
__global__ __launch_bounds__(256) void lnorm(
    const float* __restrict__ X, const float* __restrict__ hsc,
    const float* __restrict__ hbi, float* __restrict__ out)
{
    int row = blockIdx.x;
    int c4 = threadIdx.x * 4;
    const float* x = X + (size_t)row * D_;
    float4 v = *(const float4*)(x + c4);
    float sum = v.x + v.y + v.z + v.w;
    float sq  = v.x*v.x + v.y*v.y + v.z*v.z + v.w*v.w;
    #pragma unroll
    for (int off = 16; off > 0; off >>= 1) {
        sum += __shfl_xor_sync(0xffffffffu, sum, off);
        sq  += __shfl_xor_sync(0xffffffffu, sq,  off);
    }
    __shared__ float rs[8], rq[8];
    int warp = threadIdx.x >> 5;
    if ((threadIdx.x & 31) == 0) { rs[warp] = sum; rq[warp] = sq; }
    __syncthreads();
    float tot = 0.f, totq = 0.f;
    #pragma unroll
    for (int wv = 0; wv < 8; wv++) { tot += rs[wv]; totq += rq[wv]; }
    float mu  = tot  * (1.0f / 1024.0f);
    float var = totq * (1.0f / 1024.0f) - mu * mu;
    float inv = rsqrtf(var + 1e-12f);
    float4 sc = *(const float4*)(hsc + c4);
    float4 bi = *(const float4*)(hbi + c4);
    float4 oo;
    oo.x = (v.x - mu) * inv * sc.x + bi.x;
    oo.y = (v.y - mu) * inv * sc.y + bi.y;
    oo.z = (v.z - mu) * inv * sc.z + bi.z;
    oo.w = (v.w - mu) * inv * sc.w + bi.w;
    *(float4*)&out[(size_t)row * D_ + c4] = oo;
}

// ---------------------------------------------------------------------------
extern "C" void kernel_launch(void* const* d_in, const int* in_sizes, int n_in,
                              void* d_out, int out_size)
{
    const float* hidden = (const float*)d_in[0];
    const float* mask   = (const float*)d_in[1];
    const float* phi    = (const float*)d_in[2];
    const float* mag    = (const float*)d_in[3];
    const float* Wq     = (const float*)d_in[4];
    const float* bq     = (const float*)d_in[5];
    const float* Wk     = (const float*)d_in[6];
    const float* bk     = (const float*)d_in[7];
    const float* Wv     = (const float*)d_in[8];
    const float* bv     = (const float*)d_in[9];
    const float* gamma  = (const float*)d_in[10];
    const float* Wo     = (const float*)d_in[11];
    const float* bo     = (const float*)d_in[12];
    const float* lns    = (const float*)d_in[13];
    const float* lnb    = (const float*)d_in[14];
    float* out = (float*)d_out;

    float *x;
    float4* prp;
    __nv_bfloat16 *ahi, *alo, *wthi, *wtlo, *qhi, *qlo, *khi, *klo, *vhi, *vlo;
    cudaGetSymbolAddress((void**)&x,    g_x);
    cudaGetSymbolAddress((void**)&prp,  g_prep);
    cudaGetSymbolAddress((void**)&ahi,  g_ahi);
    cudaGetSymbolAddress((void**)&alo,  g_alo);
    cudaGetSymbolAddress((void**)&wthi, g_wthi);
    cudaGetSymbolAddress((void**)&wtlo, g_wtlo);
    cudaGetSymbolAddress((void**)&qhi,  g_qhi);
    cudaGetSymbolAddress((void**)&qlo,  g_qlo);
    cudaGetSymbolAddress((void**)&khi,  g_khi);
    cudaGetSymbolAddress((void**)&klo,  g_klo);
    cudaGetSymbolAddress((void**)&vhi,  g_vhi);
    cudaGetSymbolAddress((void**)&vlo,  g_vlo);

    cudaFuncSetAttribute(gemm_hmma, cudaFuncAttributeMaxDynamicSharedMemorySize, GEMM_DYN);
    cudaFuncSetAttribute(attn_hmma, cudaFuncAttributeMaxDynamicSharedMemorySize, ATTN_DYN);

    const int DD = D_ * D_;

    prep<<<(B_ * H_ * L_) / 256, 256>>>(phi, mag, gamma, prp);
    convA<<<(M_TOT * D_ / 4 + 255) / 256, 256>>>((const float4*)hidden, (uint2*)ahi, (uint2*)alo, M_TOT * D_ / 4);
    convW4<<<dim3(32, 32, 4), 256>>>(Wq, Wk, Wv, Wo, wthi, wtlo);

    // QKV fused (z: 0=Q rot, 1=K rot, 2=V), all bf16 hi/lo head-major outputs
    gemm_hmma<<<dim3(D_ / GN, M_TOT / GM, 3), 256, GEMM_DYN>>>(
        ahi, alo, wthi, wtlo, bq, bk, bv, prp,
        qhi, qlo, khi, klo, vhi, vlo, nullptr, nullptr);

    attn_hmma<<<dim3(L_ / 128, B_ * H_), 256, ATTN_DYN>>>(
        qhi, qlo, khi, klo, vhi, vlo, mask, ahi, alo);

    // Wo projection + residual
    gemm_hmma<<<dim3(D_ / GN, M_TOT / GM, 1), 256, GEMM_DYN>>>(
        ahi, alo, wthi + 3*DD, wtlo + 3*DD, bo, bo, bo, prp,
        nullptr, nullptr, nullptr, nullptr, nullptr, nullptr, hidden, x);

    lnorm<<<M_TOT, 256>>>(x, lns, lnb, out);
}

// round 8
// speedup vs baseline: 3.9185x; 1.4122x over previous
#include <cuda_runtime.h>
#include <cuda_fp16.h>
#include <math.h>
#include <stdint.h>

#define B_  4
#define L_  1024
#define D_  1024
#define H_  16
#define HD_ 64
#define M_TOT (B_*L_)   // 4096

// ---------------------------------------------------------------------------
// Scratch
// ---------------------------------------------------------------------------
__device__ float g_x[M_TOT * D_];
__device__ float4 g_prep[B_ * H_ * L_];     // (sc, sin, cos, 0) per (bh,l)
__device__ __half g_ahi[M_TOT * D_];        // activations / ctx hi (22-bit side)
__device__ __half g_alo[M_TOT * D_];
__device__ __half g_wthi[4 * D_ * D_];      // W^T [N][K] fp16 (11-bit side)
__device__ __half g_qhi[M_TOT * D_];        // rotated Q fp16 hi/lo, head-major
__device__ __half g_qlo[M_TOT * D_];
__device__ __half g_khi[M_TOT * D_];        // rotated K fp16 (hi only)
__device__ __half g_vhi[M_TOT * D_];        // V fp16 hi/lo, head-major
__device__ __half g_vlo[M_TOT * D_];

// ---------------------------------------------------------------------------
// Helpers
// ---------------------------------------------------------------------------
__device__ __forceinline__ uint32_t smem_to_u32(const void* p) {
    uint32_t a;
    asm("{ .reg .u64 t; cvta.to.shared.u64 t, %1; cvt.u32.u64 %0, t; }"
        : "=r"(a) : "l"(p));
    return a;
}

#define CP16(dst, src) \
    asm volatile("cp.async.cg.shared.global [%0], [%1], 16;" \
                 :: "r"(dst), "l"(src) : "memory")
#define CP_COMMIT() asm volatile("cp.async.commit_group;" ::: "memory")

#define LDSM4(r, addr) \
    asm volatile("ldmatrix.sync.aligned.m8n8.x4.shared.b16 {%0,%1,%2,%3}, [%4];" \
                 : "=r"((r)[0]), "=r"((r)[1]), "=r"((r)[2]), "=r"((r)[3]) : "r"(addr))
#define LDSM4T(r, addr) \
    asm volatile("ldmatrix.sync.aligned.m8n8.x4.trans.shared.b16 {%0,%1,%2,%3}, [%4];" \
                 : "=r"((r)[0]), "=r"((r)[1]), "=r"((r)[2]), "=r"((r)[3]) : "r"(addr))

#define MMA16816(c, a, b0, b1) \
    asm volatile("mma.sync.aligned.m16n8k16.row.col.f32.f16.f16.f32 " \
                 "{%0,%1,%2,%3}, {%4,%5,%6,%7}, {%8,%9}, {%0,%1,%2,%3};" \
                 : "+f"((c)[0]), "+f"((c)[1]), "+f"((c)[2]), "+f"((c)[3]) \
                 : "r"((a)[0]), "r"((a)[1]), "r"((a)[2]), "r"((a)[3]), \
                   "r"(b0), "r"(b1))

// pack two floats -> fp16x2 (x in low half)
__device__ __forceinline__ uint32_t pack2h(float x, float y) {
    uint32_t d;
    asm("cvt.rn.f16x2.f32 %0, %1, %2;" : "=r"(d) : "f"(y), "f"(x));
    return d;
}
// two floats -> fp16x2 hi + fp16x2 lo (residual)
__device__ __forceinline__ void split2h(float x, float y, uint32_t& h, uint32_t& l) {
    uint32_t hp = pack2h(x, y);
    __half2 h2 = *reinterpret_cast<const __half2*>(&hp);
    float2 r = __half22float2(h2);
    h = hp;
    l = pack2h(x - r.x, y - r.y);
}

// ---------------------------------------------------------------------------
// prep: per (bh, l) compute (scale, sin(phi), cos(phi))
// ---------------------------------------------------------------------------
__global__ __launch_bounds__(256) void prep(
    const float* __restrict__ phi, const float* __restrict__ mag,
    const float* __restrict__ gamma, float4* __restrict__ out)
{
    int i = blockIdx.x * 256 + threadIdx.x;      // < 65536
    int h = (i >> 10) & 15;
    float sc = 1.0f + gamma[h] * tanhf(mag[i]);
    float s, c;
    sincosf(phi[i], &s, &c);
    out[i] = make_float4(sc, s, c, 0.f);
}

// ---------------------------------------------------------------------------
// convA: fp32 -> fp16 hi/lo
// ---------------------------------------------------------------------------
__global__ __launch_bounds__(256) void convA(
    const float4* __restrict__ x, uint2* __restrict__ hi, uint2* __restrict__ lo, int n4)
{
    int i = blockIdx.x * 256 + threadIdx.x;
    if (i >= n4) return;
    float4 v = x[i];
    uint2 ho, lv;
    split2h(v.x, v.y, ho.x, lv.x);
    split2h(v.z, v.w, ho.y, lv.y);
    hi[i] = ho; lo[i] = lv;
}

// W[K,N] fp32 -> WT[N,K] fp16 (hi only); grid.z selects matrix.
__global__ __launch_bounds__(256) void convW4(
    const float* __restrict__ Wq, const float* __restrict__ Wk,
    const float* __restrict__ Wv, const float* __restrict__ Wo,
    __half* __restrict__ hi)
{
    __shared__ float t[32][33];
    const int z = blockIdx.z;
    const float* W = (z == 0) ? Wq : (z == 1) ? Wk : (z == 2) ? Wv : Wo;
    __half* hz = hi + (size_t)z * D_ * D_;
    int n0 = blockIdx.x * 32, k0 = blockIdx.y * 32;
    int tx = threadIdx.x & 31, ty = threadIdx.x >> 5;
    #pragma unroll
    for (int j = 0; j < 4; j++)
        t[ty + j*8][tx] = W[(size_t)(k0 + ty + j*8) * D_ + n0 + tx];
    __syncthreads();
    #pragma unroll
    for (int j = 0; j < 4; j++)
        hz[(size_t)(n0 + ty + j*8) * D_ + k0 + tx] = __float2half_rn(t[tx][ty + j*8]);
}

// ---------------------------------------------------------------------------
// HMMA fp16 2-term GEMM, 128x256 CTA tile, 256 threads = 8 warps (64x64 tiles).
// C = (Ahi + Alo) @ Bhi. Modes:
//  res == nullptr, z=0: Q -> bias+scale+rotate -> fp16 hi/lo head-major
//  res == nullptr, z=1: K -> bias+scale+rotate -> fp16 hi only head-major
//  res == nullptr, z=2: V -> bias -> fp16 hi/lo head-major
//  res != nullptr:      Wo -> bias + residual -> fp32 row-major
// ---------------------------------------------------------------------------
#define GM 128
#define GN 256
#define KC 64
#define OFF_ALO  16384
#define OFF_BHI  32768
#define STAGE    65536
#define GEMM_DYN (2*STAGE)   // 131072

__global__ __launch_bounds__(256, 1) void gemm_hmma(
    const __half* __restrict__ Ahi, const __half* __restrict__ Alo,
    const __half* __restrict__ WThi,
    const float* __restrict__ bias0, const float* __restrict__ bias1,
    const float* __restrict__ bias2,
    const float4* __restrict__ prp,
    __half* __restrict__ qh, __half* __restrict__ ql,
    __half* __restrict__ kh,
    __half* __restrict__ vh, __half* __restrict__ vl,
    const float* __restrict__ res, float* __restrict__ xout)
{
    extern __shared__ char smraw[];
    const uint32_t sbase = smem_to_u32(smraw);
    const int tid  = threadIdx.x;
    const int lane = tid & 31, wid = tid >> 5;
    const int wm = wid >> 2, wn = wid & 3;
    const int bm = blockIdx.y * GM, bn = blockIdx.x * GN;
    const int z  = blockIdx.z;

    const __half* Bh = WThi + (size_t)z * D_ * D_;
    const float* bias = (z == 0) ? bias0 : (z == 1) ? bias1 : bias2;

    const int rr  = tid >> 3;
    const int seg = tid & 7;

    #define LOAD_STAGE(s, kc) do { \
        uint32_t sb_ = sbase + (uint32_t)(s) * STAGE; \
        _Pragma("unroll") \
        for (int h4 = 0; h4 < 4; h4++) { \
            int r_ = rr + h4 * 32; \
            uint32_t sw_ = (uint32_t)r_ * 128 + (uint32_t)((seg ^ (r_ & 7)) << 4); \
            size_t g_ = (size_t)(bm + r_) * D_ + (kc) + seg * 8; \
            CP16(sb_ + sw_,           Ahi + g_); \
            CP16(sb_ + OFF_ALO + sw_, Alo + g_); \
        } \
        _Pragma("unroll") \
        for (int h8 = 0; h8 < 8; h8++) { \
            int r_ = rr + h8 * 32; \
            uint32_t sw_ = (uint32_t)r_ * 128 + (uint32_t)((seg ^ (r_ & 7)) << 4); \
            size_t g_ = (size_t)(bn + r_) * D_ + (kc) + seg * 8; \
            CP16(sb_ + OFF_BHI + sw_, Bh + g_); \
        } \
        CP_COMMIT(); \
    } while (0)

    float c[4][8][4];
    #pragma unroll
    for (int mi = 0; mi < 4; mi++)
        #pragma unroll
        for (int ni = 0; ni < 8; ni++)
            #pragma unroll
            for (int e = 0; e < 4; e++) c[mi][ni][e] = 0.f;

    LOAD_STAGE(0, 0);

    const int rAb = wm * 64 + (lane & 15);
    const int rBb = wn * 64 + ((lane >> 4) << 3) + (lane & 7);
    const int sgA = lane >> 4;
    const int sgB = (lane >> 3) & 1;

    for (int ch = 0; ch < 16; ch++) {
        if (ch < 15) {
            LOAD_STAGE((ch + 1) & 1, (ch + 1) * KC);
            asm volatile("cp.async.wait_group 1;" ::: "memory");
        } else {
            asm volatile("cp.async.wait_group 0;" ::: "memory");
        }
        __syncthreads();

        const uint32_t sb = sbase + (uint32_t)(ch & 1) * STAGE;
        #pragma unroll
        for (int ks = 0; ks < 4; ks++) {
            uint32_t ah[4][4], al[4][4];
            #pragma unroll
            for (int mi = 0; mi < 4; mi++) {
                int rA = rAb + mi * 16;
                uint32_t addr = sb + (uint32_t)rA * 128
                              + (uint32_t)(((ks * 2 + sgA) ^ (rA & 7)) << 4);
                LDSM4(ah[mi], addr);
                LDSM4(al[mi], addr + OFF_ALO);
            }
            #pragma unroll
            for (int np = 0; np < 4; np++) {
                int rB = rBb + np * 16;
                uint32_t addr = sb + OFF_BHI + (uint32_t)rB * 128
                              + (uint32_t)(((ks * 2 + sgB) ^ (rB & 7)) << 4);
                uint32_t bh[4];
                LDSM4(bh, addr);
                #pragma unroll
                for (int hf = 0; hf < 2; hf++) {
                    int ni = np * 2 + hf, rb = hf * 2;
                    #pragma unroll
                    for (int mi = 0; mi < 4; mi++) {
                        MMA16816(c[mi][ni], ah[mi], bh[rb], bh[rb + 1]);
                        MMA16816(c[mi][ni], al[mi], bh[rb], bh[rb + 1]);
                    }
                }
            }
        }
        __syncthreads();
    }

    // ---- epilogue ----
    const int g = lane >> 2, tig = lane & 3;
    if (res) {
        // Wo projection + bias + residual -> fp32 row-major
        #pragma unroll
        for (int mi = 0; mi < 4; mi++) {
            int row0 = bm + wm * 64 + mi * 16 + g;
            #pragma unroll
            for (int ni = 0; ni < 8; ni++) {
                int col = bn + wn * 64 + ni * 8 + tig * 2;
                float2 bv = *(const float2*)(bias + col);
                float2 r0 = *(const float2*)(res + (size_t)row0 * D_ + col);
                float2 r1 = *(const float2*)(res + (size_t)(row0 + 8) * D_ + col);
                *(float2*)(xout + (size_t)row0 * D_ + col) =
                    make_float2(c[mi][ni][0] + bv.x + r0.x, c[mi][ni][1] + bv.y + r0.y);
                *(float2*)(xout + (size_t)(row0 + 8) * D_ + col) =
                    make_float2(c[mi][ni][2] + bv.x + r1.x, c[mi][ni][3] + bv.y + r1.y);
            }
        }
    } else if (z == 2) {
        // V: bias -> fp16 hi/lo head-major
        #pragma unroll
        for (int mi = 0; mi < 4; mi++) {
            int row0 = bm + wm * 64 + mi * 16 + g;
            int bidx = row0 >> 10, l0 = row0 & 1023;
            #pragma unroll
            for (int ni = 0; ni < 8; ni++) {
                int col = bn + wn * 64 + ni * 8 + tig * 2;
                float2 bv = *(const float2*)(bias + col);
                size_t o0 = (((size_t)bidx * 16 + (col >> 6)) * 1024 + l0) * 64 + (col & 63);
                size_t o1 = o0 + 8 * 64;
                uint32_t h, l;
                split2h(c[mi][ni][0] + bv.x, c[mi][ni][1] + bv.y, h, l);
                *(uint32_t*)(vh + o0) = h; *(uint32_t*)(vl + o0) = l;
                split2h(c[mi][ni][2] + bv.x, c[mi][ni][3] + bv.y, h, l);
                *(uint32_t*)(vh + o1) = h; *(uint32_t*)(vl + o1) = l;
            }
        }
    } else {
        // Q/K: bias + scale + rotate; Q -> hi/lo, K -> hi only
        const int hh = (bn + wn * 64) >> 6;
        #pragma unroll
        for (int mi = 0; mi < 4; mi++) {
            int row0 = bm + wm * 64 + mi * 16 + g;
            int bidx = row0 >> 10, l0 = row0 & 1023;
            int pidx = (bidx * 16 + hh) * 1024 + l0;
            float4 p0 = prp[pidx];
            float4 p1 = prp[pidx + 8];
            size_t ob = ((size_t)(bidx * 16 + hh) * 1024 + l0) * 64;
            #pragma unroll
            for (int ni = 0; ni < 4; ni++) {
                int d = ni * 8 + tig * 2;
                float2 b1 = *(const float2*)(bias + bn + wn * 64 + d);
                float2 b2 = *(const float2*)(bias + bn + wn * 64 + d + 32);
                // row0
                {
                    float x0 = (c[mi][ni][0]   + b1.x) * p0.x;
                    float x1 = (c[mi][ni][1]   + b1.y) * p0.x;
                    float y0 = (c[mi][ni+4][0] + b2.x) * p0.x;
                    float y1 = (c[mi][ni+4][1] + b2.y) * p0.x;
                    float rx0 = x0 * p0.z - y0 * p0.y, rx1 = x1 * p0.z - y1 * p0.y;
                    float ry0 = y0 * p0.z + x0 * p0.y, ry1 = y1 * p0.z + x1 * p0.y;
                    if (z == 0) {
                        uint32_t hA, lA, hB, lB;
                        split2h(rx0, rx1, hA, lA);
                        split2h(ry0, ry1, hB, lB);
                        *(uint32_t*)(qh + ob + d)      = hA; *(uint32_t*)(ql + ob + d)      = lA;
                        *(uint32_t*)(qh + ob + d + 32) = hB; *(uint32_t*)(ql + ob + d + 32) = lB;
                    } else {
                        *(uint32_t*)(kh + ob + d)      = pack2h(rx0, rx1);
                        *(uint32_t*)(kh + ob + d + 32) = pack2h(ry0, ry1);
                    }
                }
                // row0 + 8
                {
                    float x0 = (c[mi][ni][2]   + b1.x) * p1.x;
                    float x1 = (c[mi][ni][3]   + b1.y) * p1.x;
                    float y0 = (c[mi][ni+4][2] + b2.x) * p1.x;
                    float y1 = (c[mi][ni+4][3] + b2.y) * p1.x;
                    float rx0 = x0 * p1.z - y0 * p1.y, rx1 = x1 * p1.z - y1 * p1.y;
                    float ry0 = y0 * p1.z + x0 * p1.y, ry1 = y1 * p1.z + x1 * p1.y;
                    if (z == 0) {
                        uint32_t hA, lA, hB, lB;
                        split2h(rx0, rx1, hA, lA);
                        split2h(ry0, ry1, hB, lB);
                        *(uint32_t*)(qh + ob + 512 + d)      = hA; *(uint32_t*)(ql + ob + 512 + d)      = lA;
                        *(uint32_t*)(qh + ob + 512 + d + 32) = hB; *(uint32_t*)(ql + ob + 512 + d + 32) = lB;
                    } else {
                        *(uint32_t*)(kh + ob + 512 + d)      = pack2h(rx0, rx1);
                        *(uint32_t*)(kh + ob + 512 + d + 32) = pack2h(ry0, ry1);
                    }
                }
            }
        }
    }
    #undef LOAD_STAGE
}

// ---------------------------------------------------------------------------
// HMMA fp16 flash attention, 2-term. Q = hi+lo (22b), K = hi (11b),
// P = hi (11b), V = hi+lo (22b). KV tiles of 64 keys, double-buffered.
// ---------------------------------------------------------------------------
#define AT_QHI 0
#define AT_QLO 16384
#define AT_STG 32768
#define KVSTG  24576                  // K @0, Vhi @8192, Vlo @16384
#define AT_MASK (AT_STG + 2*KVSTG)    // 81920
#define ATTN_DYN (AT_MASK + 4096)     // 86016

__global__ __launch_bounds__(256, 2) void attn_hmma(
    const __half* __restrict__ qhi, const __half* __restrict__ qlo,
    const __half* __restrict__ khi,
    const __half* __restrict__ vhi, const __half* __restrict__ vlo,
    const float* __restrict__ mask,
    __half* __restrict__ chi, __half* __restrict__ clo)
{
    extern __shared__ char smraw[];
    const uint32_t sb = smem_to_u32(smraw);
    const int tid = threadIdx.x, lane = tid & 31, w = tid >> 5;
    const int qt = blockIdx.x, bh = blockIdx.y;
    const int b = bh >> 4, h = bh & 15;

    CP16(sb + AT_MASK + tid * 16, mask + b * 1024 + tid * 4);
    #pragma unroll
    for (int it = 0; it < 4; it++) {
        int idx = tid + it * 256, r = idx >> 3, seg = idx & 7;
        size_t g = ((size_t)bh * 1024 + qt * 128 + r) * 64 + seg * 8;
        uint32_t d = sb + (uint32_t)r * 128 + (uint32_t)((seg ^ (r & 7)) << 4);
        CP16(d + AT_QHI, qhi + g);
        CP16(d + AT_QLO, qlo + g);
    }
    CP_COMMIT();

    #define LOADKV(s, kt_) do { \
        _Pragma("unroll") \
        for (int it = 0; it < 2; it++) { \
            int idx = tid + it * 256, r = idx >> 3, sg = idx & 7; \
            size_t g = ((size_t)bh * 1024 + (kt_) * 64 + r) * 64 + sg * 8; \
            uint32_t d = sb + AT_STG + (uint32_t)(s) * KVSTG \
                       + (uint32_t)r * 128 + (uint32_t)((sg ^ (r & 7)) << 4); \
            CP16(d,         khi + g); \
            CP16(d + 8192,  vhi + g); \
            CP16(d + 16384, vlo + g); \
        } \
        CP_COMMIT(); \
    } while (0)

    LOADKV(0, 0);

    float o[8][4];
    #pragma unroll
    for (int j = 0; j < 8; j++)
        #pragma unroll
        for (int e = 0; e < 4; e++) o[j][e] = 0.f;
    float m0 = -INFINITY, m1 = -INFINITY, l0 = 0.f, l1 = 0.f;

    const int rA = w * 16 + (lane & 15);
    const int rBb = ((lane >> 4) << 3) + (lane & 7);
    const int c2 = (lane & 3) * 2;

    for (int kt = 0; kt < 16; kt++) {
        asm volatile("cp.async.wait_group 0;" ::: "memory");
        __syncthreads();
        if (kt < 15) LOADKV((kt + 1) & 1, kt + 1);
        const uint32_t kb = sb + AT_STG + (uint32_t)(kt & 1) * KVSTG;

        float s[8][4];
        #pragma unroll
        for (int j = 0; j < 8; j++)
            #pragma unroll
            for (int e = 0; e < 4; e++) s[j][e] = 0.f;

        #pragma unroll
        for (int ks = 0; ks < 4; ks++) {
            uint32_t ah[4], al[4];
            uint32_t aaddr = sb + AT_QHI + (uint32_t)rA * 128
                           + (uint32_t)(((ks * 2 + (lane >> 4)) ^ (rA & 7)) << 4);
            LDSM4(ah, aaddr);
            LDSM4(al, aaddr + (AT_QLO - AT_QHI));
            #pragma unroll
            for (int np = 0; np < 4; np++) {
                int rB = np * 16 + rBb;
                uint32_t baddr = kb + (uint32_t)rB * 128
                               + (uint32_t)(((ks * 2 + ((lane >> 3) & 1)) ^ (rB & 7)) << 4);
                uint32_t bhF[4];
                LDSM4(bhF, baddr);
                #pragma unroll
                for (int hf = 0; hf < 2; hf++) {
                    int nt = np * 2 + hf, rb = hf * 2;
                    MMA16816(s[nt], ah, bhF[rb], bhF[rb + 1]);
                    MMA16816(s[nt], al, bhF[rb], bhF[rb + 1]);
                }
            }
        }

        float mx0 = -INFINITY, mx1 = -INFINITY;
        #pragma unroll
        for (int j = 0; j < 8; j++) {
            float2 mk = *(float2*)(smraw + AT_MASK + (size_t)(kt * 64 + j * 8 + c2) * 4);
            s[j][0] = s[j][0] * 0.125f + mk.x;
            s[j][1] = s[j][1] * 0.125f + mk.y;
            s[j][2] = s[j][2] * 0.125f + mk.x;
            s[j][3] = s[j][3] * 0.125f + mk.y;
            mx0 = fmaxf(mx0, fmaxf(s[j][0], s[j][1]));
            mx1 = fmaxf(mx1, fmaxf(s[j][2], s[j][3]));
        }
        #pragma unroll
        for (int off = 1; off < 4; off <<= 1) {
            mx0 = fmaxf(mx0, __shfl_xor_sync(0xffffffffu, mx0, off));
            mx1 = fmaxf(mx1, __shfl_xor_sync(0xffffffffu, mx1, off));
        }
        float mn0 = fmaxf(m0, mx0), mn1 = fmaxf(m1, mx1);
        float corr0 = __expf(m0 - mn0), corr1 = __expf(m1 - mn1);
        m0 = mn0; m1 = mn1;
        float sum0 = 0.f, sum1 = 0.f;
        #pragma unroll
        for (int j = 0; j < 8; j++) {
            s[j][0] = __expf(s[j][0] - m0);
            s[j][1] = __expf(s[j][1] - m0);
            s[j][2] = __expf(s[j][2] - m1);
            s[j][3] = __expf(s[j][3] - m1);
            sum0 += s[j][0] + s[j][1];
            sum1 += s[j][2] + s[j][3];
        }
        #pragma unroll
        for (int off = 1; off < 4; off <<= 1) {
            sum0 += __shfl_xor_sync(0xffffffffu, sum0, off);
            sum1 += __shfl_xor_sync(0xffffffffu, sum1, off);
        }
        l0 = l0 * corr0 + sum0;
        l1 = l1 * corr1 + sum1;
        #pragma unroll
        for (int j = 0; j < 8; j++) {
            o[j][0] *= corr0; o[j][1] *= corr0;
            o[j][2] *= corr1; o[j][3] *= corr1;
        }

        #pragma unroll
        for (int kg = 0; kg < 4; kg++) {
            uint32_t ph[4];
            ph[0] = pack2h(s[2*kg][0],   s[2*kg][1]);
            ph[1] = pack2h(s[2*kg][2],   s[2*kg][3]);
            ph[2] = pack2h(s[2*kg+1][0], s[2*kg+1][1]);
            ph[3] = pack2h(s[2*kg+1][2], s[2*kg+1][3]);
            int rV = kg * 16 + (lane & 15);
            #pragma unroll
            for (int np = 0; np < 4; np++) {
                uint32_t vaddr = kb + 8192 + (uint32_t)rV * 128
                               + (uint32_t)(((np * 2 + (lane >> 4)) ^ (rV & 7)) << 4);
                uint32_t vhF[4], vlF[4];
                LDSM4T(vhF, vaddr);
                LDSM4T(vlF, vaddr + 8192);
                #pragma unroll
                for (int hf = 0; hf < 2; hf++) {
                    int nt = np * 2 + hf, rb = hf * 2;
                    MMA16816(o[nt], ph, vhF[rb], vhF[rb + 1]);
                    MMA16816(o[nt], ph, vlF[rb], vlF[rb + 1]);
                }
            }
        }
    }

    float i0 = 1.0f / l0, i1 = 1.0f / l1;
    size_t row0 = (size_t)b * 1024 + qt * 128 + w * 16 + (lane >> 2);
    #pragma unroll
    for (int j = 0; j < 8; j++) {
        int col = h * 64 + j * 8 + c2;
        uint32_t hph, lph;
        split2h(o[j][0] * i0, o[j][1] * i0, hph, lph);
        *(uint32_t*)(chi + row0 * D_ + col) = hph;
        *(uint32_t*)(clo + row0 * D_ + col) = lph;
        split2h(o[j][2] * i1, o[j][3] * i1, hph, lph);
        *(uint32_t*)(chi + (row0 + 8) * D_ + col) = hph;
        *(uint32_t*)(clo + (row0 + 8) * D_ + col) = lph;
    }
    #undef LOADKV
}

// ---------------------------------------------------------------------------
// LayerNorm over last dim (1024).
// ---------------------------------------------------------------------------
__global__ __launch_bounds__(256) void lnorm(
    const float* __restrict__ X, const float* __restrict__ hsc,
    const float* __restrict__ hbi, float* __restrict__ out)
{
    int row = blockIdx.x;
    int c4 = threadIdx.x * 4;
    const float* x = X + (size_t)row * D_;
    float4 v = *(const float4*)(x + c4);
    float sum = v.x + v.y + v.z + v.w;
    float sq  = v.x*v.x + v.y*v.y + v.z*v.z + v.w*v.w;
    #pragma unroll
    for (int off = 16; off > 0; off >>= 1) {
        sum += __shfl_xor_sync(0xffffffffu, sum, off);
        sq  += __shfl_xor_sync(0xffffffffu, sq,  off);
    }
    __shared__ float rs[8], rq[8];
    int warp = threadIdx.x >> 5;
    if ((threadIdx.x & 31) == 0) { rs[warp] = sum; rq[warp] = sq; }
    __syncthreads();
    float tot = 0.f, totq = 0.f;
    #pragma unroll
    for (int wv = 0; wv < 8; wv++) { tot += rs[wv]; totq += rq[wv]; }
    float mu  = tot  * (1.0f / 1024.0f);
    float var = totq * (1.0f / 1024.0f) - mu * mu;
    float inv = rsqrtf(var + 1e-12f);
    float4 sc = *(const float4*)(hsc + c4);
    float4 bi = *(const float4*)(hbi + c4);
    float4 oo;
    oo.x = (v.x - mu) * inv * sc.x + bi.x;
    oo.y = (v.y - mu) * inv * sc.y + bi.y;
    oo.z = (v.z - mu) * inv * sc.z + bi.z;
    oo.w = (v.w - mu) * inv * sc.w + bi.w;
    *(float4*)&out[(size_t)row * D_ + c4] = oo;
}

// ---------------------------------------------------------------------------
extern "C" void kernel_launch(void* const* d_in, const int* in_sizes, int n_in,
                              void* d_out, int out_size)
{
    const float* hidden = (const float*)d_in[0];
    const float* mask   = (const float*)d_in[1];
    const float* phi    = (const float*)d_in[2];
    const float* mag    = (const float*)d_in[3];
    const float* Wq     = (const float*)d_in[4];
    const float* bq     = (const float*)d_in[5];
    const float* Wk     = (const float*)d_in[6];
    const float* bk     = (const float*)d_in[7];
    const float* Wv     = (const float*)d_in[8];
    const float* bv     = (const float*)d_in[9];
    const float* gamma  = (const float*)d_in[10];
    const float* Wo     = (const float*)d_in[11];
    const float* bo     = (const float*)d_in[12];
    const float* lns    = (const float*)d_in[13];
    const float* lnb    = (const float*)d_in[14];
    float* out = (float*)d_out;

    float *x;
    float4* prp;
    __half *ahi, *alo, *wthi, *qhi, *qlo, *khi, *vhi, *vlo;
    cudaGetSymbolAddress((void**)&x,    g_x);
    cudaGetSymbolAddress((void**)&prp,  g_prep);
    cudaGetSymbolAddress((void**)&ahi,  g_ahi);
    cudaGetSymbolAddress((void**)&alo,  g_alo);
    cudaGetSymbolAddress((void**)&wthi, g_wthi);
    cudaGetSymbolAddress((void**)&qhi,  g_qhi);
    cudaGetSymbolAddress((void**)&qlo,  g_qlo);
    cudaGetSymbolAddress((void**)&khi,  g_khi);
    cudaGetSymbolAddress((void**)&vhi,  g_vhi);
    cudaGetSymbolAddress((void**)&vlo,  g_vlo);

    cudaFuncSetAttribute(gemm_hmma, cudaFuncAttributeMaxDynamicSharedMemorySize, GEMM_DYN);
    cudaFuncSetAttribute(attn_hmma, cudaFuncAttributeMaxDynamicSharedMemorySize, ATTN_DYN);

    const int DD = D_ * D_;

    prep<<<(B_ * H_ * L_) / 256, 256>>>(phi, mag, gamma, prp);
    convA<<<(M_TOT * D_ / 4 + 255) / 256, 256>>>((const float4*)hidden, (uint2*)ahi, (uint2*)alo, M_TOT * D_ / 4);
    convW4<<<dim3(32, 32, 4), 256>>>(Wq, Wk, Wv, Wo, wthi);

    // QKV fused (z: 0=Q rot hi/lo, 1=K rot hi, 2=V hi/lo), head-major outputs
    gemm_hmma<<<dim3(D_ / GN, M_TOT / GM, 3), 256, GEMM_DYN>>>(
        ahi, alo, wthi, bq, bk, bv, prp,
        qhi, qlo, khi, vhi, vlo, nullptr, nullptr);

    attn_hmma<<<dim3(L_ / 128, B_ * H_), 256, ATTN_DYN>>>(
        qhi, qlo, khi, vhi, vlo, mask, ahi, alo);

    // Wo projection + residual
    gemm_hmma<<<dim3(D_ / GN, M_TOT / GM, 1), 256, GEMM_DYN>>>(
        ahi, alo, wthi + 3*DD, bo, bo, bo, prp,
        nullptr, nullptr, nullptr, nullptr, nullptr, hidden, x);

    lnorm<<<M_TOT, 256>>>(x, lns, lnb, out);
}

// round 9
// speedup vs baseline: 6.0172x; 1.5356x over previous
#include <cuda_runtime.h>
#include <cuda_fp16.h>
#include <math.h>
#include <stdint.h>

#define B_  4
#define L_  1024
#define D_  1024
#define H_  16
#define HD_ 64
#define M_TOT (B_*L_)   // 4096

// ---------------------------------------------------------------------------
// Scratch
// ---------------------------------------------------------------------------
__device__ float g_x[M_TOT * D_];
__device__ float4 g_prep[B_ * H_ * L_];     // (sc, sin, cos, 0) per (bh,l)
__device__ __half g_ahi[M_TOT * D_];        // activations / ctx fp16
__device__ __half g_wthi[4 * D_ * D_];      // W^T [N][K] fp16 (q,k,v,o)
__device__ __half g_qhi[M_TOT * D_];        // rotated Q fp16, head-major
__device__ __half g_khi[M_TOT * D_];        // rotated K fp16, head-major
__device__ __half g_vhi[M_TOT * D_];        // V fp16, head-major

// ---------------------------------------------------------------------------
// Helpers
// ---------------------------------------------------------------------------
__device__ __forceinline__ uint32_t smem_to_u32(const void* p) {
    uint32_t a;
    asm("{ .reg .u64 t; cvta.to.shared.u64 t, %1; cvt.u32.u64 %0, t; }"
        : "=r"(a) : "l"(p));
    return a;
}

#define CP16(dst, src) \
    asm volatile("cp.async.cg.shared.global [%0], [%1], 16;" \
                 :: "r"(dst), "l"(src) : "memory")
#define CP_COMMIT() asm volatile("cp.async.commit_group;" ::: "memory")

#define LDSM4(r, addr) \
    asm volatile("ldmatrix.sync.aligned.m8n8.x4.shared.b16 {%0,%1,%2,%3}, [%4];" \
                 : "=r"((r)[0]), "=r"((r)[1]), "=r"((r)[2]), "=r"((r)[3]) : "r"(addr))
#define LDSM4T(r, addr) \
    asm volatile("ldmatrix.sync.aligned.m8n8.x4.trans.shared.b16 {%0,%1,%2,%3}, [%4];" \
                 : "=r"((r)[0]), "=r"((r)[1]), "=r"((r)[2]), "=r"((r)[3]) : "r"(addr))

#define MMA16816(c, a, b0, b1) \
    asm volatile("mma.sync.aligned.m16n8k16.row.col.f32.f16.f16.f32 " \
                 "{%0,%1,%2,%3}, {%4,%5,%6,%7}, {%8,%9}, {%0,%1,%2,%3};" \
                 : "+f"((c)[0]), "+f"((c)[1]), "+f"((c)[2]), "+f"((c)[3]) \
                 : "r"((a)[0]), "r"((a)[1]), "r"((a)[2]), "r"((a)[3]), \
                   "r"(b0), "r"(b1))

// pack two floats -> fp16x2 (x in low half)
__device__ __forceinline__ uint32_t pack2h(float x, float y) {
    uint32_t d;
    asm("cvt.rn.f16x2.f32 %0, %1, %2;" : "=r"(d) : "f"(y), "f"(x));
    return d;
}

// ---------------------------------------------------------------------------
// prep: per (bh, l) compute (scale, sin(phi), cos(phi))
// ---------------------------------------------------------------------------
__global__ __launch_bounds__(256) void prep(
    const float* __restrict__ phi, const float* __restrict__ mag,
    const float* __restrict__ gamma, float4* __restrict__ out)
{
    int i = blockIdx.x * 256 + threadIdx.x;      // < 65536
    int h = (i >> 10) & 15;
    float sc = 1.0f + gamma[h] * tanhf(mag[i]);
    float s, c;
    sincosf(phi[i], &s, &c);
    out[i] = make_float4(sc, s, c, 0.f);
}

// ---------------------------------------------------------------------------
// convA: fp32 -> fp16
// ---------------------------------------------------------------------------
__global__ __launch_bounds__(256) void convA(
    const float4* __restrict__ x, uint2* __restrict__ hi, int n4)
{
    int i = blockIdx.x * 256 + threadIdx.x;
    if (i >= n4) return;
    float4 v = x[i];
    uint2 ho;
    ho.x = pack2h(v.x, v.y);
    ho.y = pack2h(v.z, v.w);
    hi[i] = ho;
}

// W[K,N] fp32 -> WT[N,K] fp16; grid.z selects matrix.
__global__ __launch_bounds__(256) void convW4(
    const float* __restrict__ Wq, const float* __restrict__ Wk,
    const float* __restrict__ Wv, const float* __restrict__ Wo,
    __half* __restrict__ hi)
{
    __shared__ float t[32][33];
    const int z = blockIdx.z;
    const float* W = (z == 0) ? Wq : (z == 1) ? Wk : (z == 2) ? Wv : Wo;
    __half* hz = hi + (size_t)z * D_ * D_;
    int n0 = blockIdx.x * 32, k0 = blockIdx.y * 32;
    int tx = threadIdx.x & 31, ty = threadIdx.x >> 5;
    #pragma unroll
    for (int j = 0; j < 4; j++)
        t[ty + j*8][tx] = W[(size_t)(k0 + ty + j*8) * D_ + n0 + tx];
    __syncthreads();
    #pragma unroll
    for (int j = 0; j < 4; j++)
        hz[(size_t)(n0 + ty + j*8) * D_ + k0 + tx] = __float2half_rn(t[tx][ty + j*8]);
}

// ---------------------------------------------------------------------------
// HMMA fp16 1-term GEMM, 128x256 CTA tile, 256 threads = 8 warps (64x64 tiles).
// Modes:
//  res == nullptr, z=0/1: Q/K -> bias+scale+rotate -> fp16 head-major
//  res == nullptr, z=2:   V  -> bias -> fp16 head-major
//  res != nullptr:        Wo -> bias + residual -> fp32 row-major
// ---------------------------------------------------------------------------
#define GM 128
#define GN 256
#define KC 64
#define OFF_BHI  16384
#define STAGE    49152
#define GEMM_DYN (2*STAGE)   // 98304

__global__ __launch_bounds__(256, 1) void gemm_hmma(
    const __half* __restrict__ Ahi,
    const __half* __restrict__ WThi,
    const float* __restrict__ bias0, const float* __restrict__ bias1,
    const float* __restrict__ bias2,
    const float4* __restrict__ prp,
    __half* __restrict__ qh, __half* __restrict__ kh,
    __half* __restrict__ vh,
    const float* __restrict__ res, float* __restrict__ xout)
{
    extern __shared__ char smraw[];
    const uint32_t sbase = smem_to_u32(smraw);
    const int tid  = threadIdx.x;
    const int lane = tid & 31, wid = tid >> 5;
    const int wm = wid >> 2, wn = wid & 3;
    const int bm = blockIdx.y * GM, bn = blockIdx.x * GN;
    const int z  = blockIdx.z;

    const __half* Bh = WThi + (size_t)z * D_ * D_;
    const float* bias = (z == 0) ? bias0 : (z == 1) ? bias1 : bias2;

    const int rr  = tid >> 3;
    const int seg = tid & 7;

    #define LOAD_STAGE(s, kc) do { \
        uint32_t sb_ = sbase + (uint32_t)(s) * STAGE; \
        _Pragma("unroll") \
        for (int h4 = 0; h4 < 4; h4++) { \
            int r_ = rr + h4 * 32; \
            uint32_t sw_ = (uint32_t)r_ * 128 + (uint32_t)((seg ^ (r_ & 7)) << 4); \
            size_t g_ = (size_t)(bm + r_) * D_ + (kc) + seg * 8; \
            CP16(sb_ + sw_, Ahi + g_); \
        } \
        _Pragma("unroll") \
        for (int h8 = 0; h8 < 8; h8++) { \
            int r_ = rr + h8 * 32; \
            uint32_t sw_ = (uint32_t)r_ * 128 + (uint32_t)((seg ^ (r_ & 7)) << 4); \
            size_t g_ = (size_t)(bn + r_) * D_ + (kc) + seg * 8; \
            CP16(sb_ + OFF_BHI + sw_, Bh + g_); \
        } \
        CP_COMMIT(); \
    } while (0)

    float c[4][8][4];
    #pragma unroll
    for (int mi = 0; mi < 4; mi++)
        #pragma unroll
        for (int ni = 0; ni < 8; ni++)
            #pragma unroll
            for (int e = 0; e < 4; e++) c[mi][ni][e] = 0.f;

    LOAD_STAGE(0, 0);

    const int rAb = wm * 64 + (lane & 15);
    const int rBb = wn * 64 + ((lane >> 4) << 3) + (lane & 7);
    const int sgA = lane >> 4;
    const int sgB = (lane >> 3) & 1;

    for (int ch = 0; ch < 16; ch++) {
        if (ch < 15) {
            LOAD_STAGE((ch + 1) & 1, (ch + 1) * KC);
            asm volatile("cp.async.wait_group 1;" ::: "memory");
        } else {
            asm volatile("cp.async.wait_group 0;" ::: "memory");
        }
        __syncthreads();

        const uint32_t sb = sbase + (uint32_t)(ch & 1) * STAGE;
        #pragma unroll
        for (int ks = 0; ks < 4; ks++) {
            uint32_t ah[4][4];
            #pragma unroll
            for (int mi = 0; mi < 4; mi++) {
                int rA = rAb + mi * 16;
                uint32_t addr = sb + (uint32_t)rA * 128
                              + (uint32_t)(((ks * 2 + sgA) ^ (rA & 7)) << 4);
                LDSM4(ah[mi], addr);
            }
            #pragma unroll
            for (int np = 0; np < 4; np++) {
                int rB = rBb + np * 16;
                uint32_t addr = sb + OFF_BHI + (uint32_t)rB * 128
                              + (uint32_t)(((ks * 2 + sgB) ^ (rB & 7)) << 4);
                uint32_t bh[4];
                LDSM4(bh, addr);
                #pragma unroll
                for (int hf = 0; hf < 2; hf++) {
                    int ni = np * 2 + hf, rb = hf * 2;
                    #pragma unroll
                    for (int mi = 0; mi < 4; mi++)
                        MMA16816(c[mi][ni], ah[mi], bh[rb], bh[rb + 1]);
                }
            }
        }
        __syncthreads();
    }

    // ---- epilogue ----
    const int g = lane >> 2, tig = lane & 3;
    if (res) {
        // Wo projection + bias + residual -> fp32 row-major
        #pragma unroll
        for (int mi = 0; mi < 4; mi++) {
            int row0 = bm + wm * 64 + mi * 16 + g;
            #pragma unroll
            for (int ni = 0; ni < 8; ni++) {
                int col = bn + wn * 64 + ni * 8 + tig * 2;
                float2 bv = *(const float2*)(bias + col);
                float2 r0 = *(const float2*)(res + (size_t)row0 * D_ + col);
                float2 r1 = *(const float2*)(res + (size_t)(row0 + 8) * D_ + col);
                *(float2*)(xout + (size_t)row0 * D_ + col) =
                    make_float2(c[mi][ni][0] + bv.x + r0.x, c[mi][ni][1] + bv.y + r0.y);
                *(float2*)(xout + (size_t)(row0 + 8) * D_ + col) =
                    make_float2(c[mi][ni][2] + bv.x + r1.x, c[mi][ni][3] + bv.y + r1.y);
            }
        }
    } else if (z == 2) {
        // V: bias -> fp16 head-major
        #pragma unroll
        for (int mi = 0; mi < 4; mi++) {
            int row0 = bm + wm * 64 + mi * 16 + g;
            int bidx = row0 >> 10, l0 = row0 & 1023;
            #pragma unroll
            for (int ni = 0; ni < 8; ni++) {
                int col = bn + wn * 64 + ni * 8 + tig * 2;
                float2 bv = *(const float2*)(bias + col);
                size_t o0 = (((size_t)bidx * 16 + (col >> 6)) * 1024 + l0) * 64 + (col & 63);
                size_t o1 = o0 + 8 * 64;
                *(uint32_t*)(vh + o0) = pack2h(c[mi][ni][0] + bv.x, c[mi][ni][1] + bv.y);
                *(uint32_t*)(vh + o1) = pack2h(c[mi][ni][2] + bv.x, c[mi][ni][3] + bv.y);
            }
        }
    } else {
        // Q/K: bias + scale + rotate -> fp16 head-major
        __half* oh = (z == 0) ? qh : kh;
        const int hh = (bn + wn * 64) >> 6;
        #pragma unroll
        for (int mi = 0; mi < 4; mi++) {
            int row0 = bm + wm * 64 + mi * 16 + g;
            int bidx = row0 >> 10, l0 = row0 & 1023;
            int pidx = (bidx * 16 + hh) * 1024 + l0;
            float4 p0 = prp[pidx];
            float4 p1 = prp[pidx + 8];
            size_t ob = ((size_t)(bidx * 16 + hh) * 1024 + l0) * 64;
            #pragma unroll
            for (int ni = 0; ni < 4; ni++) {
                int d = ni * 8 + tig * 2;
                float2 b1 = *(const float2*)(bias + bn + wn * 64 + d);
                float2 b2 = *(const float2*)(bias + bn + wn * 64 + d + 32);
                // row0
                {
                    float x0 = (c[mi][ni][0]   + b1.x) * p0.x;
                    float x1 = (c[mi][ni][1]   + b1.y) * p0.x;
                    float y0 = (c[mi][ni+4][0] + b2.x) * p0.x;
                    float y1 = (c[mi][ni+4][1] + b2.y) * p0.x;
                    *(uint32_t*)(oh + ob + d) =
                        pack2h(x0 * p0.z - y0 * p0.y, x1 * p0.z - y1 * p0.y);
                    *(uint32_t*)(oh + ob + d + 32) =
                        pack2h(y0 * p0.z + x0 * p0.y, y1 * p0.z + x1 * p0.y);
                }
                // row0 + 8
                {
                    float x0 = (c[mi][ni][2]   + b1.x) * p1.x;
                    float x1 = (c[mi][ni][3]   + b1.y) * p1.x;
                    float y0 = (c[mi][ni+4][2] + b2.x) * p1.x;
                    float y1 = (c[mi][ni+4][3] + b2.y) * p1.x;
                    *(uint32_t*)(oh + ob + 512 + d) =
                        pack2h(x0 * p1.z - y0 * p1.y, x1 * p1.z - y1 * p1.y);
                    *(uint32_t*)(oh + ob + 512 + d + 32) =
                        pack2h(y0 * p1.z + x0 * p1.y, y1 * p1.z + x1 * p1.y);
                }
            }
        }
    }
    #undef LOAD_STAGE
}

// ---------------------------------------------------------------------------
// HMMA fp16 flash attention, 1-term. KV tiles of 64 keys, double-buffered.
// ---------------------------------------------------------------------------
#define AT_Q   0
#define AT_STG 16384
#define KVSTG  16384                  // K @0, V @8192
#define AT_MASK (AT_STG + 2*KVSTG)    // 49152
#define ATTN_DYN (AT_MASK + 4096)     // 53248

__global__ __launch_bounds__(256, 2) void attn_hmma(
    const __half* __restrict__ qhi,
    const __half* __restrict__ khi,
    const __half* __restrict__ vhi,
    const float* __restrict__ mask,
    __half* __restrict__ chi)
{
    extern __shared__ char smraw[];
    const uint32_t sb = smem_to_u32(smraw);
    const int tid = threadIdx.x, lane = tid & 31, w = tid >> 5;
    const int qt = blockIdx.x, bh = blockIdx.y;
    const int b = bh >> 4, h = bh & 15;

    CP16(sb + AT_MASK + tid * 16, mask + b * 1024 + tid * 4);
    #pragma unroll
    for (int it = 0; it < 4; it++) {
        int idx = tid + it * 256, r = idx >> 3, seg = idx & 7;
        size_t g = ((size_t)bh * 1024 + qt * 128 + r) * 64 + seg * 8;
        uint32_t d = sb + (uint32_t)r * 128 + (uint32_t)((seg ^ (r & 7)) << 4);
        CP16(d + AT_Q, qhi + g);
    }
    CP_COMMIT();

    #define LOADKV(s, kt_) do { \
        _Pragma("unroll") \
        for (int it = 0; it < 2; it++) { \
            int idx = tid + it * 256, r = idx >> 3, sg = idx & 7; \
            size_t g = ((size_t)bh * 1024 + (kt_) * 64 + r) * 64 + sg * 8; \
            uint32_t d = sb + AT_STG + (uint32_t)(s) * KVSTG \
                       + (uint32_t)r * 128 + (uint32_t)((sg ^ (r & 7)) << 4); \
            CP16(d,        khi + g); \
            CP16(d + 8192, vhi + g); \
        } \
        CP_COMMIT(); \
    } while (0)

    LOADKV(0, 0);

    float o[8][4];
    #pragma unroll
    for (int j = 0; j < 8; j++)
        #pragma unroll
        for (int e = 0; e < 4; e++) o[j][e] = 0.f;
    float m0 = -INFINITY, m1 = -INFINITY, l0 = 0.f, l1 = 0.f;

    const int rA = w * 16 + (lane & 15);
    const int rBb = ((lane >> 4) << 3) + (lane & 7);
    const int c2 = (lane & 3) * 2;

    for (int kt = 0; kt < 16; kt++) {
        asm volatile("cp.async.wait_group 0;" ::: "memory");
        __syncthreads();
        if (kt < 15) LOADKV((kt + 1) & 1, kt + 1);
        const uint32_t kb = sb + AT_STG + (uint32_t)(kt & 1) * KVSTG;

        float s[8][4];
        #pragma unroll
        for (int j = 0; j < 8; j++)
            #pragma unroll
            for (int e = 0; e < 4; e++) s[j][e] = 0.f;

        #pragma unroll
        for (int ks = 0; ks < 4; ks++) {
            uint32_t ah[4];
            uint32_t aaddr = sb + AT_Q + (uint32_t)rA * 128
                           + (uint32_t)(((ks * 2 + (lane >> 4)) ^ (rA & 7)) << 4);
            LDSM4(ah, aaddr);
            #pragma unroll
            for (int np = 0; np < 4; np++) {
                int rB = np * 16 + rBb;
                uint32_t baddr = kb + (uint32_t)rB * 128
                               + (uint32_t)(((ks * 2 + ((lane >> 3) & 1)) ^ (rB & 7)) << 4);
                uint32_t bhF[4];
                LDSM4(bhF, baddr);
                #pragma unroll
                for (int hf = 0; hf < 2; hf++) {
                    int nt = np * 2 + hf, rb = hf * 2;
                    MMA16816(s[nt], ah, bhF[rb], bhF[rb + 1]);
                }
            }
        }

        float mx0 = -INFINITY, mx1 = -INFINITY;
        #pragma unroll
        for (int j = 0; j < 8; j++) {
            float2 mk = *(float2*)(smraw + AT_MASK + (size_t)(kt * 64 + j * 8 + c2) * 4);
            s[j][0] = s[j][0] * 0.125f + mk.x;
            s[j][1] = s[j][1] * 0.125f + mk.y;
            s[j][2] = s[j][2] * 0.125f + mk.x;
            s[j][3] = s[j][3] * 0.125f + mk.y;
            mx0 = fmaxf(mx0, fmaxf(s[j][0], s[j][1]));
            mx1 = fmaxf(mx1, fmaxf(s[j][2], s[j][3]));
        }
        #pragma unroll
        for (int off = 1; off < 4; off <<= 1) {
            mx0 = fmaxf(mx0, __shfl_xor_sync(0xffffffffu, mx0, off));
            mx1 = fmaxf(mx1, __shfl_xor_sync(0xffffffffu, mx1, off));
        }
        float mn0 = fmaxf(m0, mx0), mn1 = fmaxf(m1, mx1);
        float corr0 = __expf(m0 - mn0), corr1 = __expf(m1 - mn1);
        m0 = mn0; m1 = mn1;
        float sum0 = 0.f, sum1 = 0.f;
        #pragma unroll
        for (int j = 0; j < 8; j++) {
            s[j][0] = __expf(s[j][0] - m0);
            s[j][1] = __expf(s[j][1] - m0);
            s[j][2] = __expf(s[j][2] - m1);
            s[j][3] = __expf(s[j][3] - m1);
            sum0 += s[j][0] + s[j][1];
            sum1 += s[j][2] + s[j][3];
        }
        #pragma unroll
        for (int off = 1; off < 4; off <<= 1) {
            sum0 += __shfl_xor_sync(0xffffffffu, sum0, off);
            sum1 += __shfl_xor_sync(0xffffffffu, sum1, off);
        }
        l0 = l0 * corr0 + sum0;
        l1 = l1 * corr1 + sum1;
        #pragma unroll
        for (int j = 0; j < 8; j++) {
            o[j][0] *= corr0; o[j][1] *= corr0;
            o[j][2] *= corr1; o[j][3] *= corr1;
        }

        #pragma unroll
        for (int kg = 0; kg < 4; kg++) {
            uint32_t ph[4];
            ph[0] = pack2h(s[2*kg][0],   s[2*kg][1]);
            ph[1] = pack2h(s[2*kg][2],   s[2*kg][3]);
            ph[2] = pack2h(s[2*kg+1][0], s[2*kg+1][1]);
            ph[3] = pack2h(s[2*kg+1][2], s[2*kg+1][3]);
            int rV = kg * 16 + (lane & 15);
            #pragma unroll
            for (int np = 0; np < 4; np++) {
                uint32_t vaddr = kb + 8192 + (uint32_t)rV * 128
                               + (uint32_t)(((np * 2 + (lane >> 4)) ^ (rV & 7)) << 4);
                uint32_t vhF[4];
                LDSM4T(vhF, vaddr);
                #pragma unroll
                for (int hf = 0; hf < 2; hf++) {
                    int nt = np * 2 + hf, rb = hf * 2;
                    MMA16816(o[nt], ph, vhF[rb], vhF[rb + 1]);
                }
            }
        }
    }

    float i0 = 1.0f / l0, i1 = 1.0f / l1;
    size_t row0 = (size_t)b * 1024 + qt * 128 + w * 16 + (lane >> 2);
    #pragma unroll
    for (int j = 0; j < 8; j++) {
        int col = h * 64 + j * 8 + c2;
        *(uint32_t*)(chi + row0 * D_ + col)       = pack2h(o[j][0] * i0, o[j][1] * i0);
        *(uint32_t*)(chi + (row0 + 8) * D_ + col) = pack2h(o[j][2] * i1, o[j][3] * i1);
    }
    #undef LOADKV
}

// ---------------------------------------------------------------------------
// LayerNorm over last dim (1024).
// ---------------------------------------------------------------------------
__global__ __launch_bounds__(256) void lnorm(
    const float* __restrict__ X, const float* __restrict__ hsc,
    const float* __restrict__ hbi, float* __restrict__ out)
{
    int row = blockIdx.x;
    int c4 = threadIdx.x * 4;
    const float* x = X + (size_t)row * D_;
    float4 v = *(const float4*)(x + c4);
    float sum = v.x + v.y + v.z + v.w;
    float sq  = v.x*v.x + v.y*v.y + v.z*v.z + v.w*v.w;
    #pragma unroll
    for (int off = 16; off > 0; off >>= 1) {
        sum += __shfl_xor_sync(0xffffffffu, sum, off);
        sq  += __shfl_xor_sync(0xffffffffu, sq,  off);
    }
    __shared__ float rs[8], rq[8];
    int warp = threadIdx.x >> 5;
    if ((threadIdx.x & 31) == 0) { rs[warp] = sum; rq[warp] = sq; }
    __syncthreads();
    float tot = 0.f, totq = 0.f;
    #pragma unroll
    for (int wv = 0; wv < 8; wv++) { tot += rs[wv]; totq += rq[wv]; }
    float mu  = tot  * (1.0f / 1024.0f);
    float var = totq * (1.0f / 1024.0f) - mu * mu;
    float inv = rsqrtf(var + 1e-12f);
    float4 sc = *(const float4*)(hsc + c4);
    float4 bi = *(const float4*)(hbi + c4);
    float4 oo;
    oo.x = (v.x - mu) * inv * sc.x + bi.x;
    oo.y = (v.y - mu) * inv * sc.y + bi.y;
    oo.z = (v.z - mu) * inv * sc.z + bi.z;
    oo.w = (v.w - mu) * inv * sc.w + bi.w;
    *(float4*)&out[(size_t)row * D_ + c4] = oo;
}

// ---------------------------------------------------------------------------
extern "C" void kernel_launch(void* const* d_in, const int* in_sizes, int n_in,
                              void* d_out, int out_size)
{
    const float* hidden = (const float*)d_in[0];
    const float* mask   = (const float*)d_in[1];
    const float* phi    = (const float*)d_in[2];
    const float* mag    = (const float*)d_in[3];
    const float* Wq     = (const float*)d_in[4];
    const float* bq     = (const float*)d_in[5];
    const float* Wk     = (const float*)d_in[6];
    const float* bk     = (const float*)d_in[7];
    const float* Wv     = (const float*)d_in[8];
    const float* bv     = (const float*)d_in[9];
    const float* gamma  = (const float*)d_in[10];
    const float* Wo     = (const float*)d_in[11];
    const float* bo     = (const float*)d_in[12];
    const float* lns    = (const float*)d_in[13];
    const float* lnb    = (const float*)d_in[14];
    float* out = (float*)d_out;

    float *x;
    float4* prp;
    __half *ahi, *wthi, *qhi, *khi, *vhi;
    cudaGetSymbolAddress((void**)&x,    g_x);
    cudaGetSymbolAddress((void**)&prp,  g_prep);
    cudaGetSymbolAddress((void**)&ahi,  g_ahi);
    cudaGetSymbolAddress((void**)&wthi, g_wthi);
    cudaGetSymbolAddress((void**)&qhi,  g_qhi);
    cudaGetSymbolAddress((void**)&khi,  g_khi);
    cudaGetSymbolAddress((void**)&vhi,  g_vhi);

    cudaFuncSetAttribute(gemm_hmma, cudaFuncAttributeMaxDynamicSharedMemorySize, GEMM_DYN);
    cudaFuncSetAttribute(attn_hmma, cudaFuncAttributeMaxDynamicSharedMemorySize, ATTN_DYN);

    const int DD = D_ * D_;

    prep<<<(B_ * H_ * L_) / 256, 256>>>(phi, mag, gamma, prp);
    convA<<<(M_TOT * D_ / 4 + 255) / 256, 256>>>((const float4*)hidden, (uint2*)ahi, M_TOT * D_ / 4);
    convW4<<<dim3(32, 32, 4), 256>>>(Wq, Wk, Wv, Wo, wthi);

    // QKV fused (z: 0=Q rot, 1=K rot, 2=V), fp16 head-major outputs
    gemm_hmma<<<dim3(D_ / GN, M_TOT / GM, 3), 256, GEMM_DYN>>>(
        ahi, wthi, bq, bk, bv, prp, qhi, khi, vhi, nullptr, nullptr);

    attn_hmma<<<dim3(L_ / 128, B_ * H_), 256, ATTN_DYN>>>(
        qhi, khi, vhi, mask, ahi);

    // Wo projection + residual
    gemm_hmma<<<dim3(D_ / GN, M_TOT / GM, 1), 256, GEMM_DYN>>>(
        ahi, wthi + 3*DD, bo, bo, bo, prp,
        nullptr, nullptr, nullptr, hidden, x);

    lnorm<<<M_TOT, 256>>>(x, lns, lnb, out);
}

// round 10
// speedup vs baseline: 6.1957x; 1.0297x over previous
#include <cuda_runtime.h>
#include <cuda_fp16.h>
#include <math.h>
#include <stdint.h>

#define B_  4
#define L_  1024
#define D_  1024
#define H_  16
#define HD_ 64
#define M_TOT (B_*L_)   // 4096

// ---------------------------------------------------------------------------
// Scratch
// ---------------------------------------------------------------------------
__device__ float g_x[M_TOT * D_];
__device__ float4 g_prep[B_ * H_ * L_];     // (sc, sin, cos, 0) per (bh,l)
__device__ __half g_ahi[M_TOT * D_];        // activations / ctx fp16
__device__ __half g_wthi[4 * D_ * D_];      // W^T [N][K] fp16 (q,k,v,o)
__device__ __half g_qhi[M_TOT * D_];        // rotated Q fp16, head-major
__device__ __half g_khi[M_TOT * D_];        // rotated K fp16, head-major
__device__ __half g_vhi[M_TOT * D_];        // V fp16, head-major

// ---------------------------------------------------------------------------
// Helpers
// ---------------------------------------------------------------------------
__device__ __forceinline__ uint32_t smem_to_u32(const void* p) {
    uint32_t a;
    asm("{ .reg .u64 t; cvta.to.shared.u64 t, %1; cvt.u32.u64 %0, t; }"
        : "=r"(a) : "l"(p));
    return a;
}

#define CP16(dst, src) \
    asm volatile("cp.async.cg.shared.global [%0], [%1], 16;" \
                 :: "r"(dst), "l"(src) : "memory")
#define CP_COMMIT() asm volatile("cp.async.commit_group;" ::: "memory")
#define CP_WAIT(n)  asm volatile("cp.async.wait_group %0;" :: "n"(n) : "memory")

#define LDSM4(r, addr) \
    asm volatile("ldmatrix.sync.aligned.m8n8.x4.shared.b16 {%0,%1,%2,%3}, [%4];" \
                 : "=r"((r)[0]), "=r"((r)[1]), "=r"((r)[2]), "=r"((r)[3]) : "r"(addr))
#define LDSM4T(r, addr) \
    asm volatile("ldmatrix.sync.aligned.m8n8.x4.trans.shared.b16 {%0,%1,%2,%3}, [%4];" \
                 : "=r"((r)[0]), "=r"((r)[1]), "=r"((r)[2]), "=r"((r)[3]) : "r"(addr))

#define MMA16816(c, a, b0, b1) \
    asm volatile("mma.sync.aligned.m16n8k16.row.col.f32.f16.f16.f32 " \
                 "{%0,%1,%2,%3}, {%4,%5,%6,%7}, {%8,%9}, {%0,%1,%2,%3};" \
                 : "+f"((c)[0]), "+f"((c)[1]), "+f"((c)[2]), "+f"((c)[3]) \
                 : "r"((a)[0]), "r"((a)[1]), "r"((a)[2]), "r"((a)[3]), \
                   "r"(b0), "r"(b1))

// pack two floats -> fp16x2 (x in low half)
__device__ __forceinline__ uint32_t pack2h(float x, float y) {
    uint32_t d;
    asm("cvt.rn.f16x2.f32 %0, %1, %2;" : "=r"(d) : "f"(y), "f"(x));
    return d;
}

// ---------------------------------------------------------------------------
// prep: per (bh, l) compute (scale, sin(phi), cos(phi))
// ---------------------------------------------------------------------------
__global__ __launch_bounds__(256) void prep(
    const float* __restrict__ phi, const float* __restrict__ mag,
    const float* __restrict__ gamma, float4* __restrict__ out)
{
    int i = blockIdx.x * 256 + threadIdx.x;      // < 65536
    int h = (i >> 10) & 15;
    float sc = 1.0f + gamma[h] * tanhf(mag[i]);
    float s, c;
    sincosf(phi[i], &s, &c);
    out[i] = make_float4(sc, s, c, 0.f);
}

// ---------------------------------------------------------------------------
// convA: fp32 -> fp16
// ---------------------------------------------------------------------------
__global__ __launch_bounds__(256) void convA(
    const float4* __restrict__ x, uint2* __restrict__ hi, int n4)
{
    int i = blockIdx.x * 256 + threadIdx.x;
    if (i >= n4) return;
    float4 v = x[i];
    uint2 ho;
    ho.x = pack2h(v.x, v.y);
    ho.y = pack2h(v.z, v.w);
    hi[i] = ho;
}

// W[K,N] fp32 -> WT[N,K] fp16; grid.z selects matrix.
__global__ __launch_bounds__(256) void convW4(
    const float* __restrict__ Wq, const float* __restrict__ Wk,
    const float* __restrict__ Wv, const float* __restrict__ Wo,
    __half* __restrict__ hi)
{
    __shared__ float t[32][33];
    const int z = blockIdx.z;
    const float* W = (z == 0) ? Wq : (z == 1) ? Wk : (z == 2) ? Wv : Wo;
    __half* hz = hi + (size_t)z * D_ * D_;
    int n0 = blockIdx.x * 32, k0 = blockIdx.y * 32;
    int tx = threadIdx.x & 31, ty = threadIdx.x >> 5;
    #pragma unroll
    for (int j = 0; j < 4; j++)
        t[ty + j*8][tx] = W[(size_t)(k0 + ty + j*8) * D_ + n0 + tx];
    __syncthreads();
    #pragma unroll
    for (int j = 0; j < 4; j++)
        hz[(size_t)(n0 + ty + j*8) * D_ + k0 + tx] = __float2half_rn(t[tx][ty + j*8]);
}

// ---------------------------------------------------------------------------
// HMMA fp16 1-term GEMM, 128x256 CTA tile, 256 threads = 8 warps (64x64 tiles).
// 4-stage cp.async pipeline, one __syncthreads per chunk.
// Modes:
//  res == nullptr, z=0/1: Q/K -> bias+scale+rotate -> fp16 head-major
//  res == nullptr, z=2:   V  -> bias -> fp16 head-major
//  res != nullptr:        Wo -> bias + residual -> fp32 row-major
// ---------------------------------------------------------------------------
#define GM 128
#define GN 256
#define KC 64
#define OFF_BHI  16384
#define STAGE    49152
#define NSTG     4
#define GEMM_DYN (NSTG*STAGE)   // 196608

__global__ __launch_bounds__(256, 1) void gemm_hmma(
    const __half* __restrict__ Ahi,
    const __half* __restrict__ WThi,
    const float* __restrict__ bias0, const float* __restrict__ bias1,
    const float* __restrict__ bias2,
    const float4* __restrict__ prp,
    __half* __restrict__ qh, __half* __restrict__ kh,
    __half* __restrict__ vh,
    const float* __restrict__ res, float* __restrict__ xout)
{
    extern __shared__ char smraw[];
    const uint32_t sbase = smem_to_u32(smraw);
    const int tid  = threadIdx.x;
    const int lane = tid & 31, wid = tid >> 5;
    const int wm = wid >> 2, wn = wid & 3;
    const int bm = blockIdx.y * GM, bn = blockIdx.x * GN;
    const int z  = blockIdx.z;

    const __half* Bh = WThi + (size_t)z * D_ * D_;
    const float* bias = (z == 0) ? bias0 : (z == 1) ? bias1 : bias2;

    const int rr  = tid >> 3;
    const int seg = tid & 7;

    #define LOAD_STAGE(s, kc) do { \
        uint32_t sb_ = sbase + (uint32_t)(s) * STAGE; \
        _Pragma("unroll") \
        for (int h4 = 0; h4 < 4; h4++) { \
            int r_ = rr + h4 * 32; \
            uint32_t sw_ = (uint32_t)r_ * 128 + (uint32_t)((seg ^ (r_ & 7)) << 4); \
            size_t g_ = (size_t)(bm + r_) * D_ + (kc) + seg * 8; \
            CP16(sb_ + sw_, Ahi + g_); \
        } \
        _Pragma("unroll") \
        for (int h8 = 0; h8 < 8; h8++) { \
            int r_ = rr + h8 * 32; \
            uint32_t sw_ = (uint32_t)r_ * 128 + (uint32_t)((seg ^ (r_ & 7)) << 4); \
            size_t g_ = (size_t)(bn + r_) * D_ + (kc) + seg * 8; \
            CP16(sb_ + OFF_BHI + sw_, Bh + g_); \
        } \
        CP_COMMIT(); \
    } while (0)

    float c[4][8][4];
    #pragma unroll
    for (int mi = 0; mi < 4; mi++)
        #pragma unroll
        for (int ni = 0; ni < 8; ni++)
            #pragma unroll
            for (int e = 0; e < 4; e++) c[mi][ni][e] = 0.f;

    LOAD_STAGE(0, 0);
    LOAD_STAGE(1, KC);
    LOAD_STAGE(2, 2 * KC);

    const int rAb = wm * 64 + (lane & 15);
    const int rBb = wn * 64 + ((lane >> 4) << 3) + (lane & 7);
    const int sgA = lane >> 4;
    const int sgB = (lane >> 3) & 1;

    for (int ch = 0; ch < 16; ch++) {
        // wait for stage ch: number of younger committed groups after it
        if (ch <= 13)      CP_WAIT(2);
        else if (ch == 14) CP_WAIT(1);
        else               CP_WAIT(0);
        __syncthreads();
        if (ch < 13) LOAD_STAGE((ch + 3) & 3, (ch + 3) * KC);

        const uint32_t sb = sbase + (uint32_t)(ch & 3) * STAGE;
        #pragma unroll
        for (int ks = 0; ks < 4; ks++) {
            uint32_t ah[4][4];
            #pragma unroll
            for (int mi = 0; mi < 4; mi++) {
                int rA = rAb + mi * 16;
                uint32_t addr = sb + (uint32_t)rA * 128
                              + (uint32_t)(((ks * 2 + sgA) ^ (rA & 7)) << 4);
                LDSM4(ah[mi], addr);
            }
            #pragma unroll
            for (int np = 0; np < 4; np++) {
                int rB = rBb + np * 16;
                uint32_t addr = sb + OFF_BHI + (uint32_t)rB * 128
                              + (uint32_t)(((ks * 2 + sgB) ^ (rB & 7)) << 4);
                uint32_t bh[4];
                LDSM4(bh, addr);
                #pragma unroll
                for (int hf = 0; hf < 2; hf++) {
                    int ni = np * 2 + hf, rb = hf * 2;
                    #pragma unroll
                    for (int mi = 0; mi < 4; mi++)
                        MMA16816(c[mi][ni], ah[mi], bh[rb], bh[rb + 1]);
                }
            }
        }
    }

    // ---- epilogue ----
    const int g = lane >> 2, tig = lane & 3;
    if (res) {
        // Wo projection + bias + residual -> fp32 row-major
        #pragma unroll
        for (int mi = 0; mi < 4; mi++) {
            int row0 = bm + wm * 64 + mi * 16 + g;
            #pragma unroll
            for (int ni = 0; ni < 8; ni++) {
                int col = bn + wn * 64 + ni * 8 + tig * 2;
                float2 bv = *(const float2*)(bias + col);
                float2 r0 = *(const float2*)(res + (size_t)row0 * D_ + col);
                float2 r1 = *(const float2*)(res + (size_t)(row0 + 8) * D_ + col);
                *(float2*)(xout + (size_t)row0 * D_ + col) =
                    make_float2(c[mi][ni][0] + bv.x + r0.x, c[mi][ni][1] + bv.y + r0.y);
                *(float2*)(xout + (size_t)(row0 + 8) * D_ + col) =
                    make_float2(c[mi][ni][2] + bv.x + r1.x, c[mi][ni][3] + bv.y + r1.y);
            }
        }
    } else if (z == 2) {
        // V: bias -> fp16 head-major
        #pragma unroll
        for (int mi = 0; mi < 4; mi++) {
            int row0 = bm + wm * 64 + mi * 16 + g;
            int bidx = row0 >> 10, l0 = row0 & 1023;
            #pragma unroll
            for (int ni = 0; ni < 8; ni++) {
                int col = bn + wn * 64 + ni * 8 + tig * 2;
                float2 bv = *(const float2*)(bias + col);
                size_t o0 = (((size_t)bidx * 16 + (col >> 6)) * 1024 + l0) * 64 + (col & 63);
                size_t o1 = o0 + 8 * 64;
                *(uint32_t*)(vh + o0) = pack2h(c[mi][ni][0] + bv.x, c[mi][ni][1] + bv.y);
                *(uint32_t*)(vh + o1) = pack2h(c[mi][ni][2] + bv.x, c[mi][ni][3] + bv.y);
            }
        }
    } else {
        // Q/K: bias + scale + rotate -> fp16 head-major
        __half* oh = (z == 0) ? qh : kh;
        const int hh = (bn + wn * 64) >> 6;
        #pragma unroll
        for (int mi = 0; mi < 4; mi++) {
            int row0 = bm + wm * 64 + mi * 16 + g;
            int bidx = row0 >> 10, l0 = row0 & 1023;
            int pidx = (bidx * 16 + hh) * 1024 + l0;
            float4 p0 = prp[pidx];
            float4 p1 = prp[pidx + 8];
            size_t ob = ((size_t)(bidx * 16 + hh) * 1024 + l0) * 64;
            #pragma unroll
            for (int ni = 0; ni < 4; ni++) {
                int d = ni * 8 + tig * 2;
                float2 b1 = *(const float2*)(bias + bn + wn * 64 + d);
                float2 b2 = *(const float2*)(bias + bn + wn * 64 + d + 32);
                // row0
                {
                    float x0 = (c[mi][ni][0]   + b1.x) * p0.x;
                    float x1 = (c[mi][ni][1]   + b1.y) * p0.x;
                    float y0 = (c[mi][ni+4][0] + b2.x) * p0.x;
                    float y1 = (c[mi][ni+4][1] + b2.y) * p0.x;
                    *(uint32_t*)(oh + ob + d) =
                        pack2h(x0 * p0.z - y0 * p0.y, x1 * p0.z - y1 * p0.y);
                    *(uint32_t*)(oh + ob + d + 32) =
                        pack2h(y0 * p0.z + x0 * p0.y, y1 * p0.z + x1 * p0.y);
                }
                // row0 + 8
                {
                    float x0 = (c[mi][ni][2]   + b1.x) * p1.x;
                    float x1 = (c[mi][ni][3]   + b1.y) * p1.x;
                    float y0 = (c[mi][ni+4][2] + b2.x) * p1.x;
                    float y1 = (c[mi][ni+4][3] + b2.y) * p1.x;
                    *(uint32_t*)(oh + ob + 512 + d) =
                        pack2h(x0 * p1.z - y0 * p1.y, x1 * p1.z - y1 * p1.y);
                    *(uint32_t*)(oh + ob + 512 + d + 32) =
                        pack2h(y0 * p1.z + x0 * p1.y, y1 * p1.z + x1 * p1.y);
                }
            }
        }
    }
    #undef LOAD_STAGE
}

// ---------------------------------------------------------------------------
// HMMA fp16 flash attention, 1-term, 3-stage KV pipeline.
// ---------------------------------------------------------------------------
#define AT_Q   0
#define AT_STG 16384
#define KVSTG  16384                  // K @0, V @8192
#define AT_MASK (AT_STG + 3*KVSTG)    // 65536
#define ATTN_DYN (AT_MASK + 4096)     // 69632

__global__ __launch_bounds__(256, 2) void attn_hmma(
    const __half* __restrict__ qhi,
    const __half* __restrict__ khi,
    const __half* __restrict__ vhi,
    const float* __restrict__ mask,
    __half* __restrict__ chi)
{
    extern __shared__ char smraw[];
    const uint32_t sb = smem_to_u32(smraw);
    const int tid = threadIdx.x, lane = tid & 31, w = tid >> 5;
    const int qt = blockIdx.x, bh = blockIdx.y;
    const int b = bh >> 4, h = bh & 15;

    CP16(sb + AT_MASK + tid * 16, mask + b * 1024 + tid * 4);
    #pragma unroll
    for (int it = 0; it < 4; it++) {
        int idx = tid + it * 256, r = idx >> 3, seg = idx & 7;
        size_t g = ((size_t)bh * 1024 + qt * 128 + r) * 64 + seg * 8;
        uint32_t d = sb + (uint32_t)r * 128 + (uint32_t)((seg ^ (r & 7)) << 4);
        CP16(d + AT_Q, qhi + g);
    }
    CP_COMMIT();

    #define LOADKV(s, kt_) do { \
        _Pragma("unroll") \
        for (int it = 0; it < 2; it++) { \
            int idx = tid + it * 256, r = idx >> 3, sg = idx & 7; \
            size_t g = ((size_t)bh * 1024 + (kt_) * 64 + r) * 64 + sg * 8; \
            uint32_t d = sb + AT_STG + (uint32_t)(s) * KVSTG \
                       + (uint32_t)r * 128 + (uint32_t)((sg ^ (r & 7)) << 4); \
            CP16(d,        khi + g); \
            CP16(d + 8192, vhi + g); \
        } \
        CP_COMMIT(); \
    } while (0)

    LOADKV(0, 0);
    LOADKV(1, 1);

    float o[8][4];
    #pragma unroll
    for (int j = 0; j < 8; j++)
        #pragma unroll
        for (int e = 0; e < 4; e++) o[j][e] = 0.f;
    float m0 = -INFINITY, m1 = -INFINITY, l0 = 0.f, l1 = 0.f;

    const int rA = w * 16 + (lane & 15);
    const int rBb = ((lane >> 4) << 3) + (lane & 7);
    const int c2 = (lane & 3) * 2;

    // stage indices mod 3
    int cur = 0;
    for (int kt = 0; kt < 16; kt++) {
        if (kt < 15) CP_WAIT(1);
        else         CP_WAIT(0);
        __syncthreads();
        if (kt < 14) {
            int nxt = cur + 2;
            if (nxt >= 3) nxt -= 3;
            LOADKV(nxt, kt + 2);
        }
        const uint32_t kb = sb + AT_STG + (uint32_t)cur * KVSTG;

        float s[8][4];
        #pragma unroll
        for (int j = 0; j < 8; j++)
            #pragma unroll
            for (int e = 0; e < 4; e++) s[j][e] = 0.f;

        #pragma unroll
        for (int ks = 0; ks < 4; ks++) {
            uint32_t ah[4];
            uint32_t aaddr = sb + AT_Q + (uint32_t)rA * 128
                           + (uint32_t)(((ks * 2 + (lane >> 4)) ^ (rA & 7)) << 4);
            LDSM4(ah, aaddr);
            #pragma unroll
            for (int np = 0; np < 4; np++) {
                int rB = np * 16 + rBb;
                uint32_t baddr = kb + (uint32_t)rB * 128
                               + (uint32_t)(((ks * 2 + ((lane >> 3) & 1)) ^ (rB & 7)) << 4);
                uint32_t bhF[4];
                LDSM4(bhF, baddr);
                #pragma unroll
                for (int hf = 0; hf < 2; hf++) {
                    int nt = np * 2 + hf, rb = hf * 2;
                    MMA16816(s[nt], ah, bhF[rb], bhF[rb + 1]);
                }
            }
        }

        float mx0 = -INFINITY, mx1 = -INFINITY;
        #pragma unroll
        for (int j = 0; j < 8; j++) {
            float2 mk = *(float2*)(smraw + AT_MASK + (size_t)(kt * 64 + j * 8 + c2) * 4);
            s[j][0] = s[j][0] * 0.125f + mk.x;
            s[j][1] = s[j][1] * 0.125f + mk.y;
            s[j][2] = s[j][2] * 0.125f + mk.x;
            s[j][3] = s[j][3] * 0.125f + mk.y;
            mx0 = fmaxf(mx0, fmaxf(s[j][0], s[j][1]));
            mx1 = fmaxf(mx1, fmaxf(s[j][2], s[j][3]));
        }
        #pragma unroll
        for (int off = 1; off < 4; off <<= 1) {
            mx0 = fmaxf(mx0, __shfl_xor_sync(0xffffffffu, mx0, off));
            mx1 = fmaxf(mx1, __shfl_xor_sync(0xffffffffu, mx1, off));
        }
        float mn0 = fmaxf(m0, mx0), mn1 = fmaxf(m1, mx1);
        float corr0 = __expf(m0 - mn0), corr1 = __expf(m1 - mn1);
        m0 = mn0; m1 = mn1;
        float sum0 = 0.f, sum1 = 0.f;
        #pragma unroll
        for (int j = 0; j < 8; j++) {
            s[j][0] = __expf(s[j][0] - m0);
            s[j][1] = __expf(s[j][1] - m0);
            s[j][2] = __expf(s[j][2] - m1);
            s[j][3] = __expf(s[j][3] - m1);
            sum0 += s[j][0] + s[j][1];
            sum1 += s[j][2] + s[j][3];
        }
        #pragma unroll
        for (int off = 1; off < 4; off <<= 1) {
            sum0 += __shfl_xor_sync(0xffffffffu, sum0, off);
            sum1 += __shfl_xor_sync(0xffffffffu, sum1, off);
        }
        l0 = l0 * corr0 + sum0;
        l1 = l1 * corr1 + sum1;
        #pragma unroll
        for (int j = 0; j < 8; j++) {
            o[j][0] *= corr0; o[j][1] *= corr0;
            o[j][2] *= corr1; o[j][3] *= corr1;
        }

        #pragma unroll
        for (int kg = 0; kg < 4; kg++) {
            uint32_t ph[4];
            ph[0] = pack2h(s[2*kg][0],   s[2*kg][1]);
            ph[1] = pack2h(s[2*kg][2],   s[2*kg][3]);
            ph[2] = pack2h(s[2*kg+1][0], s[2*kg+1][1]);
            ph[3] = pack2h(s[2*kg+1][2], s[2*kg+1][3]);
            int rV = kg * 16 + (lane & 15);
            #pragma unroll
            for (int np = 0; np < 4; np++) {
                uint32_t vaddr = kb + 8192 + (uint32_t)rV * 128
                               + (uint32_t)(((np * 2 + (lane >> 4)) ^ (rV & 7)) << 4);
                uint32_t vhF[4];
                LDSM4T(vhF, vaddr);
                #pragma unroll
                for (int hf = 0; hf < 2; hf++) {
                    int nt = np * 2 + hf, rb = hf * 2;
                    MMA16816(o[nt], ph, vhF[rb], vhF[rb + 1]);
                }
            }
        }

        cur++;
        if (cur == 3) cur = 0;
    }

    float i0 = 1.0f / l0, i1 = 1.0f / l1;
    size_t row0 = (size_t)b * 1024 + qt * 128 + w * 16 + (lane >> 2);
    #pragma unroll
    for (int j = 0; j < 8; j++) {
        int col = h * 64 + j * 8 + c2;
        *(uint32_t*)(chi + row0 * D_ + col)       = pack2h(o[j][0] * i0, o[j][1] * i0);
        *(uint32_t*)(chi + (row0 + 8) * D_ + col) = pack2h(o[j][2] * i1, o[j][3] * i1);
    }
    #undef LOADKV
}

// ---------------------------------------------------------------------------
// LayerNorm over last dim (1024).
// ---------------------------------------------------------------------------
__global__ __launch_bounds__(256) void lnorm(
    const float* __restrict__ X, const float* __restrict__ hsc,
    const float* __restrict__ hbi, float* __restrict__ out)
{
    int row = blockIdx.x;
    int c4 = threadIdx.x * 4;
    const float* x = X + (size_t)row * D_;
    float4 v = *(const float4*)(x + c4);
    float sum = v.x + v.y + v.z + v.w;
    float sq  = v.x*v.x + v.y*v.y + v.z*v.z + v.w*v.w;
    #pragma unroll
    for (int off = 16; off > 0; off >>= 1) {
        sum += __shfl_xor_sync(0xffffffffu, sum, off);
        sq  += __shfl_xor_sync(0xffffffffu, sq,  off);
    }
    __shared__ float rs[8], rq[8];
    int warp = threadIdx.x >> 5;
    if ((threadIdx.x & 31) == 0) { rs[warp] = sum; rq[warp] = sq; }
    __syncthreads();
    float tot = 0.f, totq = 0.f;
    #pragma unroll
    for (int wv = 0; wv < 8; wv++) { tot += rs[wv]; totq += rq[wv]; }
    float mu  = tot  * (1.0f / 1024.0f);
    float var = totq * (1.0f / 1024.0f) - mu * mu;
    float inv = rsqrtf(var + 1e-12f);
    float4 sc = *(const float4*)(hsc + c4);
    float4 bi = *(const float4*)(hbi + c4);
    float4 oo;
    oo.x = (v.x - mu) * inv * sc.x + bi.x;
    oo.y = (v.y - mu) * inv * sc.y + bi.y;
    oo.z = (v.z - mu) * inv * sc.z + bi.z;
    oo.w = (v.w - mu) * inv * sc.w + bi.w;
    *(float4*)&out[(size_t)row * D_ + c4] = oo;
}

// ---------------------------------------------------------------------------
extern "C" void kernel_launch(void* const* d_in, const int* in_sizes, int n_in,
                              void* d_out, int out_size)
{
    const float* hidden = (const float*)d_in[0];
    const float* mask   = (const float*)d_in[1];
    const float* phi    = (const float*)d_in[2];
    const float* mag    = (const float*)d_in[3];
    const float* Wq     = (const float*)d_in[4];
    const float* bq     = (const float*)d_in[5];
    const float* Wk     = (const float*)d_in[6];
    const float* bk     = (const float*)d_in[7];
    const float* Wv     = (const float*)d_in[8];
    const float* bv     = (const float*)d_in[9];
    const float* gamma  = (const float*)d_in[10];
    const float* Wo     = (const float*)d_in[11];
    const float* bo     = (const float*)d_in[12];
    const float* lns    = (const float*)d_in[13];
    const float* lnb    = (const float*)d_in[14];
    float* out = (float*)d_out;

    float *x;
    float4* prp;
    __half *ahi, *wthi, *qhi, *khi, *vhi;
    cudaGetSymbolAddress((void**)&x,    g_x);
    cudaGetSymbolAddress((void**)&prp,  g_prep);
    cudaGetSymbolAddress((void**)&ahi,  g_ahi);
    cudaGetSymbolAddress((void**)&wthi, g_wthi);
    cudaGetSymbolAddress((void**)&qhi,  g_qhi);
    cudaGetSymbolAddress((void**)&khi,  g_khi);
    cudaGetSymbolAddress((void**)&vhi,  g_vhi);

    cudaFuncSetAttribute(gemm_hmma, cudaFuncAttributeMaxDynamicSharedMemorySize, GEMM_DYN);
    cudaFuncSetAttribute(attn_hmma, cudaFuncAttributeMaxDynamicSharedMemorySize, ATTN_DYN);

    const int DD = D_ * D_;

    prep<<<(B_ * H_ * L_) / 256, 256>>>(phi, mag, gamma, prp);
    convA<<<(M_TOT * D_ / 4 + 255) / 256, 256>>>((const float4*)hidden, (uint2*)ahi, M_TOT * D_ / 4);
    convW4<<<dim3(32, 32, 4), 256>>>(Wq, Wk, Wv, Wo, wthi);

    // QKV fused (z: 0=Q rot, 1=K rot, 2=V), fp16 head-major outputs
    gemm_hmma<<<dim3(D_ / GN, M_TOT / GM, 3), 256, GEMM_DYN>>>(
        ahi, wthi, bq, bk, bv, prp, qhi, khi, vhi, nullptr, nullptr);

    attn_hmma<<<dim3(L_ / 128, B_ * H_), 256, ATTN_DYN>>>(
        qhi, khi, vhi, mask, ahi);

    // Wo projection + residual
    gemm_hmma<<<dim3(D_ / GN, M_TOT / GM, 1), 256, GEMM_DYN>>>(
        ahi, wthi + 3*DD, bo, bo, bo, prp,
        nullptr, nullptr, nullptr, hidden, x);

    lnorm<<<M_TOT, 256>>>(x, lns, lnb, out);
}

// round 11
// speedup vs baseline: 6.2169x; 1.0034x over previous
#include <cuda_runtime.h>
#include <cuda_fp16.h>
#include <math.h>
#include <stdint.h>

#define B_  4
#define L_  1024
#define D_  1024
#define H_  16
#define HD_ 64
#define M_TOT (B_*L_)   // 4096

// ---------------------------------------------------------------------------
// Scratch
// ---------------------------------------------------------------------------
__device__ float g_x[M_TOT * D_];
__device__ float4 g_prep[B_ * H_ * L_];     // (sc, sin, cos, 0) per (bh,l)
__device__ __half g_ahi[M_TOT * D_];        // activations / ctx fp16
__device__ __half g_wthi[4 * D_ * D_];      // W^T [N][K] fp16 (q,k,v,o)
__device__ __half g_qhi[M_TOT * D_];        // rotated Q fp16, head-major
__device__ __half g_khi[M_TOT * D_];        // rotated K fp16, head-major
__device__ __half g_vhi[M_TOT * D_];        // V fp16, head-major

// ---------------------------------------------------------------------------
// Helpers
// ---------------------------------------------------------------------------
__device__ __forceinline__ uint32_t smem_to_u32(const void* p) {
    uint32_t a;
    asm("{ .reg .u64 t; cvta.to.shared.u64 t, %1; cvt.u32.u64 %0, t; }"
        : "=r"(a) : "l"(p));
    return a;
}

#define CP16(dst, src) \
    asm volatile("cp.async.cg.shared.global [%0], [%1], 16;" \
                 :: "r"(dst), "l"(src) : "memory")
#define CP_COMMIT() asm volatile("cp.async.commit_group;" ::: "memory")
#define CP_WAIT(n)  asm volatile("cp.async.wait_group %0;" :: "n"(n) : "memory")

#define LDSM4(r, addr) \
    asm volatile("ldmatrix.sync.aligned.m8n8.x4.shared.b16 {%0,%1,%2,%3}, [%4];" \
                 : "=r"((r)[0]), "=r"((r)[1]), "=r"((r)[2]), "=r"((r)[3]) : "r"(addr))
#define LDSM4T(r, addr) \
    asm volatile("ldmatrix.sync.aligned.m8n8.x4.trans.shared.b16 {%0,%1,%2,%3}, [%4];" \
                 : "=r"((r)[0]), "=r"((r)[1]), "=r"((r)[2]), "=r"((r)[3]) : "r"(addr))

#define MMA16816(c, a, b0, b1) \
    asm volatile("mma.sync.aligned.m16n8k16.row.col.f32.f16.f16.f32 " \
                 "{%0,%1,%2,%3}, {%4,%5,%6,%7}, {%8,%9}, {%0,%1,%2,%3};" \
                 : "+f"((c)[0]), "+f"((c)[1]), "+f"((c)[2]), "+f"((c)[3]) \
                 : "r"((a)[0]), "r"((a)[1]), "r"((a)[2]), "r"((a)[3]), \
                   "r"(b0), "r"(b1))

// pack two floats -> fp16x2 (x in low half)
__device__ __forceinline__ uint32_t pack2h(float x, float y) {
    uint32_t d;
    asm("cvt.rn.f16x2.f32 %0, %1, %2;" : "=r"(d) : "f"(y), "f"(x));
    return d;
}

// ---------------------------------------------------------------------------
// prep: per (bh, l) compute (scale, sin(phi), cos(phi))
// ---------------------------------------------------------------------------
__global__ __launch_bounds__(256) void prep(
    const float* __restrict__ phi, const float* __restrict__ mag,
    const float* __restrict__ gamma, float4* __restrict__ out)
{
    int i = blockIdx.x * 256 + threadIdx.x;      // < 65536
    int h = (i >> 10) & 15;
    float sc = 1.0f + gamma[h] * tanhf(mag[i]);
    float s, c;
    sincosf(phi[i], &s, &c);
    out[i] = make_float4(sc, s, c, 0.f);
}

// ---------------------------------------------------------------------------
// convA: fp32 -> fp16
// ---------------------------------------------------------------------------
__global__ __launch_bounds__(256) void convA(
    const float4* __restrict__ x, uint2* __restrict__ hi, int n4)
{
    int i = blockIdx.x * 256 + threadIdx.x;
    if (i >= n4) return;
    float4 v = x[i];
    uint2 ho;
    ho.x = pack2h(v.x, v.y);
    ho.y = pack2h(v.z, v.w);
    hi[i] = ho;
}

// W[K,N] fp32 -> WT[N,K] fp16; grid.z selects matrix.
__global__ __launch_bounds__(256) void convW4(
    const float* __restrict__ Wq, const float* __restrict__ Wk,
    const float* __restrict__ Wv, const float* __restrict__ Wo,
    __half* __restrict__ hi)
{
    __shared__ float t[32][33];
    const int z = blockIdx.z;
    const float* W = (z == 0) ? Wq : (z == 1) ? Wk : (z == 2) ? Wv : Wo;
    __half* hz = hi + (size_t)z * D_ * D_;
    int n0 = blockIdx.x * 32, k0 = blockIdx.y * 32;
    int tx = threadIdx.x & 31, ty = threadIdx.x >> 5;
    #pragma unroll
    for (int j = 0; j < 4; j++)
        t[ty + j*8][tx] = W[(size_t)(k0 + ty + j*8) * D_ + n0 + tx];
    __syncthreads();
    #pragma unroll
    for (int j = 0; j < 4; j++)
        hz[(size_t)(n0 + ty + j*8) * D_ + k0 + tx] = __float2half_rn(t[tx][ty + j*8]);
}

// ---------------------------------------------------------------------------
// HMMA fp16 GEMM, 128x128 CTA tile, 256 threads = 8 warps (32x64 tiles),
// 3-stage cp.async pipeline, 2 CTAs/SM for tensor-pipe overlap.
// Modes:
//  res == nullptr, z=0/1: Q/K -> bias+scale+rotate -> fp16 head-major
//  res == nullptr, z=2:   V  -> bias -> fp16 head-major
//  res != nullptr:        Wo -> bias + residual -> fp32 row-major
// ---------------------------------------------------------------------------
#define GM 128
#define GN 128
#define KC 64
#define OFF_BHI  16384
#define STAGE    32768
#define NSTG     3
#define GEMM_DYN (NSTG*STAGE)   // 98304

__global__ __launch_bounds__(256, 2) void gemm_hmma(
    const __half* __restrict__ Ahi,
    const __half* __restrict__ WThi,
    const float* __restrict__ bias0, const float* __restrict__ bias1,
    const float* __restrict__ bias2,
    const float4* __restrict__ prp,
    __half* __restrict__ qh, __half* __restrict__ kh,
    __half* __restrict__ vh,
    const float* __restrict__ res, float* __restrict__ xout)
{
    extern __shared__ char smraw[];
    const uint32_t sbase = smem_to_u32(smraw);
    const int tid  = threadIdx.x;
    const int lane = tid & 31, wid = tid >> 5;
    const int wm = wid >> 1, wn = wid & 1;    // 4 x 2 warps of 32x64
    const int bm = blockIdx.y * GM, bn = blockIdx.x * GN;
    const int z  = blockIdx.z;

    const __half* Bh = WThi + (size_t)z * D_ * D_;
    const float* bias = (z == 0) ? bias0 : (z == 1) ? bias1 : bias2;

    const int rr  = tid >> 3;     // 0..31
    const int seg = tid & 7;

    #define LOAD_STAGE(s, kc) do { \
        uint32_t sb_ = sbase + (uint32_t)(s) * STAGE; \
        _Pragma("unroll") \
        for (int h4 = 0; h4 < 4; h4++) { \
            int r_ = rr + h4 * 32; \
            uint32_t sw_ = (uint32_t)r_ * 128 + (uint32_t)((seg ^ (r_ & 7)) << 4); \
            size_t ga_ = (size_t)(bm + r_) * D_ + (kc) + seg * 8; \
            size_t gb_ = (size_t)(bn + r_) * D_ + (kc) + seg * 8; \
            CP16(sb_ + sw_,           Ahi + ga_); \
            CP16(sb_ + OFF_BHI + sw_, Bh + gb_); \
        } \
        CP_COMMIT(); \
    } while (0)

    float c[2][8][4];
    #pragma unroll
    for (int mi = 0; mi < 2; mi++)
        #pragma unroll
        for (int ni = 0; ni < 8; ni++)
            #pragma unroll
            for (int e = 0; e < 4; e++) c[mi][ni][e] = 0.f;

    LOAD_STAGE(0, 0);
    LOAD_STAGE(1, KC);

    const int rAb = wm * 32 + (lane & 15);
    const int rBb = wn * 64 + ((lane >> 4) << 3) + (lane & 7);
    const int sgA = lane >> 4;
    const int sgB = (lane >> 3) & 1;

    int cur = 0;
    for (int ch = 0; ch < 16; ch++) {
        if (ch < 15) CP_WAIT(1);
        else         CP_WAIT(0);
        __syncthreads();
        if (ch < 14) {
            int nxt = cur + 2;
            if (nxt >= 3) nxt -= 3;
            LOAD_STAGE(nxt, (ch + 2) * KC);
        }

        const uint32_t sb = sbase + (uint32_t)cur * STAGE;
        #pragma unroll
        for (int ks = 0; ks < 4; ks++) {
            uint32_t ah[2][4];
            #pragma unroll
            for (int mi = 0; mi < 2; mi++) {
                int rA = rAb + mi * 16;
                uint32_t addr = sb + (uint32_t)rA * 128
                              + (uint32_t)(((ks * 2 + sgA) ^ (rA & 7)) << 4);
                LDSM4(ah[mi], addr);
            }
            #pragma unroll
            for (int np = 0; np < 4; np++) {
                int rB = rBb + np * 16;
                uint32_t addr = sb + OFF_BHI + (uint32_t)rB * 128
                              + (uint32_t)(((ks * 2 + sgB) ^ (rB & 7)) << 4);
                uint32_t bh[4];
                LDSM4(bh, addr);
                #pragma unroll
                for (int hf = 0; hf < 2; hf++) {
                    int ni = np * 2 + hf, rb = hf * 2;
                    #pragma unroll
                    for (int mi = 0; mi < 2; mi++)
                        MMA16816(c[mi][ni], ah[mi], bh[rb], bh[rb + 1]);
                }
            }
        }
        cur++;
        if (cur == 3) cur = 0;
    }

    // ---- epilogue ----
    const int g = lane >> 2, tig = lane & 3;
    if (res) {
        // Wo projection + bias + residual -> fp32 row-major
        #pragma unroll
        for (int mi = 0; mi < 2; mi++) {
            int row0 = bm + wm * 32 + mi * 16 + g;
            #pragma unroll
            for (int ni = 0; ni < 8; ni++) {
                int col = bn + wn * 64 + ni * 8 + tig * 2;
                float2 bv = *(const float2*)(bias + col);
                float2 r0 = *(const float2*)(res + (size_t)row0 * D_ + col);
                float2 r1 = *(const float2*)(res + (size_t)(row0 + 8) * D_ + col);
                *(float2*)(xout + (size_t)row0 * D_ + col) =
                    make_float2(c[mi][ni][0] + bv.x + r0.x, c[mi][ni][1] + bv.y + r0.y);
                *(float2*)(xout + (size_t)(row0 + 8) * D_ + col) =
                    make_float2(c[mi][ni][2] + bv.x + r1.x, c[mi][ni][3] + bv.y + r1.y);
            }
        }
    } else if (z == 2) {
        // V: bias -> fp16 head-major
        #pragma unroll
        for (int mi = 0; mi < 2; mi++) {
            int row0 = bm + wm * 32 + mi * 16 + g;
            int bidx = row0 >> 10, l0 = row0 & 1023;
            #pragma unroll
            for (int ni = 0; ni < 8; ni++) {
                int col = bn + wn * 64 + ni * 8 + tig * 2;
                float2 bv = *(const float2*)(bias + col);
                size_t o0 = (((size_t)bidx * 16 + (col >> 6)) * 1024 + l0) * 64 + (col & 63);
                size_t o1 = o0 + 8 * 64;
                *(uint32_t*)(vh + o0) = pack2h(c[mi][ni][0] + bv.x, c[mi][ni][1] + bv.y);
                *(uint32_t*)(vh + o1) = pack2h(c[mi][ni][2] + bv.x, c[mi][ni][3] + bv.y);
            }
        }
    } else {
        // Q/K: bias + scale + rotate -> fp16 head-major
        __half* oh = (z == 0) ? qh : kh;
        const int hh = (bn + wn * 64) >> 6;
        #pragma unroll
        for (int mi = 0; mi < 2; mi++) {
            int row0 = bm + wm * 32 + mi * 16 + g;
            int bidx = row0 >> 10, l0 = row0 & 1023;
            int pidx = (bidx * 16 + hh) * 1024 + l0;
            float4 p0 = prp[pidx];
            float4 p1 = prp[pidx + 8];
            size_t ob = ((size_t)(bidx * 16 + hh) * 1024 + l0) * 64;
            #pragma unroll
            for (int ni = 0; ni < 4; ni++) {
                int d = ni * 8 + tig * 2;
                float2 b1 = *(const float2*)(bias + bn + wn * 64 + d);
                float2 b2 = *(const float2*)(bias + bn + wn * 64 + d + 32);
                // row0
                {
                    float x0 = (c[mi][ni][0]   + b1.x) * p0.x;
                    float x1 = (c[mi][ni][1]   + b1.y) * p0.x;
                    float y0 = (c[mi][ni+4][0] + b2.x) * p0.x;
                    float y1 = (c[mi][ni+4][1] + b2.y) * p0.x;
                    *(uint32_t*)(oh + ob + d) =
                        pack2h(x0 * p0.z - y0 * p0.y, x1 * p0.z - y1 * p0.y);
                    *(uint32_t*)(oh + ob + d + 32) =
                        pack2h(y0 * p0.z + x0 * p0.y, y1 * p0.z + x1 * p0.y);
                }
                // row0 + 8
                {
                    float x0 = (c[mi][ni][2]   + b1.x) * p1.x;
                    float x1 = (c[mi][ni][3]   + b1.y) * p1.x;
                    float y0 = (c[mi][ni+4][2] + b2.x) * p1.x;
                    float y1 = (c[mi][ni+4][3] + b2.y) * p1.x;
                    *(uint32_t*)(oh + ob + 512 + d) =
                        pack2h(x0 * p1.z - y0 * p1.y, x1 * p1.z - y1 * p1.y);
                    *(uint32_t*)(oh + ob + 512 + d + 32) =
                        pack2h(y0 * p1.z + x0 * p1.y, y1 * p1.z + x1 * p1.y);
                }
            }
        }
    }
    #undef LOAD_STAGE
}

// ---------------------------------------------------------------------------
// HMMA fp16 flash attention, 1-term, 3-stage KV pipeline (unchanged from R10).
// ---------------------------------------------------------------------------
#define AT_Q   0
#define AT_STG 16384
#define KVSTG  16384                  // K @0, V @8192
#define AT_MASK (AT_STG + 3*KVSTG)    // 65536
#define ATTN_DYN (AT_MASK + 4096)     // 69632

__global__ __launch_bounds__(256, 2) void attn_hmma(
    const __half* __restrict__ qhi,
    const __half* __restrict__ khi,
    const __half* __restrict__ vhi,
    const float* __restrict__ mask,
    __half* __restrict__ chi)
{
    extern __shared__ char smraw[];
    const uint32_t sb = smem_to_u32(smraw);
    const int tid = threadIdx.x, lane = tid & 31, w = tid >> 5;
    const int qt = blockIdx.x, bh = blockIdx.y;
    const int b = bh >> 4, h = bh & 15;

    CP16(sb + AT_MASK + tid * 16, mask + b * 1024 + tid * 4);
    #pragma unroll
    for (int it = 0; it < 4; it++) {
        int idx = tid + it * 256, r = idx >> 3, seg = idx & 7;
        size_t g = ((size_t)bh * 1024 + qt * 128 + r) * 64 + seg * 8;
        uint32_t d = sb + (uint32_t)r * 128 + (uint32_t)((seg ^ (r & 7)) << 4);
        CP16(d + AT_Q, qhi + g);
    }
    CP_COMMIT();

    #define LOADKV(s, kt_) do { \
        _Pragma("unroll") \
        for (int it = 0; it < 2; it++) { \
            int idx = tid + it * 256, r = idx >> 3, sg = idx & 7; \
            size_t g = ((size_t)bh * 1024 + (kt_) * 64 + r) * 64 + sg * 8; \
            uint32_t d = sb + AT_STG + (uint32_t)(s) * KVSTG \
                       + (uint32_t)r * 128 + (uint32_t)((sg ^ (r & 7)) << 4); \
            CP16(d,        khi + g); \
            CP16(d + 8192, vhi + g); \
        } \
        CP_COMMIT(); \
    } while (0)

    LOADKV(0, 0);
    LOADKV(1, 1);

    float o[8][4];
    #pragma unroll
    for (int j = 0; j < 8; j++)
        #pragma unroll
        for (int e = 0; e < 4; e++) o[j][e] = 0.f;
    float m0 = -INFINITY, m1 = -INFINITY, l0 = 0.f, l1 = 0.f;

    const int rA = w * 16 + (lane & 15);
    const int rBb = ((lane >> 4) << 3) + (lane & 7);
    const int c2 = (lane & 3) * 2;

    int cur = 0;
    for (int kt = 0; kt < 16; kt++) {
        if (kt < 15) CP_WAIT(1);
        else         CP_WAIT(0);
        __syncthreads();
        if (kt < 14) {
            int nxt = cur + 2;
            if (nxt >= 3) nxt -= 3;
            LOADKV(nxt, kt + 2);
        }
        const uint32_t kb = sb + AT_STG + (uint32_t)cur * KVSTG;

        float s[8][4];
        #pragma unroll
        for (int j = 0; j < 8; j++)
            #pragma unroll
            for (int e = 0; e < 4; e++) s[j][e] = 0.f;

        #pragma unroll
        for (int ks = 0; ks < 4; ks++) {
            uint32_t ah[4];
            uint32_t aaddr = sb + AT_Q + (uint32_t)rA * 128
                           + (uint32_t)(((ks * 2 + (lane >> 4)) ^ (rA & 7)) << 4);
            LDSM4(ah, aaddr);
            #pragma unroll
            for (int np = 0; np < 4; np++) {
                int rB = np * 16 + rBb;
                uint32_t baddr = kb + (uint32_t)rB * 128
                               + (uint32_t)(((ks * 2 + ((lane >> 3) & 1)) ^ (rB & 7)) << 4);
                uint32_t bhF[4];
                LDSM4(bhF, baddr);
                #pragma unroll
                for (int hf = 0; hf < 2; hf++) {
                    int nt = np * 2 + hf, rb = hf * 2;
                    MMA16816(s[nt], ah, bhF[rb], bhF[rb + 1]);
                }
            }
        }

        float mx0 = -INFINITY, mx1 = -INFINITY;
        #pragma unroll
        for (int j = 0; j < 8; j++) {
            float2 mk = *(float2*)(smraw + AT_MASK + (size_t)(kt * 64 + j * 8 + c2) * 4);
            s[j][0] = s[j][0] * 0.125f + mk.x;
            s[j][1] = s[j][1] * 0.125f + mk.y;
            s[j][2] = s[j][2] * 0.125f + mk.x;
            s[j][3] = s[j][3] * 0.125f + mk.y;
            mx0 = fmaxf(mx0, fmaxf(s[j][0], s[j][1]));
            mx1 = fmaxf(mx1, fmaxf(s[j][2], s[j][3]));
        }
        #pragma unroll
        for (int off = 1; off < 4; off <<= 1) {
            mx0 = fmaxf(mx0, __shfl_xor_sync(0xffffffffu, mx0, off));
            mx1 = fmaxf(mx1, __shfl_xor_sync(0xffffffffu, mx1, off));
        }
        float mn0 = fmaxf(m0, mx0), mn1 = fmaxf(m1, mx1);
        float corr0 = __expf(m0 - mn0), corr1 = __expf(m1 - mn1);
        m0 = mn0; m1 = mn1;
        float sum0 = 0.f, sum1 = 0.f;
        #pragma unroll
        for (int j = 0; j < 8; j++) {
            s[j][0] = __expf(s[j][0] - m0);
            s[j][1] = __expf(s[j][1] - m0);
            s[j][2] = __expf(s[j][2] - m1);
            s[j][3] = __expf(s[j][3] - m1);
            sum0 += s[j][0] + s[j][1];
            sum1 += s[j][2] + s[j][3];
        }
        #pragma unroll
        for (int off = 1; off < 4; off <<= 1) {
            sum0 += __shfl_xor_sync(0xffffffffu, sum0, off);
            sum1 += __shfl_xor_sync(0xffffffffu, sum1, off);
        }
        l0 = l0 * corr0 + sum0;
        l1 = l1 * corr1 + sum1;
        #pragma unroll
        for (int j = 0; j < 8; j++) {
            o[j][0] *= corr0; o[j][1] *= corr0;
            o[j][2] *= corr1; o[j][3] *= corr1;
        }

        #pragma unroll
        for (int kg = 0; kg < 4; kg++) {
            uint32_t ph[4];
            ph[0] = pack2h(s[2*kg][0],   s[2*kg][1]);
            ph[1] = pack2h(s[2*kg][2],   s[2*kg][3]);
            ph[2] = pack2h(s[2*kg+1][0], s[2*kg+1][1]);
            ph[3] = pack2h(s[2*kg+1][2], s[2*kg+1][3]);
            int rV = kg * 16 + (lane & 15);
            #pragma unroll
            for (int np = 0; np < 4; np++) {
                uint32_t vaddr = kb + 8192 + (uint32_t)rV * 128
                               + (uint32_t)(((np * 2 + (lane >> 4)) ^ (rV & 7)) << 4);
                uint32_t vhF[4];
                LDSM4T(vhF, vaddr);
                #pragma unroll
                for (int hf = 0; hf < 2; hf++) {
                    int nt = np * 2 + hf, rb = hf * 2;
                    MMA16816(o[nt], ph, vhF[rb], vhF[rb + 1]);
                }
            }
        }

        cur++;
        if (cur == 3) cur = 0;
    }

    float i0 = 1.0f / l0, i1 = 1.0f / l1;
    size_t row0 = (size_t)b * 1024 + qt * 128 + w * 16 + (lane >> 2);
    #pragma unroll
    for (int j = 0; j < 8; j++) {
        int col = h * 64 + j * 8 + c2;
        *(uint32_t*)(chi + row0 * D_ + col)       = pack2h(o[j][0] * i0, o[j][1] * i0);
        *(uint32_t*)(chi + (row0 + 8) * D_ + col) = pack2h(o[j][2] * i1, o[j][3] * i1);
    }
    #undef LOADKV
}

// ---------------------------------------------------------------------------
// LayerNorm over last dim (1024).
// ---------------------------------------------------------------------------
__global__ __launch_bounds__(256) void lnorm(
    const float* __restrict__ X, const float* __restrict__ hsc,
    const float* __restrict__ hbi, float* __restrict__ out)
{
    int row = blockIdx.x;
    int c4 = threadIdx.x * 4;
    const float* x = X + (size_t)row * D_;
    float4 v = *(const float4*)(x + c4);
    float sum = v.x + v.y + v.z + v.w;
    float sq  = v.x*v.x + v.y*v.y + v.z*v.z + v.w*v.w;
    #pragma unroll
    for (int off = 16; off > 0; off >>= 1) {
        sum += __shfl_xor_sync(0xffffffffu, sum, off);
        sq  += __shfl_xor_sync(0xffffffffu, sq,  off);
    }
    __shared__ float rs[8], rq[8];
    int warp = threadIdx.x >> 5;
    if ((threadIdx.x & 31) == 0) { rs[warp] = sum; rq[warp] = sq; }
    __syncthreads();
    float tot = 0.f, totq = 0.f;
    #pragma unroll
    for (int wv = 0; wv < 8; wv++) { tot += rs[wv]; totq += rq[wv]; }
    float mu  = tot  * (1.0f / 1024.0f);
    float var = totq * (1.0f / 1024.0f) - mu * mu;
    float inv = rsqrtf(var + 1e-12f);
    float4 sc = *(const float4*)(hsc + c4);
    float4 bi = *(const float4*)(hbi + c4);
    float4 oo;
    oo.x = (v.x - mu) * inv * sc.x + bi.x;
    oo.y = (v.y - mu) * inv * sc.y + bi.y;
    oo.z = (v.z - mu) * inv * sc.z + bi.z;
    oo.w = (v.w - mu) * inv * sc.w + bi.w;
    *(float4*)&out[(size_t)row * D_ + c4] = oo;
}

// ---------------------------------------------------------------------------
extern "C" void kernel_launch(void* const* d_in, const int* in_sizes, int n_in,
                              void* d_out, int out_size)
{
    const float* hidden = (const float*)d_in[0];
    const float* mask   = (const float*)d_in[1];
    const float* phi    = (const float*)d_in[2];
    const float* mag    = (const float*)d_in[3];
    const float* Wq     = (const float*)d_in[4];
    const float* bq     = (const float*)d_in[5];
    const float* Wk     = (const float*)d_in[6];
    const float* bk     = (const float*)d_in[7];
    const float* Wv     = (const float*)d_in[8];
    const float* bv     = (const float*)d_in[9];
    const float* gamma  = (const float*)d_in[10];
    const float* Wo     = (const float*)d_in[11];
    const float* bo     = (const float*)d_in[12];
    const float* lns    = (const float*)d_in[13];
    const float* lnb    = (const float*)d_in[14];
    float* out = (float*)d_out;

    float *x;
    float4* prp;
    __half *ahi, *wthi, *qhi, *khi, *vhi;
    cudaGetSymbolAddress((void**)&x,    g_x);
    cudaGetSymbolAddress((void**)&prp,  g_prep);
    cudaGetSymbolAddress((void**)&ahi,  g_ahi);
    cudaGetSymbolAddress((void**)&wthi, g_wthi);
    cudaGetSymbolAddress((void**)&qhi,  g_qhi);
    cudaGetSymbolAddress((void**)&khi,  g_khi);
    cudaGetSymbolAddress((void**)&vhi,  g_vhi);

    cudaFuncSetAttribute(gemm_hmma, cudaFuncAttributeMaxDynamicSharedMemorySize, GEMM_DYN);
    cudaFuncSetAttribute(attn_hmma, cudaFuncAttributeMaxDynamicSharedMemorySize, ATTN_DYN);

    const int DD = D_ * D_;

    prep<<<(B_ * H_ * L_) / 256, 256>>>(phi, mag, gamma, prp);
    convA<<<(M_TOT * D_ / 4 + 255) / 256, 256>>>((const float4*)hidden, (uint2*)ahi, M_TOT * D_ / 4);
    convW4<<<dim3(32, 32, 4), 256>>>(Wq, Wk, Wv, Wo, wthi);

    // QKV fused (z: 0=Q rot, 1=K rot, 2=V), fp16 head-major outputs
    gemm_hmma<<<dim3(D_ / GN, M_TOT / GM, 3), 256, GEMM_DYN>>>(
        ahi, wthi, bq, bk, bv, prp, qhi, khi, vhi, nullptr, nullptr);

    attn_hmma<<<dim3(L_ / 128, B_ * H_), 256, ATTN_DYN>>>(
        qhi, khi, vhi, mask, ahi);

    // Wo projection + residual
    gemm_hmma<<<dim3(D_ / GN, M_TOT / GM, 1), 256, GEMM_DYN>>>(
        ahi, wthi + 3*DD, bo, bo, bo, prp,
        nullptr, nullptr, nullptr, hidden, x);

    lnorm<<<M_TOT, 256>>>(x, lns, lnb, out);
}